// round 1
// baseline (speedup 1.0000x reference)
#include <cuda_runtime.h>
#include <cuda_bf16.h>
#include <math.h>

#define SEQLEN  2048
#define DIM     4096
#define NHEADS  32
#define NKV     8
#define HDIM    128

// ---------------- scratch (device globals; no allocation allowed) ----------
__device__ float g_q[SEQLEN * (size_t)DIM];           // 32 MB
__device__ float g_k[SEQLEN * (size_t)(NKV * HDIM)];  // 8 MB
__device__ float g_v[SEQLEN * (size_t)(NKV * HDIM)];  // 8 MB
__device__ float g_y[SEQLEN * (size_t)DIM];           // 32 MB

// ---------------- GEMM: C[M,N] = A[M,K] @ B[N,K]^T  (both row-major) -------
// Block tile 128x64, BK=16, 256 threads, 8x4 per-thread microtile.
#define BM 128
#define BN 64
#define BK 16

__global__ __launch_bounds__(256) void gemm_nt_kernel(
    const float* __restrict__ A, const float* __restrict__ B,
    float* __restrict__ C, int M, int N, int K)
{
    __shared__ float As[BK][BM + 4];
    __shared__ float Bs[BK][BN + 4];

    const int tid = threadIdx.x;
    const int tx = tid & 15;        // 0..15
    const int ty = tid >> 4;        // 0..15
    const int row0 = blockIdx.y * BM;
    const int col0 = blockIdx.x * BN;

    const int lr = tid >> 2;        // 0..63
    const int lc = (tid & 3) << 2;  // 0,4,8,12

    float acc[8][4];
#pragma unroll
    for (int i = 0; i < 8; i++)
#pragma unroll
        for (int j = 0; j < 4; j++) acc[i][j] = 0.0f;

    for (int k0 = 0; k0 < K; k0 += BK) {
        // load A tile (128x16) : 512 float4, 2 per thread
        float4 a0 = *(const float4*)(A + (size_t)(row0 + lr) * K + k0 + lc);
        float4 a1 = *(const float4*)(A + (size_t)(row0 + lr + 64) * K + k0 + lc);
        As[lc + 0][lr] = a0.x; As[lc + 1][lr] = a0.y;
        As[lc + 2][lr] = a0.z; As[lc + 3][lr] = a0.w;
        As[lc + 0][lr + 64] = a1.x; As[lc + 1][lr + 64] = a1.y;
        As[lc + 2][lr + 64] = a1.z; As[lc + 3][lr + 64] = a1.w;
        // load B tile (64x16) : 256 float4, 1 per thread
        float4 b0 = *(const float4*)(B + (size_t)(col0 + lr) * K + k0 + lc);
        Bs[lc + 0][lr] = b0.x; Bs[lc + 1][lr] = b0.y;
        Bs[lc + 2][lr] = b0.z; Bs[lc + 3][lr] = b0.w;
        __syncthreads();

#pragma unroll
        for (int kk = 0; kk < BK; kk++) {
            float ra[8], rb[4];
#pragma unroll
            for (int i = 0; i < 8; i++) ra[i] = As[kk][ty * 8 + i];
#pragma unroll
            for (int j = 0; j < 4; j++) rb[j] = Bs[kk][tx * 4 + j];
#pragma unroll
            for (int i = 0; i < 8; i++)
#pragma unroll
                for (int j = 0; j < 4; j++) acc[i][j] = fmaf(ra[i], rb[j], acc[i][j]);
        }
        __syncthreads();
    }

#pragma unroll
    for (int i = 0; i < 8; i++) {
        float4 o = make_float4(acc[i][0], acc[i][1], acc[i][2], acc[i][3]);
        *(float4*)(C + (size_t)(row0 + ty * 8 + i) * N + col0 + tx * 4) = o;
    }
}

// ---------------- RoPE (interleaved pairs) --------------------------------
__global__ void rope_kernel(float* __restrict__ t, const float* __restrict__ fc,
                            int nheads)
{
    int idx = blockIdx.x * blockDim.x + threadIdx.x;
    int total = SEQLEN * nheads * (HDIM / 2);
    if (idx >= total) return;
    int p = idx & 63;                 // pair index 0..63
    int h = (idx >> 6) % nheads;
    int s = idx / (64 * nheads);
    float c  = fc[s * HDIM + p * 2 + 0];
    float sn = fc[s * HDIM + p * 2 + 1];
    float* base = t + (size_t)s * nheads * HDIM + h * HDIM + p * 2;
    float x0 = base[0], x1 = base[1];
    base[0] = x0 * c - x1 * sn;
    base[1] = x1 * c + x0 * sn;
}

// ---------------- Flash attention (fp32, online softmax) ------------------
// grid: (SEQLEN/64, NHEADS). block: 256 threads.
// smem (dynamic): Qs[64][129], Ks[64][129], Vs[64][129], Ss[64][65], m/l/alpha[64]
#define QSTR 129
#define SSTR 65
#define ATTN_SMEM ((3 * 64 * QSTR + 64 * SSTR + 3 * 64) * 4)

__global__ __launch_bounds__(256) void attn_kernel(
    const float* __restrict__ q, const float* __restrict__ k,
    const float* __restrict__ v, float* __restrict__ y)
{
    extern __shared__ float sm[];
    float* Qs  = sm;
    float* Ks  = Qs + 64 * QSTR;
    float* Vs  = Ks + 64 * QSTR;
    float* Ss  = Vs + 64 * QSTR;
    float* m_s = Ss + 64 * SSTR;
    float* l_s = m_s + 64;
    float* a_s = l_s + 64;

    const int tid = threadIdx.x;
    const int tx = tid & 15;
    const int ty = tid >> 4;
    const int qt = blockIdx.x;
    const int h  = blockIdx.y;
    const int hk = h >> 2;              // GQA: 4 q-heads per kv-head
    const int q0 = qt * 64;
    const float scale = 0.08838834764831845f; // 1/sqrt(128)

    // load Q tile (64 x 128)
    for (int t = tid; t < 64 * 32; t += 256) {
        int r = t >> 5; int d4 = (t & 31) << 2;
        float4 qv = *(const float4*)(q + (size_t)(q0 + r) * DIM + h * HDIM + d4);
        Qs[r * QSTR + d4 + 0] = qv.x; Qs[r * QSTR + d4 + 1] = qv.y;
        Qs[r * QSTR + d4 + 2] = qv.z; Qs[r * QSTR + d4 + 3] = qv.w;
    }
    if (tid < 64) { m_s[tid] = -INFINITY; l_s[tid] = 0.0f; }

    float o[4][8];
#pragma unroll
    for (int i = 0; i < 4; i++)
#pragma unroll
        for (int j = 0; j < 8; j++) o[i][j] = 0.0f;

    __syncthreads();

    const int ntile = qt + 1;
    for (int jt = 0; jt < ntile; jt++) {
        const int j0 = jt * 64;
        // load K,V tiles (64 x 128 each)
        for (int t = tid; t < 64 * 32; t += 256) {
            int r = t >> 5; int d4 = (t & 31) << 2;
            size_t goff = (size_t)(j0 + r) * (NKV * HDIM) + hk * HDIM + d4;
            float4 kv4 = *(const float4*)(k + goff);
            Ks[r * QSTR + d4 + 0] = kv4.x; Ks[r * QSTR + d4 + 1] = kv4.y;
            Ks[r * QSTR + d4 + 2] = kv4.z; Ks[r * QSTR + d4 + 3] = kv4.w;
            float4 vv4 = *(const float4*)(v + goff);
            Vs[r * QSTR + d4 + 0] = vv4.x; Vs[r * QSTR + d4 + 1] = vv4.y;
            Vs[r * QSTR + d4 + 2] = vv4.z; Vs[r * QSTR + d4 + 3] = vv4.w;
        }
        __syncthreads();

        // S = Q K^T : rows r = ty*4+i, cols c = tx + 16*j
        float sacc[4][4];
#pragma unroll
        for (int i = 0; i < 4; i++)
#pragma unroll
            for (int j = 0; j < 4; j++) sacc[i][j] = 0.0f;

        for (int d = 0; d < HDIM; d++) {
            float ra[4], rb[4];
#pragma unroll
            for (int i = 0; i < 4; i++) ra[i] = Qs[(ty * 4 + i) * QSTR + d];
#pragma unroll
            for (int j = 0; j < 4; j++) rb[j] = Ks[(tx + 16 * j) * QSTR + d];
#pragma unroll
            for (int i = 0; i < 4; i++)
#pragma unroll
                for (int j = 0; j < 4; j++) sacc[i][j] = fmaf(ra[i], rb[j], sacc[i][j]);
        }
#pragma unroll
        for (int i = 0; i < 4; i++)
#pragma unroll
            for (int j = 0; j < 4; j++) {
                int r = ty * 4 + i, c = tx + 16 * j;
                float s = sacc[i][j] * scale;
                if (j0 + c > q0 + r) s = -1e9f;   // causal mask (matches reference)
                Ss[r * SSTR + c] = s;
            }
        __syncthreads();

        // online softmax per row
        if (tid < 64) {
            int r = tid;
            float mold = m_s[r];
            float tmax = -INFINITY;
#pragma unroll 8
            for (int c = 0; c < 64; c++) tmax = fmaxf(tmax, Ss[r * SSTR + c]);
            float mnew = fmaxf(mold, tmax);
            float alpha = (mold == -INFINITY) ? 0.0f : __expf(mold - mnew);
            float sum = 0.0f;
#pragma unroll 8
            for (int c = 0; c < 64; c++) {
                float p = __expf(Ss[r * SSTR + c] - mnew);
                Ss[r * SSTR + c] = p;
                sum += p;
            }
            l_s[r] = l_s[r] * alpha + sum;
            m_s[r] = mnew;
            a_s[r] = alpha;
        }
        __syncthreads();

        // O = O*alpha + P @ V : rows r = ty*4+i, cols d = tx + 16*j
        float al[4];
#pragma unroll
        for (int i = 0; i < 4; i++) al[i] = a_s[ty * 4 + i];
#pragma unroll
        for (int i = 0; i < 4; i++)
#pragma unroll
            for (int j = 0; j < 8; j++) o[i][j] *= al[i];

        for (int c = 0; c < 64; c++) {
            float rp[4], rv[8];
#pragma unroll
            for (int i = 0; i < 4; i++) rp[i] = Ss[(ty * 4 + i) * SSTR + c];
#pragma unroll
            for (int j = 0; j < 8; j++) rv[j] = Vs[c * QSTR + tx + 16 * j];
#pragma unroll
            for (int i = 0; i < 4; i++)
#pragma unroll
                for (int j = 0; j < 8; j++) o[i][j] = fmaf(rp[i], rv[j], o[i][j]);
        }
        __syncthreads();
    }

    // epilogue: divide by l, write y[s][h*128 + d]
#pragma unroll
    for (int i = 0; i < 4; i++) {
        int r = ty * 4 + i;
        float inv = 1.0f / l_s[r];
#pragma unroll
        for (int j = 0; j < 8; j++) {
            y[(size_t)(q0 + r) * DIM + h * HDIM + tx + 16 * j] = o[i][j] * inv;
        }
    }
}

// ---------------- launch ---------------------------------------------------
extern "C" void kernel_launch(void* const* d_in, const int* in_sizes, int n_in,
                              void* d_out, int out_size)
{
    const float* x  = (const float*)d_in[0];
    const float* fc = (const float*)d_in[1];
    // d_in[2] = mask (unused; causal mask computed analytically, identical values)
    const float* wq = (const float*)d_in[3];
    const float* wk = (const float*)d_in[4];
    const float* wv = (const float*)d_in[5];
    const float* wo = (const float*)d_in[6];
    float* out = (float*)d_out;

    void *pq, *pk, *pv, *py;
    cudaGetSymbolAddress(&pq, g_q);
    cudaGetSymbolAddress(&pk, g_k);
    cudaGetSymbolAddress(&pv, g_v);
    cudaGetSymbolAddress(&py, g_y);
    float* dq = (float*)pq;
    float* dk = (float*)pk;
    float* dv = (float*)pv;
    float* dy = (float*)py;

    cudaFuncSetAttribute(attn_kernel,
                         cudaFuncAttributeMaxDynamicSharedMemorySize, ATTN_SMEM);

    dim3 blk(256);
    // projections: q = x @ wq^T, k = x @ wk^T, v = x @ wv^T
    gemm_nt_kernel<<<dim3(DIM / BN, SEQLEN / BM), blk>>>(x, wq, dq, SEQLEN, DIM, DIM);
    gemm_nt_kernel<<<dim3((NKV * HDIM) / BN, SEQLEN / BM), blk>>>(x, wk, dk, SEQLEN, NKV * HDIM, DIM);
    gemm_nt_kernel<<<dim3((NKV * HDIM) / BN, SEQLEN / BM), blk>>>(x, wv, dv, SEQLEN, NKV * HDIM, DIM);

    // RoPE on q and k
    {
        int nq = SEQLEN * NHEADS * (HDIM / 2);
        rope_kernel<<<(nq + 255) / 256, 256>>>(dq, fc, NHEADS);
        int nk = SEQLEN * NKV * (HDIM / 2);
        rope_kernel<<<(nk + 255) / 256, 256>>>(dk, fc, NKV);
    }

    // flash attention
    attn_kernel<<<dim3(SEQLEN / 64, NHEADS), blk, ATTN_SMEM>>>(dq, dk, dv, dy);

    // output projection: out = y @ wo^T
    gemm_nt_kernel<<<dim3(DIM / BN, SEQLEN / BM), blk>>>(dy, wo, out, SEQLEN, DIM, DIM);
}

// round 4
// speedup vs baseline: 1.3841x; 1.3841x over previous
#include <cuda_runtime.h>
#include <cuda_bf16.h>
#include <math.h>
#include <stdint.h>

#define SEQLEN  2048
#define DIM     4096
#define NHEADS  32
#define NKV     8
#define HDIM    128
#define KVDIM   (NKV*HDIM)

// single dynamic smem symbol shared by all kernels
extern __shared__ char dynsm[];

// ---------------- device scratch (no allocation allowed) -------------------
__device__ __align__(256) float g_q[(size_t)SEQLEN*DIM];
__device__ __align__(256) float g_k[(size_t)SEQLEN*KVDIM];
__device__ __align__(256) float g_v[(size_t)SEQLEN*KVDIM];
__device__ __align__(256) float g_y[(size_t)SEQLEN*DIM];
__device__ __align__(256) __nv_bfloat16 g_xhi[(size_t)SEQLEN*DIM];
__device__ __align__(256) __nv_bfloat16 g_xlo[(size_t)SEQLEN*DIM];
__device__ __align__(256) __nv_bfloat16 g_wqhi[(size_t)DIM*DIM];
__device__ __align__(256) __nv_bfloat16 g_wqlo[(size_t)DIM*DIM];
__device__ __align__(256) __nv_bfloat16 g_wkhi[(size_t)KVDIM*DIM];
__device__ __align__(256) __nv_bfloat16 g_wklo[(size_t)KVDIM*DIM];
__device__ __align__(256) __nv_bfloat16 g_wvhi[(size_t)KVDIM*DIM];
__device__ __align__(256) __nv_bfloat16 g_wvlo[(size_t)KVDIM*DIM];
__device__ __align__(256) __nv_bfloat16 g_wohi[(size_t)DIM*DIM];
__device__ __align__(256) __nv_bfloat16 g_wolo[(size_t)DIM*DIM];
__device__ __align__(256) __nv_bfloat16 g_yhi[(size_t)SEQLEN*DIM];
__device__ __align__(256) __nv_bfloat16 g_ylo[(size_t)SEQLEN*DIM];

// ---------------- split fp32 -> (hi, lo) bf16 ------------------------------
__global__ void split_kernel(const float* __restrict__ in, __nv_bfloat16* __restrict__ hi,
                             __nv_bfloat16* __restrict__ lo, int n){
    int i = blockIdx.x * blockDim.x + threadIdx.x;
    if (i < n){
        float x = in[i];
        __nv_bfloat16 h = __float2bfloat16(x);
        hi[i] = h;
        lo[i] = __float2bfloat16(x - __bfloat162float(h));
    }
}

// ---------------- HMMA helper ----------------------------------------------
__device__ __forceinline__ void mma16816(float* d, const uint32_t* a, const uint32_t* b){
    asm volatile(
        "mma.sync.aligned.m16n8k16.row.col.f32.bf16.bf16.f32 "
        "{%0,%1,%2,%3}, {%4,%5,%6,%7}, {%8,%9}, {%0,%1,%2,%3};"
        : "+f"(d[0]), "+f"(d[1]), "+f"(d[2]), "+f"(d[3])
        : "r"(a[0]), "r"(a[1]), "r"(a[2]), "r"(a[3]), "r"(b[0]), "r"(b[1]));
}

// ---------------- bf16 split GEMM: C[M,N] = A[M,K] @ B[N,K]^T --------------
// CTA tile 128x128, BK=32, 256 threads (2x4 warps, 64x32 per warp),
// 3-stage cp.async pipeline, 3-pass split accumulation (AhBh + AhBl + AlBh).
#define BKC   32
#define RSTR  80                        // bytes per smem row (32 bf16 + 8 pad)
#define TILEB (128*RSTR)                // 10240 B
#define STAGEB (4*TILEB)                // Ahi, Alo, Bhi, Blo
#define NSTG  3
#define GSMEM (NSTG*STAGEB)             // 122880 B

__global__ __launch_bounds__(256, 1) void gemm_mma(
    const __nv_bfloat16* __restrict__ Ahi, const __nv_bfloat16* __restrict__ Alo,
    const __nv_bfloat16* __restrict__ Bhi, const __nv_bfloat16* __restrict__ Blo,
    float* __restrict__ C, int N, int K)
{
    char* smb = dynsm;
    const int tid  = threadIdx.x;
    const int wid  = tid >> 5;
    const int lane = tid & 31;
    const int g  = lane >> 2;      // 0..7
    const int tg = lane & 3;       // 0..3
    const int warpM = (wid >> 2) * 64;   // 0 or 64
    const int warpN = (wid & 3) * 32;    // 0,32,64,96
    const int row0 = blockIdx.y * 128;
    const int col0 = blockIdx.x * 128;

    float acc[4][4][4];
#pragma unroll
    for (int i = 0; i < 4; i++)
#pragma unroll
        for (int j = 0; j < 4; j++)
#pragma unroll
            for (int l = 0; l < 4; l++) acc[i][j][l] = 0.0f;

    const int lr = tid & 127;       // smem row this thread fills
    const int lq = tid >> 7;        // 0..1 : which 32B half of the 64B row

    const __nv_bfloat16* srcs[4];
    srcs[0] = Ahi + (size_t)(row0 + lr) * K;
    srcs[1] = Alo + (size_t)(row0 + lr) * K;
    srcs[2] = Bhi + (size_t)(col0 + lr) * K;
    srcs[3] = Blo + (size_t)(col0 + lr) * K;

    auto load_stage = [&](int c, int st){
        char* stb = smb + st*STAGEB;
        int k0 = c * BKC;
#pragma unroll
        for (int t = 0; t < 4; t++){
            char* dst = stb + t*TILEB + lr*RSTR + lq*32;
            const __nv_bfloat16* src = srcs[t] + k0 + lq*16;
            asm volatile("cp.async.cg.shared.global [%0], [%1], 16;"
                         :: "r"((uint32_t)__cvta_generic_to_shared(dst)), "l"(src));
            asm volatile("cp.async.cg.shared.global [%0], [%1], 16;"
                         :: "r"((uint32_t)__cvta_generic_to_shared(dst+16)), "l"(src+8));
        }
    };

    const int nc = K / BKC;
    load_stage(0, 0); asm volatile("cp.async.commit_group;" ::: "memory");
    load_stage(1, 1); asm volatile("cp.async.commit_group;" ::: "memory");

    for (int c = 0; c < nc; c++){
        int cl = c + 2;
        if (cl < nc) load_stage(cl, cl % NSTG);
        asm volatile("cp.async.commit_group;" ::: "memory");
        asm volatile("cp.async.wait_group 2;"  ::: "memory");
        __syncthreads();

        char* stb = smb + (c % NSTG)*STAGEB;
        char* As_h = stb;
        char* As_l = stb + TILEB;
        char* Bs_h = stb + 2*TILEB;
        char* Bs_l = stb + 3*TILEB;

#pragma unroll
        for (int kc = 0; kc < 2; kc++){
            int colb = kc*16 + tg*2;     // bf16 col of the first element
            uint32_t afh[4][4], afl[4][4];
#pragma unroll
            for (int mt = 0; mt < 4; mt++){
                int r = warpM + mt*16 + g;
                afh[mt][0] = *(const uint32_t*)(As_h + r*RSTR + colb*2);
                afh[mt][1] = *(const uint32_t*)(As_h + (r+8)*RSTR + colb*2);
                afh[mt][2] = *(const uint32_t*)(As_h + r*RSTR + (colb+8)*2);
                afh[mt][3] = *(const uint32_t*)(As_h + (r+8)*RSTR + (colb+8)*2);
                afl[mt][0] = *(const uint32_t*)(As_l + r*RSTR + colb*2);
                afl[mt][1] = *(const uint32_t*)(As_l + (r+8)*RSTR + colb*2);
                afl[mt][2] = *(const uint32_t*)(As_l + r*RSTR + (colb+8)*2);
                afl[mt][3] = *(const uint32_t*)(As_l + (r+8)*RSTR + (colb+8)*2);
            }
            uint32_t bfh[4][2], bfl[4][2];
#pragma unroll
            for (int nt = 0; nt < 4; nt++){
                int r = warpN + nt*8 + g;
                bfh[nt][0] = *(const uint32_t*)(Bs_h + r*RSTR + colb*2);
                bfh[nt][1] = *(const uint32_t*)(Bs_h + r*RSTR + (colb+8)*2);
                bfl[nt][0] = *(const uint32_t*)(Bs_l + r*RSTR + colb*2);
                bfl[nt][1] = *(const uint32_t*)(Bs_l + r*RSTR + (colb+8)*2);
            }
#pragma unroll
            for (int mt = 0; mt < 4; mt++)
#pragma unroll
                for (int nt = 0; nt < 4; nt++){
                    mma16816(acc[mt][nt], afh[mt], bfh[nt]);
                    mma16816(acc[mt][nt], afh[mt], bfl[nt]);
                    mma16816(acc[mt][nt], afl[mt], bfh[nt]);
                }
        }
        __syncthreads();
    }

    // epilogue
#pragma unroll
    for (int mt = 0; mt < 4; mt++){
#pragma unroll
        for (int nt = 0; nt < 4; nt++){
            int r0 = row0 + warpM + mt*16 + g;
            int c0 = col0 + warpN + nt*8 + tg*2;
            *(float2*)(C + (size_t)r0*N + c0)     = make_float2(acc[mt][nt][0], acc[mt][nt][1]);
            *(float2*)(C + (size_t)(r0+8)*N + c0) = make_float2(acc[mt][nt][2], acc[mt][nt][3]);
        }
    }
}

// ---------------- RoPE (interleaved pairs) --------------------------------
__global__ void rope_kernel(float* __restrict__ t, const float* __restrict__ fc,
                            int nheads)
{
    int idx = blockIdx.x * blockDim.x + threadIdx.x;
    int total = SEQLEN * nheads * (HDIM / 2);
    if (idx >= total) return;
    int p = idx & 63;
    int h = (idx >> 6) % nheads;
    int s = idx / (64 * nheads);
    float c  = fc[s * HDIM + p * 2 + 0];
    float sn = fc[s * HDIM + p * 2 + 1];
    float* base = t + (size_t)s * nheads * HDIM + h * HDIM + p * 2;
    float x0 = base[0], x1 = base[1];
    base[0] = x0 * c - x1 * sn;
    base[1] = x1 * c + x0 * sn;
}

// ---------------- Flash attention (fp32, online softmax) ------------------
#define QSTR 129
#define SSTR 65
#define ATTN_SMEM ((3 * 64 * QSTR + 64 * SSTR + 3 * 64) * 4)

__global__ __launch_bounds__(256) void attn_kernel(
    const float* __restrict__ q, const float* __restrict__ k,
    const float* __restrict__ v, float* __restrict__ y)
{
    float* smf = (float*)dynsm;
    float* Qs  = smf;
    float* Ks  = Qs + 64 * QSTR;
    float* Vs  = Ks + 64 * QSTR;
    float* Ss  = Vs + 64 * QSTR;
    float* m_s = Ss + 64 * SSTR;
    float* l_s = m_s + 64;
    float* a_s = l_s + 64;

    const int tid = threadIdx.x;
    const int tx = tid & 15;
    const int ty = tid >> 4;
    const int qt = blockIdx.x;
    const int h  = blockIdx.y;
    const int hk = h >> 2;
    const int q0 = qt * 64;
    const float scale = 0.08838834764831845f;

    for (int t = tid; t < 64 * 32; t += 256) {
        int r = t >> 5; int d4 = (t & 31) << 2;
        float4 qv = *(const float4*)(q + (size_t)(q0 + r) * DIM + h * HDIM + d4);
        Qs[r * QSTR + d4 + 0] = qv.x; Qs[r * QSTR + d4 + 1] = qv.y;
        Qs[r * QSTR + d4 + 2] = qv.z; Qs[r * QSTR + d4 + 3] = qv.w;
    }
    if (tid < 64) { m_s[tid] = -INFINITY; l_s[tid] = 0.0f; }

    float o[4][8];
#pragma unroll
    for (int i = 0; i < 4; i++)
#pragma unroll
        for (int j = 0; j < 8; j++) o[i][j] = 0.0f;

    __syncthreads();

    const int ntile = qt + 1;
    for (int jt = 0; jt < ntile; jt++) {
        const int j0 = jt * 64;
        for (int t = tid; t < 64 * 32; t += 256) {
            int r = t >> 5; int d4 = (t & 31) << 2;
            size_t goff = (size_t)(j0 + r) * KVDIM + hk * HDIM + d4;
            float4 kv4 = *(const float4*)(k + goff);
            Ks[r * QSTR + d4 + 0] = kv4.x; Ks[r * QSTR + d4 + 1] = kv4.y;
            Ks[r * QSTR + d4 + 2] = kv4.z; Ks[r * QSTR + d4 + 3] = kv4.w;
            float4 vv4 = *(const float4*)(v + goff);
            Vs[r * QSTR + d4 + 0] = vv4.x; Vs[r * QSTR + d4 + 1] = vv4.y;
            Vs[r * QSTR + d4 + 2] = vv4.z; Vs[r * QSTR + d4 + 3] = vv4.w;
        }
        __syncthreads();

        float sacc[4][4];
#pragma unroll
        for (int i = 0; i < 4; i++)
#pragma unroll
            for (int j = 0; j < 4; j++) sacc[i][j] = 0.0f;

        for (int d = 0; d < HDIM; d++) {
            float ra[4], rb[4];
#pragma unroll
            for (int i = 0; i < 4; i++) ra[i] = Qs[(ty * 4 + i) * QSTR + d];
#pragma unroll
            for (int j = 0; j < 4; j++) rb[j] = Ks[(tx + 16 * j) * QSTR + d];
#pragma unroll
            for (int i = 0; i < 4; i++)
#pragma unroll
                for (int j = 0; j < 4; j++) sacc[i][j] = fmaf(ra[i], rb[j], sacc[i][j]);
        }
#pragma unroll
        for (int i = 0; i < 4; i++)
#pragma unroll
            for (int j = 0; j < 4; j++) {
                int r = ty * 4 + i, c = tx + 16 * j;
                float s = sacc[i][j] * scale;
                if (j0 + c > q0 + r) s = -1e9f;
                Ss[r * SSTR + c] = s;
            }
        __syncthreads();

        if (tid < 64) {
            int r = tid;
            float mold = m_s[r];
            float tmax = -INFINITY;
#pragma unroll 8
            for (int c = 0; c < 64; c++) tmax = fmaxf(tmax, Ss[r * SSTR + c]);
            float mnew = fmaxf(mold, tmax);
            float alpha = (mold == -INFINITY) ? 0.0f : __expf(mold - mnew);
            float sum = 0.0f;
#pragma unroll 8
            for (int c = 0; c < 64; c++) {
                float p = __expf(Ss[r * SSTR + c] - mnew);
                Ss[r * SSTR + c] = p;
                sum += p;
            }
            l_s[r] = l_s[r] * alpha + sum;
            m_s[r] = mnew;
            a_s[r] = alpha;
        }
        __syncthreads();

        float al[4];
#pragma unroll
        for (int i = 0; i < 4; i++) al[i] = a_s[ty * 4 + i];
#pragma unroll
        for (int i = 0; i < 4; i++)
#pragma unroll
            for (int j = 0; j < 8; j++) o[i][j] *= al[i];

        for (int c = 0; c < 64; c++) {
            float rp[4], rv[8];
#pragma unroll
            for (int i = 0; i < 4; i++) rp[i] = Ss[(ty * 4 + i) * SSTR + c];
#pragma unroll
            for (int j = 0; j < 8; j++) rv[j] = Vs[c * QSTR + tx + 16 * j];
#pragma unroll
            for (int i = 0; i < 4; i++)
#pragma unroll
                for (int j = 0; j < 8; j++) o[i][j] = fmaf(rp[i], rv[j], o[i][j]);
        }
        __syncthreads();
    }

#pragma unroll
    for (int i = 0; i < 4; i++) {
        int r = ty * 4 + i;
        float inv = 1.0f / l_s[r];
#pragma unroll
        for (int j = 0; j < 8; j++) {
            y[(size_t)(q0 + r) * DIM + h * HDIM + tx + 16 * j] = o[i][j] * inv;
        }
    }
}

// ---------------- launch ---------------------------------------------------
extern "C" void kernel_launch(void* const* d_in, const int* in_sizes, int n_in,
                              void* d_out, int out_size)
{
    const float* x  = (const float*)d_in[0];
    const float* fc = (const float*)d_in[1];
    // d_in[2] = mask (unused; causal mask computed analytically)
    const float* wq = (const float*)d_in[3];
    const float* wk = (const float*)d_in[4];
    const float* wv = (const float*)d_in[5];
    const float* wo = (const float*)d_in[6];
    float* out = (float*)d_out;

    void *pq, *pk, *pv, *py;
    void *pxh, *pxl, *pqh, *pql, *pkh, *pkl, *pvh, *pvl, *poh, *pol, *pyh, *pyl;
    cudaGetSymbolAddress(&pq, g_q);
    cudaGetSymbolAddress(&pk, g_k);
    cudaGetSymbolAddress(&pv, g_v);
    cudaGetSymbolAddress(&py, g_y);
    cudaGetSymbolAddress(&pxh, g_xhi);  cudaGetSymbolAddress(&pxl, g_xlo);
    cudaGetSymbolAddress(&pqh, g_wqhi); cudaGetSymbolAddress(&pql, g_wqlo);
    cudaGetSymbolAddress(&pkh, g_wkhi); cudaGetSymbolAddress(&pkl, g_wklo);
    cudaGetSymbolAddress(&pvh, g_wvhi); cudaGetSymbolAddress(&pvl, g_wvlo);
    cudaGetSymbolAddress(&poh, g_wohi); cudaGetSymbolAddress(&pol, g_wolo);
    cudaGetSymbolAddress(&pyh, g_yhi);  cudaGetSymbolAddress(&pyl, g_ylo);

    float* dq = (float*)pq;  float* dk = (float*)pk;
    float* dv = (float*)pv;  float* dy = (float*)py;
    __nv_bfloat16* xhi = (__nv_bfloat16*)pxh; __nv_bfloat16* xlo = (__nv_bfloat16*)pxl;
    __nv_bfloat16* qhi = (__nv_bfloat16*)pqh; __nv_bfloat16* qlo = (__nv_bfloat16*)pql;
    __nv_bfloat16* khi = (__nv_bfloat16*)pkh; __nv_bfloat16* klo = (__nv_bfloat16*)pkl;
    __nv_bfloat16* vhi = (__nv_bfloat16*)pvh; __nv_bfloat16* vlo = (__nv_bfloat16*)pvl;
    __nv_bfloat16* ohi = (__nv_bfloat16*)poh; __nv_bfloat16* olo = (__nv_bfloat16*)pol;
    __nv_bfloat16* yhi = (__nv_bfloat16*)pyh; __nv_bfloat16* ylo = (__nv_bfloat16*)pyl;

    cudaFuncSetAttribute(gemm_mma, cudaFuncAttributeMaxDynamicSharedMemorySize, GSMEM);
    cudaFuncSetAttribute(attn_kernel, cudaFuncAttributeMaxDynamicSharedMemorySize, ATTN_SMEM);

    // split inputs & weights to bf16 hi/lo
    {
        int n;
        n = SEQLEN*DIM;  split_kernel<<<(n+255)/256, 256>>>(x,  xhi, xlo, n);
        n = DIM*DIM;     split_kernel<<<(n+255)/256, 256>>>(wq, qhi, qlo, n);
        n = KVDIM*DIM;   split_kernel<<<(n+255)/256, 256>>>(wk, khi, klo, n);
        n = KVDIM*DIM;   split_kernel<<<(n+255)/256, 256>>>(wv, vhi, vlo, n);
        n = DIM*DIM;     split_kernel<<<(n+255)/256, 256>>>(wo, ohi, olo, n);
    }

    // projections (HMMA)
    gemm_mma<<<dim3(DIM/128,   SEQLEN/128), 256, GSMEM>>>(xhi, xlo, qhi, qlo, dq, DIM,   DIM);
    gemm_mma<<<dim3(KVDIM/128, SEQLEN/128), 256, GSMEM>>>(xhi, xlo, khi, klo, dk, KVDIM, DIM);
    gemm_mma<<<dim3(KVDIM/128, SEQLEN/128), 256, GSMEM>>>(xhi, xlo, vhi, vlo, dv, KVDIM, DIM);

    // RoPE
    {
        int nq = SEQLEN * NHEADS * (HDIM/2);
        rope_kernel<<<(nq+255)/256, 256>>>(dq, fc, NHEADS);
        int nk = SEQLEN * NKV * (HDIM/2);
        rope_kernel<<<(nk+255)/256, 256>>>(dk, fc, NKV);
    }

    // attention
    attn_kernel<<<dim3(SEQLEN/64, NHEADS), 256, ATTN_SMEM>>>(dq, dk, dv, dy);

    // output projection
    {
        int n = SEQLEN*DIM;
        split_kernel<<<(n+255)/256, 256>>>(dy, yhi, ylo, n);
    }
    gemm_mma<<<dim3(DIM/128, SEQLEN/128), 256, GSMEM>>>(yhi, ylo, ohi, olo, out, DIM, DIM);
}

// round 8
// speedup vs baseline: 1.7600x; 1.2716x over previous
#include <cuda_runtime.h>
#include <cuda_bf16.h>
#include <math.h>
#include <stdint.h>

#define SEQLEN  2048
#define DIM     4096
#define NHEADS  32
#define NKV     8
#define HDIM    128
#define KVDIM   (NKV*HDIM)

typedef __nv_bfloat16 bf16;

// single dynamic smem symbol shared by all kernels
extern __shared__ char dynsm[];

// ---------------- device scratch (no allocation allowed) -------------------
__device__ __align__(256) float g_q[(size_t)SEQLEN*DIM];
__device__ __align__(256) float g_k[(size_t)SEQLEN*KVDIM];
__device__ __align__(256) float g_v[(size_t)SEQLEN*KVDIM];
__device__ __align__(256) float g_y[(size_t)SEQLEN*DIM];
__device__ __align__(256) bf16 g_xhi[(size_t)SEQLEN*DIM];   // later reused: q_hi
__device__ __align__(256) bf16 g_xlo[(size_t)SEQLEN*DIM];   // later reused: q_lo
__device__ __align__(256) bf16 g_wqhi[(size_t)DIM*DIM];
__device__ __align__(256) bf16 g_wqlo[(size_t)DIM*DIM];
__device__ __align__(256) bf16 g_wkhi[(size_t)KVDIM*DIM];
__device__ __align__(256) bf16 g_wklo[(size_t)KVDIM*DIM];
__device__ __align__(256) bf16 g_wvhi[(size_t)KVDIM*DIM];
__device__ __align__(256) bf16 g_wvlo[(size_t)KVDIM*DIM];
__device__ __align__(256) bf16 g_wohi[(size_t)DIM*DIM];
__device__ __align__(256) bf16 g_wolo[(size_t)DIM*DIM];
__device__ __align__(256) bf16 g_yhi[(size_t)SEQLEN*DIM];
__device__ __align__(256) bf16 g_ylo[(size_t)SEQLEN*DIM];
__device__ __align__(256) bf16 g_khi[(size_t)SEQLEN*KVDIM];
__device__ __align__(256) bf16 g_klo[(size_t)SEQLEN*KVDIM];
__device__ __align__(256) bf16 g_vhi[(size_t)SEQLEN*KVDIM];
__device__ __align__(256) bf16 g_vlo[(size_t)SEQLEN*KVDIM];

// ---------------- split fp32 -> (hi, lo) bf16 ------------------------------
__global__ void split_kernel(const float* __restrict__ in, bf16* __restrict__ hi,
                             bf16* __restrict__ lo, int n){
    int i = blockIdx.x * blockDim.x + threadIdx.x;
    if (i < n){
        float x = in[i];
        bf16 h = __float2bfloat16(x);
        hi[i] = h;
        lo[i] = __float2bfloat16(x - __bfloat162float(h));
    }
}

// ---------------- HMMA helper ----------------------------------------------
__device__ __forceinline__ void mma16816(float* d, const uint32_t* a, const uint32_t* b){
    asm volatile(
        "mma.sync.aligned.m16n8k16.row.col.f32.bf16.bf16.f32 "
        "{%0,%1,%2,%3}, {%4,%5,%6,%7}, {%8,%9}, {%0,%1,%2,%3};"
        : "+f"(d[0]), "+f"(d[1]), "+f"(d[2]), "+f"(d[3])
        : "r"(a[0]), "r"(a[1]), "r"(a[2]), "r"(a[3]), "r"(b[0]), "r"(b[1]));
}

__device__ __forceinline__ void cpa16(void* smem_dst, const void* gmem_src){
    asm volatile("cp.async.cg.shared.global [%0], [%1], 16;"
                 :: "r"((uint32_t)__cvta_generic_to_shared(smem_dst)), "l"(gmem_src));
}

// ---------------- bf16 split GEMM: C[M,N] = A[M,K] @ B[N,K]^T --------------
#define BKC   32
#define RSTR  80
#define TILEB (128*RSTR)
#define STAGEB (4*TILEB)
#define NSTG  3
#define GSMEM (NSTG*STAGEB)

__global__ __launch_bounds__(256, 1) void gemm_mma(
    const bf16* __restrict__ Ahi, const bf16* __restrict__ Alo,
    const bf16* __restrict__ Bhi, const bf16* __restrict__ Blo,
    float* __restrict__ C, int N, int K)
{
    char* smb = dynsm;
    const int tid  = threadIdx.x;
    const int wid  = tid >> 5;
    const int lane = tid & 31;
    const int g  = lane >> 2;
    const int tg = lane & 3;
    const int warpM = (wid >> 2) * 64;
    const int warpN = (wid & 3) * 32;
    const int row0 = blockIdx.y * 128;
    const int col0 = blockIdx.x * 128;

    float acc[4][4][4];
#pragma unroll
    for (int i = 0; i < 4; i++)
#pragma unroll
        for (int j = 0; j < 4; j++)
#pragma unroll
            for (int l = 0; l < 4; l++) acc[i][j][l] = 0.0f;

    const int lr = tid & 127;
    const int lq = tid >> 7;

    const bf16* srcs[4];
    srcs[0] = Ahi + (size_t)(row0 + lr) * K;
    srcs[1] = Alo + (size_t)(row0 + lr) * K;
    srcs[2] = Bhi + (size_t)(col0 + lr) * K;
    srcs[3] = Blo + (size_t)(col0 + lr) * K;

    auto load_stage = [&](int c, int st){
        char* stb = smb + st*STAGEB;
        int k0 = c * BKC;
#pragma unroll
        for (int t = 0; t < 4; t++){
            char* dst = stb + t*TILEB + lr*RSTR + lq*32;
            const bf16* src = srcs[t] + k0 + lq*16;
            cpa16(dst, src);
            cpa16(dst+16, src+8);
        }
    };

    const int nc = K / BKC;
    load_stage(0, 0); asm volatile("cp.async.commit_group;" ::: "memory");
    load_stage(1, 1); asm volatile("cp.async.commit_group;" ::: "memory");

    for (int c = 0; c < nc; c++){
        int cl = c + 2;
        if (cl < nc) load_stage(cl, cl % NSTG);
        asm volatile("cp.async.commit_group;" ::: "memory");
        asm volatile("cp.async.wait_group 2;"  ::: "memory");
        __syncthreads();

        char* stb = smb + (c % NSTG)*STAGEB;
        char* As_h = stb;
        char* As_l = stb + TILEB;
        char* Bs_h = stb + 2*TILEB;
        char* Bs_l = stb + 3*TILEB;

#pragma unroll
        for (int kc = 0; kc < 2; kc++){
            int colb = kc*16 + tg*2;
            uint32_t afh[4][4], afl[4][4];
#pragma unroll
            for (int mt = 0; mt < 4; mt++){
                int r = warpM + mt*16 + g;
                afh[mt][0] = *(const uint32_t*)(As_h + r*RSTR + colb*2);
                afh[mt][1] = *(const uint32_t*)(As_h + (r+8)*RSTR + colb*2);
                afh[mt][2] = *(const uint32_t*)(As_h + r*RSTR + (colb+8)*2);
                afh[mt][3] = *(const uint32_t*)(As_h + (r+8)*RSTR + (colb+8)*2);
                afl[mt][0] = *(const uint32_t*)(As_l + r*RSTR + colb*2);
                afl[mt][1] = *(const uint32_t*)(As_l + (r+8)*RSTR + colb*2);
                afl[mt][2] = *(const uint32_t*)(As_l + r*RSTR + (colb+8)*2);
                afl[mt][3] = *(const uint32_t*)(As_l + (r+8)*RSTR + (colb+8)*2);
            }
            uint32_t bfh[4][2], bfl[4][2];
#pragma unroll
            for (int nt = 0; nt < 4; nt++){
                int r = warpN + nt*8 + g;
                bfh[nt][0] = *(const uint32_t*)(Bs_h + r*RSTR + colb*2);
                bfh[nt][1] = *(const uint32_t*)(Bs_h + r*RSTR + (colb+8)*2);
                bfl[nt][0] = *(const uint32_t*)(Bs_l + r*RSTR + colb*2);
                bfl[nt][1] = *(const uint32_t*)(Bs_l + r*RSTR + (colb+8)*2);
            }
#pragma unroll
            for (int mt = 0; mt < 4; mt++)
#pragma unroll
                for (int nt = 0; nt < 4; nt++){
                    mma16816(acc[mt][nt], afh[mt], bfh[nt]);
                    mma16816(acc[mt][nt], afh[mt], bfl[nt]);
                    mma16816(acc[mt][nt], afl[mt], bfh[nt]);
                }
        }
        __syncthreads();
    }

#pragma unroll
    for (int mt = 0; mt < 4; mt++){
#pragma unroll
        for (int nt = 0; nt < 4; nt++){
            int r0 = row0 + warpM + mt*16 + g;
            int c0 = col0 + warpN + nt*8 + tg*2;
            *(float2*)(C + (size_t)r0*N + c0)     = make_float2(acc[mt][nt][0], acc[mt][nt][1]);
            *(float2*)(C + (size_t)(r0+8)*N + c0) = make_float2(acc[mt][nt][2], acc[mt][nt][3]);
        }
    }
}

// ---------------- RoPE (interleaved pairs) --------------------------------
__global__ void rope_kernel(float* __restrict__ t, const float* __restrict__ fc,
                            int nheads)
{
    int idx = blockIdx.x * blockDim.x + threadIdx.x;
    int total = SEQLEN * nheads * (HDIM / 2);
    if (idx >= total) return;
    int p = idx & 63;
    int h = (idx >> 6) % nheads;
    int s = idx / (64 * nheads);
    float c  = fc[s * HDIM + p * 2 + 0];
    float sn = fc[s * HDIM + p * 2 + 1];
    float* base = t + (size_t)s * nheads * HDIM + h * HDIM + p * 2;
    float x0 = base[0], x1 = base[1];
    base[0] = x0 * c - x1 * sn;
    base[1] = x1 * c + x0 * sn;
}

// ---------------- Flash attention (HMMA, split-bf16, online softmax) -------
// block: 256 threads (8 warps), 64 q-rows x 1 head. K/V tiles of 64 tokens,
// double-buffered cp.async. 3-pass split MMA for both QK^T and PV.
#define QKSTR 136               // bf16 elems per smem row (128 + 8 pad) = 272 B
#define OFF_QH 0
#define OFF_QL 17408
#define OFF_KB 34816            // + st*34816 : Kh ; +17408 : Kl
#define OFF_VB 104448           // + st*34816 : Vh ; +17408 : Vl
#define OFF_SS 174080           // fp32 [64][73]
#define SSTRF  73
#define OFF_PH 192768           // bf16 [64][72]
#define OFF_PL 201984
#define PSTR   72
#define OFF_M  211200
#define OFF_L  211456
#define OFF_A  211712
#define ATTN_SMEM2 211968

__global__ __launch_bounds__(256, 1) void attn_mma(
    const bf16* __restrict__ qh, const bf16* __restrict__ ql,
    const bf16* __restrict__ kh, const bf16* __restrict__ kl,
    const bf16* __restrict__ vh, const bf16* __restrict__ vl,
    float* __restrict__ y)
{
    char* sb = dynsm;
    float* m_s = (float*)(sb + OFF_M);
    float* l_s = (float*)(sb + OFF_L);
    float* a_s = (float*)(sb + OFF_A);

    const int tid  = threadIdx.x;
    const int wid  = tid >> 5;
    const int lane = tid & 31;
    const int g  = lane >> 2;
    const int tg = lane & 3;
    const int qt = (gridDim.x - 1) - blockIdx.x;   // longest blocks first
    const int h  = blockIdx.y;
    const int hk = h >> 2;
    const int q0 = qt * 64;
    const float scale = 0.08838834764831845f;

    // ---- prologue: load Q (once) + K/V tile 0 (stage 0) ----
    {
#pragma unroll
        for (int i = 0; i < 4; i++){
            int chunk = tid + i*256;           // 1024 chunks
            int r = chunk >> 4, c = chunk & 15;
            size_t go = (size_t)(q0 + r)*DIM + h*HDIM + c*8;
            cpa16(sb + OFF_QH + r*272 + c*16, qh + go);
            cpa16(sb + OFF_QL + r*272 + c*16, ql + go);
        }
    }
    auto load_kv = [&](int st, int j0){
#pragma unroll
        for (int i = 0; i < 4; i++){
            int chunk = tid + i*256;
            int r = chunk >> 4, c = chunk & 15;
            size_t go = (size_t)(j0 + r)*KVDIM + hk*HDIM + c*8;
            char* kb = sb + OFF_KB + st*34816 + r*272 + c*16;
            char* vb = sb + OFF_VB + st*34816 + r*272 + c*16;
            cpa16(kb,         kh + go);
            cpa16(kb + 17408, kl + go);
            cpa16(vb,         vh + go);
            cpa16(vb + 17408, vl + go);
        }
    };
    load_kv(0, 0);
    asm volatile("cp.async.commit_group;" ::: "memory");

    if (tid < 64){ m_s[tid] = -INFINITY; l_s[tid] = 0.0f; }

    float o[4][2][4];
#pragma unroll
    for (int mt = 0; mt < 4; mt++)
#pragma unroll
        for (int nt = 0; nt < 2; nt++)
#pragma unroll
            for (int l = 0; l < 4; l++) o[mt][nt][l] = 0.0f;

    const int ntile = qt + 1;
    for (int jt = 0; jt < ntile; jt++){
        const int st = jt & 1;
        const int j0 = jt * 64;
        asm volatile("cp.async.wait_group 0;" ::: "memory");
        __syncthreads();
        if (jt + 1 < ntile) load_kv(st ^ 1, (jt+1)*64);
        asm volatile("cp.async.commit_group;" ::: "memory");

        // ---- S = Q K^T (warp owns S cols [wid*8, wid*8+8)) ----
        char* Khs = sb + OFF_KB + st*34816;
        char* Kls = Khs + 17408;
        float sacc[4][4];
#pragma unroll
        for (int mt = 0; mt < 4; mt++)
#pragma unroll
            for (int l = 0; l < 4; l++) sacc[mt][l] = 0.0f;

#pragma unroll
        for (int ks = 0; ks < 8; ks++){
            int colb = ks*16 + tg*2;
            uint32_t bh[2], bl[2];
            {
                int r = wid*8 + g;
                bh[0] = *(const uint32_t*)(Khs + r*272 + colb*2);
                bh[1] = *(const uint32_t*)(Khs + r*272 + (colb+8)*2);
                bl[0] = *(const uint32_t*)(Kls + r*272 + colb*2);
                bl[1] = *(const uint32_t*)(Kls + r*272 + (colb+8)*2);
            }
#pragma unroll
            for (int mt = 0; mt < 4; mt++){
                int r = mt*16 + g;
                uint32_t ah[4], al[4];
                ah[0] = *(const uint32_t*)(sb + OFF_QH + r*272 + colb*2);
                ah[1] = *(const uint32_t*)(sb + OFF_QH + (r+8)*272 + colb*2);
                ah[2] = *(const uint32_t*)(sb + OFF_QH + r*272 + (colb+8)*2);
                ah[3] = *(const uint32_t*)(sb + OFF_QH + (r+8)*272 + (colb+8)*2);
                al[0] = *(const uint32_t*)(sb + OFF_QL + r*272 + colb*2);
                al[1] = *(const uint32_t*)(sb + OFF_QL + (r+8)*272 + colb*2);
                al[2] = *(const uint32_t*)(sb + OFF_QL + r*272 + (colb+8)*2);
                al[3] = *(const uint32_t*)(sb + OFF_QL + (r+8)*272 + (colb+8)*2);
                mma16816(sacc[mt], ah, bh);
                mma16816(sacc[mt], ah, bl);
                mma16816(sacc[mt], al, bh);
            }
        }
        // write S with scale + causal mask
        {
            float* Ss = (float*)(sb + OFF_SS);
            int c0 = wid*8 + tg*2;
#pragma unroll
            for (int mt = 0; mt < 4; mt++){
                int r0 = mt*16 + g, r1 = r0 + 8;
                float s00 = sacc[mt][0]*scale, s01 = sacc[mt][1]*scale;
                float s10 = sacc[mt][2]*scale, s11 = sacc[mt][3]*scale;
                if (j0 + c0     > q0 + r0) s00 = -1e9f;
                if (j0 + c0 + 1 > q0 + r0) s01 = -1e9f;
                if (j0 + c0     > q0 + r1) s10 = -1e9f;
                if (j0 + c0 + 1 > q0 + r1) s11 = -1e9f;
                Ss[r0*SSTRF + c0] = s00; Ss[r0*SSTRF + c0+1] = s01;
                Ss[r1*SSTRF + c0] = s10; Ss[r1*SSTRF + c0+1] = s11;
            }
        }
        __syncthreads();

        // ---- online softmax: 4 lanes per row ----
        {
            float* Ss = (float*)(sb + OFF_SS);
            bf16* Ph = (bf16*)(sb + OFF_PH);
            bf16* Pl = (bf16*)(sb + OFF_PL);
            int row = tid >> 2, part = tid & 3;
            float* srow = Ss + row*SSTRF + part*16;
            float tmax = -INFINITY;
#pragma unroll
            for (int c = 0; c < 16; c++) tmax = fmaxf(tmax, srow[c]);
            tmax = fmaxf(tmax, __shfl_xor_sync(0xffffffffu, tmax, 1));
            tmax = fmaxf(tmax, __shfl_xor_sync(0xffffffffu, tmax, 2));
            float mold = m_s[row];
            float mnew = fmaxf(mold, tmax);
            float alpha = (mold == -INFINITY) ? 0.0f : __expf(mold - mnew);
            float sum = 0.0f;
            bf16* phrow = Ph + row*PSTR + part*16;
            bf16* plrow = Pl + row*PSTR + part*16;
#pragma unroll
            for (int c = 0; c < 16; c++){
                float p = __expf(srow[c] - mnew);
                sum += p;
                bf16 ph = __float2bfloat16(p);
                phrow[c] = ph;
                plrow[c] = __float2bfloat16(p - __bfloat162float(ph));
            }
            sum += __shfl_xor_sync(0xffffffffu, sum, 1);
            sum += __shfl_xor_sync(0xffffffffu, sum, 2);
            if (part == 0){
                l_s[row] = l_s[row]*alpha + sum;
                m_s[row] = mnew;
                a_s[row] = alpha;
            }
        }
        __syncthreads();

        // ---- rescale o, then O += P V (warp owns hd cols [wid*16, wid*16+16)) ----
#pragma unroll
        for (int mt = 0; mt < 4; mt++){
            float alA = a_s[mt*16 + g];
            float alB = a_s[mt*16 + g + 8];
#pragma unroll
            for (int nt = 0; nt < 2; nt++){
                o[mt][nt][0] *= alA; o[mt][nt][1] *= alA;
                o[mt][nt][2] *= alB; o[mt][nt][3] *= alB;
            }
        }
        {
            bf16* Ph = (bf16*)(sb + OFF_PH);
            bf16* Pl = (bf16*)(sb + OFF_PL);
            const uint16_t* Vhs = (const uint16_t*)(sb + OFF_VB + st*34816);
            const uint16_t* Vls = (const uint16_t*)(sb + OFF_VB + st*34816 + 17408);
#pragma unroll
            for (int ksv = 0; ksv < 4; ksv++){
                int colb = ksv*16 + tg*2;
                uint32_t aph[4][4], apl[4][4];
#pragma unroll
                for (int mt = 0; mt < 4; mt++){
                    int r = mt*16 + g;
                    aph[mt][0] = *(const uint32_t*)(Ph + r*PSTR + colb);
                    aph[mt][1] = *(const uint32_t*)(Ph + (r+8)*PSTR + colb);
                    aph[mt][2] = *(const uint32_t*)(Ph + r*PSTR + colb + 8);
                    aph[mt][3] = *(const uint32_t*)(Ph + (r+8)*PSTR + colb + 8);
                    apl[mt][0] = *(const uint32_t*)(Pl + r*PSTR + colb);
                    apl[mt][1] = *(const uint32_t*)(Pl + (r+8)*PSTR + colb);
                    apl[mt][2] = *(const uint32_t*)(Pl + r*PSTR + colb + 8);
                    apl[mt][3] = *(const uint32_t*)(Pl + (r+8)*PSTR + colb + 8);
                }
#pragma unroll
                for (int nt = 0; nt < 2; nt++){
                    int n = wid*16 + nt*8 + g;
                    int k0 = ksv*16 + tg*2;
                    uint32_t bvh[2], bvl[2];
                    bvh[0] = (uint32_t)Vhs[k0*QKSTR + n]     | ((uint32_t)Vhs[(k0+1)*QKSTR + n] << 16);
                    bvh[1] = (uint32_t)Vhs[(k0+8)*QKSTR + n] | ((uint32_t)Vhs[(k0+9)*QKSTR + n] << 16);
                    bvl[0] = (uint32_t)Vls[k0*QKSTR + n]     | ((uint32_t)Vls[(k0+1)*QKSTR + n] << 16);
                    bvl[1] = (uint32_t)Vls[(k0+8)*QKSTR + n] | ((uint32_t)Vls[(k0+9)*QKSTR + n] << 16);
#pragma unroll
                    for (int mt = 0; mt < 4; mt++){
                        mma16816(o[mt][nt], aph[mt], bvh);
                        mma16816(o[mt][nt], aph[mt], bvl);
                        mma16816(o[mt][nt], apl[mt], bvh);
                    }
                }
            }
        }
        __syncthreads();
    }

    // ---- epilogue: divide by l, write y ----
#pragma unroll
    for (int mt = 0; mt < 4; mt++){
        float invA = 1.0f / l_s[mt*16 + g];
        float invB = 1.0f / l_s[mt*16 + g + 8];
#pragma unroll
        for (int nt = 0; nt < 2; nt++){
            int col = h*HDIM + wid*16 + nt*8 + tg*2;
            int r0 = q0 + mt*16 + g;
            *(float2*)(y + (size_t)r0*DIM + col)     = make_float2(o[mt][nt][0]*invA, o[mt][nt][1]*invA);
            *(float2*)(y + (size_t)(r0+8)*DIM + col) = make_float2(o[mt][nt][2]*invB, o[mt][nt][3]*invB);
        }
    }
}

// ---------------- launch ---------------------------------------------------
extern "C" void kernel_launch(void* const* d_in, const int* in_sizes, int n_in,
                              void* d_out, int out_size)
{
    const float* x  = (const float*)d_in[0];
    const float* fc = (const float*)d_in[1];
    // d_in[2] = mask (unused; causal mask computed analytically)
    const float* wq = (const float*)d_in[3];
    const float* wk = (const float*)d_in[4];
    const float* wv = (const float*)d_in[5];
    const float* wo = (const float*)d_in[6];
    float* out = (float*)d_out;

    void *pq, *pk, *pv, *py;
    void *pxh, *pxl, *pqh, *pql, *pkh, *pkl, *pvh, *pvl, *poh, *pol, *pyh, *pyl;
    void *pkh2, *pkl2, *pvh2, *pvl2;
    cudaGetSymbolAddress(&pq, g_q);
    cudaGetSymbolAddress(&pk, g_k);
    cudaGetSymbolAddress(&pv, g_v);
    cudaGetSymbolAddress(&py, g_y);
    cudaGetSymbolAddress(&pxh, g_xhi);  cudaGetSymbolAddress(&pxl, g_xlo);
    cudaGetSymbolAddress(&pqh, g_wqhi); cudaGetSymbolAddress(&pql, g_wqlo);
    cudaGetSymbolAddress(&pkh, g_wkhi); cudaGetSymbolAddress(&pkl, g_wklo);
    cudaGetSymbolAddress(&pvh, g_wvhi); cudaGetSymbolAddress(&pvl, g_wvlo);
    cudaGetSymbolAddress(&poh, g_wohi); cudaGetSymbolAddress(&pol, g_wolo);
    cudaGetSymbolAddress(&pyh, g_yhi);  cudaGetSymbolAddress(&pyl, g_ylo);
    cudaGetSymbolAddress(&pkh2, g_khi); cudaGetSymbolAddress(&pkl2, g_klo);
    cudaGetSymbolAddress(&pvh2, g_vhi); cudaGetSymbolAddress(&pvl2, g_vlo);

    float* dq = (float*)pq;  float* dk = (float*)pk;
    float* dv = (float*)pv;  float* dy = (float*)py;
    bf16* xhi = (bf16*)pxh; bf16* xlo = (bf16*)pxl;
    bf16* qhi = (bf16*)pqh; bf16* qlo = (bf16*)pql;
    bf16* khi = (bf16*)pkh; bf16* klo = (bf16*)pkl;
    bf16* vhi = (bf16*)pvh; bf16* vlo = (bf16*)pvl;
    bf16* ohi = (bf16*)poh; bf16* olo = (bf16*)pol;
    bf16* yhi = (bf16*)pyh; bf16* ylo = (bf16*)pyl;
    bf16* akh = (bf16*)pkh2; bf16* akl = (bf16*)pkl2;
    bf16* avh = (bf16*)pvh2; bf16* avl = (bf16*)pvl2;

    cudaFuncSetAttribute(gemm_mma, cudaFuncAttributeMaxDynamicSharedMemorySize, GSMEM);
    cudaFuncSetAttribute(attn_mma, cudaFuncAttributeMaxDynamicSharedMemorySize, ATTN_SMEM2);

    // split inputs & weights to bf16 hi/lo
    {
        int n;
        n = SEQLEN*DIM;  split_kernel<<<(n+255)/256, 256>>>(x,  xhi, xlo, n);
        n = DIM*DIM;     split_kernel<<<(n+255)/256, 256>>>(wq, qhi, qlo, n);
        n = KVDIM*DIM;   split_kernel<<<(n+255)/256, 256>>>(wk, khi, klo, n);
        n = KVDIM*DIM;   split_kernel<<<(n+255)/256, 256>>>(wv, vhi, vlo, n);
        n = DIM*DIM;     split_kernel<<<(n+255)/256, 256>>>(wo, ohi, olo, n);
    }

    // projections (HMMA)
    gemm_mma<<<dim3(DIM/128,   SEQLEN/128), 256, GSMEM>>>(xhi, xlo, qhi, qlo, dq, DIM,   DIM);
    gemm_mma<<<dim3(KVDIM/128, SEQLEN/128), 256, GSMEM>>>(xhi, xlo, khi, klo, dk, KVDIM, DIM);
    gemm_mma<<<dim3(KVDIM/128, SEQLEN/128), 256, GSMEM>>>(xhi, xlo, vhi, vlo, dv, KVDIM, DIM);

    // RoPE
    {
        int nq = SEQLEN * NHEADS * (HDIM/2);
        rope_kernel<<<(nq+255)/256, 256>>>(dq, fc, NHEADS);
        int nk = SEQLEN * NKV * (HDIM/2);
        rope_kernel<<<(nk+255)/256, 256>>>(dk, fc, NKV);
    }

    // split q/k/v into bf16 hi/lo for the HMMA attention (q reuses x buffers)
    {
        int n;
        n = SEQLEN*DIM;   split_kernel<<<(n+255)/256, 256>>>(dq, xhi, xlo, n);
        n = SEQLEN*KVDIM; split_kernel<<<(n+255)/256, 256>>>(dk, akh, akl, n);
        n = SEQLEN*KVDIM; split_kernel<<<(n+255)/256, 256>>>(dv, avh, avl, n);
    }

    // attention (HMMA)
    attn_mma<<<dim3(SEQLEN/64, NHEADS), 256, ATTN_SMEM2>>>(xhi, xlo, akh, akl, avh, avl, dy);

    // output projection
    {
        int n = SEQLEN*DIM;
        split_kernel<<<(n+255)/256, 256>>>(dy, yhi, ylo, n);
    }
    gemm_mma<<<dim3(DIM/128, SEQLEN/128), 256, GSMEM>>>(yhi, ylo, ohi, olo, out, DIM, DIM);
}

// round 9
// speedup vs baseline: 1.8178x; 1.0329x over previous
#include <cuda_runtime.h>
#include <cuda_bf16.h>
#include <math.h>
#include <stdint.h>

#define SEQLEN  2048
#define DIM     4096
#define NHEADS  32
#define NKV     8
#define HDIM    128
#define KVDIM   (NKV*HDIM)

typedef __nv_bfloat16 bf16;

// single dynamic smem symbol shared by all kernels
extern __shared__ char dynsm[];

// ---------------- device scratch (no allocation allowed) -------------------
__device__ __align__(256) float g_q[(size_t)SEQLEN*DIM];
__device__ __align__(256) float g_k[(size_t)SEQLEN*KVDIM];
__device__ __align__(256) float g_v[(size_t)SEQLEN*KVDIM];
__device__ __align__(256) float g_y[(size_t)SEQLEN*DIM];
__device__ __align__(256) bf16 g_xhi[(size_t)SEQLEN*DIM];   // later reused: q_hi
__device__ __align__(256) bf16 g_xlo[(size_t)SEQLEN*DIM];   // later reused: q_lo
__device__ __align__(256) bf16 g_wqhi[(size_t)DIM*DIM];
__device__ __align__(256) bf16 g_wqlo[(size_t)DIM*DIM];
__device__ __align__(256) bf16 g_wkhi[(size_t)KVDIM*DIM];
__device__ __align__(256) bf16 g_wklo[(size_t)KVDIM*DIM];
__device__ __align__(256) bf16 g_wvhi[(size_t)KVDIM*DIM];
__device__ __align__(256) bf16 g_wvlo[(size_t)KVDIM*DIM];
__device__ __align__(256) bf16 g_wohi[(size_t)DIM*DIM];
__device__ __align__(256) bf16 g_wolo[(size_t)DIM*DIM];
__device__ __align__(256) bf16 g_yhi[(size_t)SEQLEN*DIM];
__device__ __align__(256) bf16 g_ylo[(size_t)SEQLEN*DIM];
__device__ __align__(256) bf16 g_khi[(size_t)SEQLEN*KVDIM];
__device__ __align__(256) bf16 g_klo[(size_t)SEQLEN*KVDIM];
__device__ __align__(256) bf16 g_vhi[(size_t)SEQLEN*KVDIM];
__device__ __align__(256) bf16 g_vlo[(size_t)SEQLEN*KVDIM];

// ---------------- split fp32 -> (hi, lo) bf16 ------------------------------
__global__ void split_kernel(const float* __restrict__ in, bf16* __restrict__ hi,
                             bf16* __restrict__ lo, int n){
    int i = blockIdx.x * blockDim.x + threadIdx.x;
    if (i < n){
        float x = in[i];
        bf16 h = __float2bfloat16(x);
        hi[i] = h;
        lo[i] = __float2bfloat16(x - __bfloat162float(h));
    }
}

// ---------------- MMA / LDSM helpers ---------------------------------------
__device__ __forceinline__ void mma16816(float* d, const uint32_t* a, const uint32_t* b){
    asm volatile(
        "mma.sync.aligned.m16n8k16.row.col.f32.bf16.bf16.f32 "
        "{%0,%1,%2,%3}, {%4,%5,%6,%7}, {%8,%9}, {%0,%1,%2,%3};"
        : "+f"(d[0]), "+f"(d[1]), "+f"(d[2]), "+f"(d[3])
        : "r"(a[0]), "r"(a[1]), "r"(a[2]), "r"(a[3]), "r"(b[0]), "r"(b[1]));
}

__device__ __forceinline__ void ldsm4(uint32_t* r, uint32_t saddr){
    asm volatile("ldmatrix.sync.aligned.m8n8.x4.shared.b16 {%0,%1,%2,%3}, [%4];"
                 : "=r"(r[0]), "=r"(r[1]), "=r"(r[2]), "=r"(r[3]) : "r"(saddr));
}

__device__ __forceinline__ void cpa16(void* smem_dst, const void* gmem_src){
    asm volatile("cp.async.cg.shared.global [%0], [%1], 16;"
                 :: "r"((uint32_t)__cvta_generic_to_shared(smem_dst)), "l"(gmem_src));
}

// ---------------- bf16 split GEMM: C[M,N] = A[M,K] @ B[N,K]^T --------------
// CTA tile 128x128, BK=32, 512 threads (4x4 warps, 32x32 per warp),
// 3-stage cp.async pipeline, ldmatrix fragment loads,
// 3-pass split accumulation (AhBh + AhBl + AlBh).
#define BKC   32
#define RSTR  80
#define TILEB (128*RSTR)
#define STAGEB (4*TILEB)
#define NSTG  3
#define GSMEM (NSTG*STAGEB)

__global__ __launch_bounds__(512, 1) void gemm_mma(
    const bf16* __restrict__ Ahi, const bf16* __restrict__ Alo,
    const bf16* __restrict__ Bhi, const bf16* __restrict__ Blo,
    float* __restrict__ C, int N, int K)
{
    char* smb = dynsm;
    const int tid  = threadIdx.x;
    const int wid  = tid >> 5;
    const int lane = tid & 31;
    const int g  = lane >> 2;
    const int tg = lane & 3;
    const int warpM = (wid >> 2) * 32;   // 0,32,64,96
    const int warpN = (wid & 3) * 32;    // 0,32,64,96
    const int row0 = blockIdx.y * 128;
    const int col0 = blockIdx.x * 128;

    float acc[2][4][4];
#pragma unroll
    for (int i = 0; i < 2; i++)
#pragma unroll
        for (int j = 0; j < 4; j++)
#pragma unroll
            for (int l = 0; l < 4; l++) acc[i][j][l] = 0.0f;

    // loader: thread handles tile tt = tid>>7, row = tid&127, 4 x 16B
    const int ltt = tid >> 7;        // 0..3
    const int lr  = tid & 127;

    const bf16* lsrc;
    {
        const bf16* s0 = Ahi + (size_t)(row0 + lr) * K;
        const bf16* s1 = Alo + (size_t)(row0 + lr) * K;
        const bf16* s2 = Bhi + (size_t)(col0 + lr) * K;
        const bf16* s3 = Blo + (size_t)(col0 + lr) * K;
        lsrc = (ltt == 0) ? s0 : (ltt == 1) ? s1 : (ltt == 2) ? s2 : s3;
    }

    auto load_stage = [&](int c, int st){
        char* dstrow = smb + st*STAGEB + ltt*TILEB + lr*RSTR;
        const bf16* src = lsrc + c*BKC;
#pragma unroll
        for (int j = 0; j < 4; j++)
            cpa16(dstrow + j*16, src + j*8);
    };

    // LDSM base addresses (shared-space u32)
    const uint32_t smbase = (uint32_t)__cvta_generic_to_shared(smb);
    // A: lane -> row warpM + mt*16 + (lane&15), col byte kc*32 + (lane>>4)*16
    const uint32_t aoff = (uint32_t)((warpM + (lane & 15)) * RSTR + (lane >> 4) * 16);
    // B: lane -> row warpN + ntp*16 + ((lane>>4)<<3) + (lane&7), col byte kc*32 + ((lane>>3)&1)*16
    const uint32_t boff = (uint32_t)((warpN + ((lane >> 4) << 3) + (lane & 7)) * RSTR + ((lane >> 3) & 1) * 16);

    const int nc = K / BKC;
    load_stage(0, 0); asm volatile("cp.async.commit_group;" ::: "memory");
    load_stage(1, 1); asm volatile("cp.async.commit_group;" ::: "memory");

    for (int c = 0; c < nc; c++){
        int cl = c + 2;
        if (cl < nc) load_stage(cl, cl % NSTG);
        asm volatile("cp.async.commit_group;" ::: "memory");
        asm volatile("cp.async.wait_group 2;"  ::: "memory");
        __syncthreads();

        uint32_t stb = smbase + (uint32_t)((c % NSTG)*STAGEB);
        uint32_t Ah = stb + aoff;
        uint32_t Al = Ah + TILEB;
        uint32_t Bh = stb + 2*TILEB + boff;
        uint32_t Bl = Bh + TILEB;

#pragma unroll
        for (int kc = 0; kc < 2; kc++){
            uint32_t kb = kc*32;
            uint32_t afh[2][4], afl[2][4], bfh[2][4], bfl[2][4];
#pragma unroll
            for (int mt = 0; mt < 2; mt++){
                ldsm4(afh[mt], Ah + mt*16*RSTR + kb);
                ldsm4(afl[mt], Al + mt*16*RSTR + kb);
            }
#pragma unroll
            for (int ntp = 0; ntp < 2; ntp++){
                ldsm4(bfh[ntp], Bh + ntp*16*RSTR + kb);
                ldsm4(bfl[ntp], Bl + ntp*16*RSTR + kb);
            }
#pragma unroll
            for (int mt = 0; mt < 2; mt++)
#pragma unroll
                for (int nt = 0; nt < 4; nt++){
                    const uint32_t* bh = &bfh[nt >> 1][(nt & 1) * 2];
                    const uint32_t* bl = &bfl[nt >> 1][(nt & 1) * 2];
                    mma16816(acc[mt][nt], afh[mt], bh);
                    mma16816(acc[mt][nt], afh[mt], bl);
                    mma16816(acc[mt][nt], afl[mt], bh);
                }
        }
        __syncthreads();
    }

    // epilogue
#pragma unroll
    for (int mt = 0; mt < 2; mt++){
#pragma unroll
        for (int nt = 0; nt < 4; nt++){
            int r0 = row0 + warpM + mt*16 + g;
            int c0 = col0 + warpN + nt*8 + tg*2;
            *(float2*)(C + (size_t)r0*N + c0)     = make_float2(acc[mt][nt][0], acc[mt][nt][1]);
            *(float2*)(C + (size_t)(r0+8)*N + c0) = make_float2(acc[mt][nt][2], acc[mt][nt][3]);
        }
    }
}

// ---------------- RoPE (interleaved pairs) --------------------------------
__global__ void rope_kernel(float* __restrict__ t, const float* __restrict__ fc,
                            int nheads)
{
    int idx = blockIdx.x * blockDim.x + threadIdx.x;
    int total = SEQLEN * nheads * (HDIM / 2);
    if (idx >= total) return;
    int p = idx & 63;
    int h = (idx >> 6) % nheads;
    int s = idx / (64 * nheads);
    float c  = fc[s * HDIM + p * 2 + 0];
    float sn = fc[s * HDIM + p * 2 + 1];
    float* base = t + (size_t)s * nheads * HDIM + h * HDIM + p * 2;
    float x0 = base[0], x1 = base[1];
    base[0] = x0 * c - x1 * sn;
    base[1] = x1 * c + x0 * sn;
}

// ---------------- Flash attention (HMMA, split-bf16, online softmax) -------
#define QKSTR 136               // bf16 elems per smem row (128 + 8 pad) = 272 B
#define OFF_QH 0
#define OFF_QL 17408
#define OFF_KB 34816            // + st*34816 : Kh ; +17408 : Kl
#define OFF_VB 104448           // + st*34816 : Vh ; +17408 : Vl
#define OFF_SS 174080           // fp32 [64][73]
#define SSTRF  73
#define OFF_PH 192768           // bf16 [64][72]
#define OFF_PL 201984
#define PSTR   72
#define OFF_M  211200
#define OFF_L  211456
#define OFF_A  211712
#define ATTN_SMEM2 211968

__global__ __launch_bounds__(256, 1) void attn_mma(
    const bf16* __restrict__ qh, const bf16* __restrict__ ql,
    const bf16* __restrict__ kh, const bf16* __restrict__ kl,
    const bf16* __restrict__ vh, const bf16* __restrict__ vl,
    float* __restrict__ y)
{
    char* sb = dynsm;
    float* m_s = (float*)(sb + OFF_M);
    float* l_s = (float*)(sb + OFF_L);
    float* a_s = (float*)(sb + OFF_A);

    const int tid  = threadIdx.x;
    const int wid  = tid >> 5;
    const int lane = tid & 31;
    const int g  = lane >> 2;
    const int tg = lane & 3;
    const int qt = (gridDim.x - 1) - blockIdx.x;   // longest blocks first
    const int h  = blockIdx.y;
    const int hk = h >> 2;
    const int q0 = qt * 64;
    const float scale = 0.08838834764831845f;

    // ---- prologue: load Q (once) + K/V tile 0 (stage 0) ----
    {
#pragma unroll
        for (int i = 0; i < 4; i++){
            int chunk = tid + i*256;           // 1024 chunks
            int r = chunk >> 4, c = chunk & 15;
            size_t go = (size_t)(q0 + r)*DIM + h*HDIM + c*8;
            cpa16(sb + OFF_QH + r*272 + c*16, qh + go);
            cpa16(sb + OFF_QL + r*272 + c*16, ql + go);
        }
    }
    auto load_kv = [&](int st, int j0){
#pragma unroll
        for (int i = 0; i < 4; i++){
            int chunk = tid + i*256;
            int r = chunk >> 4, c = chunk & 15;
            size_t go = (size_t)(j0 + r)*KVDIM + hk*HDIM + c*8;
            char* kb = sb + OFF_KB + st*34816 + r*272 + c*16;
            char* vb = sb + OFF_VB + st*34816 + r*272 + c*16;
            cpa16(kb,         kh + go);
            cpa16(kb + 17408, kl + go);
            cpa16(vb,         vh + go);
            cpa16(vb + 17408, vl + go);
        }
    };
    load_kv(0, 0);
    asm volatile("cp.async.commit_group;" ::: "memory");

    if (tid < 64){ m_s[tid] = -INFINITY; l_s[tid] = 0.0f; }

    float o[4][2][4];
#pragma unroll
    for (int mt = 0; mt < 4; mt++)
#pragma unroll
        for (int nt = 0; nt < 2; nt++)
#pragma unroll
            for (int l = 0; l < 4; l++) o[mt][nt][l] = 0.0f;

    const int ntile = qt + 1;
    for (int jt = 0; jt < ntile; jt++){
        const int st = jt & 1;
        const int j0 = jt * 64;
        asm volatile("cp.async.wait_group 0;" ::: "memory");
        __syncthreads();
        if (jt + 1 < ntile) load_kv(st ^ 1, (jt+1)*64);
        asm volatile("cp.async.commit_group;" ::: "memory");

        // ---- S = Q K^T (warp owns S cols [wid*8, wid*8+8)) ----
        char* Khs = sb + OFF_KB + st*34816;
        char* Kls = Khs + 17408;
        float sacc[4][4];
#pragma unroll
        for (int mt = 0; mt < 4; mt++)
#pragma unroll
            for (int l = 0; l < 4; l++) sacc[mt][l] = 0.0f;

#pragma unroll
        for (int ks = 0; ks < 8; ks++){
            int colb = ks*16 + tg*2;
            uint32_t bh[2], bl[2];
            {
                int r = wid*8 + g;
                bh[0] = *(const uint32_t*)(Khs + r*272 + colb*2);
                bh[1] = *(const uint32_t*)(Khs + r*272 + (colb+8)*2);
                bl[0] = *(const uint32_t*)(Kls + r*272 + colb*2);
                bl[1] = *(const uint32_t*)(Kls + r*272 + (colb+8)*2);
            }
#pragma unroll
            for (int mt = 0; mt < 4; mt++){
                int r = mt*16 + g;
                uint32_t ah[4], al[4];
                ah[0] = *(const uint32_t*)(sb + OFF_QH + r*272 + colb*2);
                ah[1] = *(const uint32_t*)(sb + OFF_QH + (r+8)*272 + colb*2);
                ah[2] = *(const uint32_t*)(sb + OFF_QH + r*272 + (colb+8)*2);
                ah[3] = *(const uint32_t*)(sb + OFF_QH + (r+8)*272 + (colb+8)*2);
                al[0] = *(const uint32_t*)(sb + OFF_QL + r*272 + colb*2);
                al[1] = *(const uint32_t*)(sb + OFF_QL + (r+8)*272 + colb*2);
                al[2] = *(const uint32_t*)(sb + OFF_QL + r*272 + (colb+8)*2);
                al[3] = *(const uint32_t*)(sb + OFF_QL + (r+8)*272 + (colb+8)*2);
                mma16816(sacc[mt], ah, bh);
                mma16816(sacc[mt], ah, bl);
                mma16816(sacc[mt], al, bh);
            }
        }
        // write S with scale + causal mask
        {
            float* Ss = (float*)(sb + OFF_SS);
            int c0 = wid*8 + tg*2;
#pragma unroll
            for (int mt = 0; mt < 4; mt++){
                int r0 = mt*16 + g, r1 = r0 + 8;
                float s00 = sacc[mt][0]*scale, s01 = sacc[mt][1]*scale;
                float s10 = sacc[mt][2]*scale, s11 = sacc[mt][3]*scale;
                if (j0 + c0     > q0 + r0) s00 = -1e9f;
                if (j0 + c0 + 1 > q0 + r0) s01 = -1e9f;
                if (j0 + c0     > q0 + r1) s10 = -1e9f;
                if (j0 + c0 + 1 > q0 + r1) s11 = -1e9f;
                Ss[r0*SSTRF + c0] = s00; Ss[r0*SSTRF + c0+1] = s01;
                Ss[r1*SSTRF + c0] = s10; Ss[r1*SSTRF + c0+1] = s11;
            }
        }
        __syncthreads();

        // ---- online softmax: 4 lanes per row ----
        {
            float* Ss = (float*)(sb + OFF_SS);
            bf16* Ph = (bf16*)(sb + OFF_PH);
            bf16* Pl = (bf16*)(sb + OFF_PL);
            int row = tid >> 2, part = tid & 3;
            float* srow = Ss + row*SSTRF + part*16;
            float tmax = -INFINITY;
#pragma unroll
            for (int c = 0; c < 16; c++) tmax = fmaxf(tmax, srow[c]);
            tmax = fmaxf(tmax, __shfl_xor_sync(0xffffffffu, tmax, 1));
            tmax = fmaxf(tmax, __shfl_xor_sync(0xffffffffu, tmax, 2));
            float mold = m_s[row];
            float mnew = fmaxf(mold, tmax);
            float alpha = (mold == -INFINITY) ? 0.0f : __expf(mold - mnew);
            float sum = 0.0f;
            bf16* phrow = Ph + row*PSTR + part*16;
            bf16* plrow = Pl + row*PSTR + part*16;
#pragma unroll
            for (int c = 0; c < 16; c++){
                float p = __expf(srow[c] - mnew);
                sum += p;
                bf16 ph = __float2bfloat16(p);
                phrow[c] = ph;
                plrow[c] = __float2bfloat16(p - __bfloat162float(ph));
            }
            sum += __shfl_xor_sync(0xffffffffu, sum, 1);
            sum += __shfl_xor_sync(0xffffffffu, sum, 2);
            if (part == 0){
                l_s[row] = l_s[row]*alpha + sum;
                m_s[row] = mnew;
                a_s[row] = alpha;
            }
        }
        __syncthreads();

        // ---- rescale o, then O += P V (warp owns hd cols [wid*16, wid*16+16)) ----
#pragma unroll
        for (int mt = 0; mt < 4; mt++){
            float alA = a_s[mt*16 + g];
            float alB = a_s[mt*16 + g + 8];
#pragma unroll
            for (int nt = 0; nt < 2; nt++){
                o[mt][nt][0] *= alA; o[mt][nt][1] *= alA;
                o[mt][nt][2] *= alB; o[mt][nt][3] *= alB;
            }
        }
        {
            bf16* Ph = (bf16*)(sb + OFF_PH);
            bf16* Pl = (bf16*)(sb + OFF_PL);
            const uint16_t* Vhs = (const uint16_t*)(sb + OFF_VB + st*34816);
            const uint16_t* Vls = (const uint16_t*)(sb + OFF_VB + st*34816 + 17408);
#pragma unroll
            for (int ksv = 0; ksv < 4; ksv++){
                int colb = ksv*16 + tg*2;
                uint32_t aph[4][4], apl[4][4];
#pragma unroll
                for (int mt = 0; mt < 4; mt++){
                    int r = mt*16 + g;
                    aph[mt][0] = *(const uint32_t*)(Ph + r*PSTR + colb);
                    aph[mt][1] = *(const uint32_t*)(Ph + (r+8)*PSTR + colb);
                    aph[mt][2] = *(const uint32_t*)(Ph + r*PSTR + colb + 8);
                    aph[mt][3] = *(const uint32_t*)(Ph + (r+8)*PSTR + colb + 8);
                    apl[mt][0] = *(const uint32_t*)(Pl + r*PSTR + colb);
                    apl[mt][1] = *(const uint32_t*)(Pl + (r+8)*PSTR + colb);
                    apl[mt][2] = *(const uint32_t*)(Pl + r*PSTR + colb + 8);
                    apl[mt][3] = *(const uint32_t*)(Pl + (r+8)*PSTR + colb + 8);
                }
#pragma unroll
                for (int nt = 0; nt < 2; nt++){
                    int n = wid*16 + nt*8 + g;
                    int k0 = ksv*16 + tg*2;
                    uint32_t bvh[2], bvl[2];
                    bvh[0] = (uint32_t)Vhs[k0*QKSTR + n]     | ((uint32_t)Vhs[(k0+1)*QKSTR + n] << 16);
                    bvh[1] = (uint32_t)Vhs[(k0+8)*QKSTR + n] | ((uint32_t)Vhs[(k0+9)*QKSTR + n] << 16);
                    bvl[0] = (uint32_t)Vls[k0*QKSTR + n]     | ((uint32_t)Vls[(k0+1)*QKSTR + n] << 16);
                    bvl[1] = (uint32_t)Vls[(k0+8)*QKSTR + n] | ((uint32_t)Vls[(k0+9)*QKSTR + n] << 16);
#pragma unroll
                    for (int mt = 0; mt < 4; mt++){
                        mma16816(o[mt][nt], aph[mt], bvh);
                        mma16816(o[mt][nt], aph[mt], bvl);
                        mma16816(o[mt][nt], apl[mt], bvh);
                    }
                }
            }
        }
        __syncthreads();
    }

    // ---- epilogue: divide by l, write y ----
#pragma unroll
    for (int mt = 0; mt < 4; mt++){
        float invA = 1.0f / l_s[mt*16 + g];
        float invB = 1.0f / l_s[mt*16 + g + 8];
#pragma unroll
        for (int nt = 0; nt < 2; nt++){
            int col = h*HDIM + wid*16 + nt*8 + tg*2;
            int r0 = q0 + mt*16 + g;
            *(float2*)(y + (size_t)r0*DIM + col)     = make_float2(o[mt][nt][0]*invA, o[mt][nt][1]*invA);
            *(float2*)(y + (size_t)(r0+8)*DIM + col) = make_float2(o[mt][nt][2]*invB, o[mt][nt][3]*invB);
        }
    }
}

// ---------------- launch ---------------------------------------------------
extern "C" void kernel_launch(void* const* d_in, const int* in_sizes, int n_in,
                              void* d_out, int out_size)
{
    const float* x  = (const float*)d_in[0];
    const float* fc = (const float*)d_in[1];
    // d_in[2] = mask (unused; causal mask computed analytically)
    const float* wq = (const float*)d_in[3];
    const float* wk = (const float*)d_in[4];
    const float* wv = (const float*)d_in[5];
    const float* wo = (const float*)d_in[6];
    float* out = (float*)d_out;

    void *pq, *pk, *pv, *py;
    void *pxh, *pxl, *pqh, *pql, *pkh, *pkl, *pvh, *pvl, *poh, *pol, *pyh, *pyl;
    void *pkh2, *pkl2, *pvh2, *pvl2;
    cudaGetSymbolAddress(&pq, g_q);
    cudaGetSymbolAddress(&pk, g_k);
    cudaGetSymbolAddress(&pv, g_v);
    cudaGetSymbolAddress(&py, g_y);
    cudaGetSymbolAddress(&pxh, g_xhi);  cudaGetSymbolAddress(&pxl, g_xlo);
    cudaGetSymbolAddress(&pqh, g_wqhi); cudaGetSymbolAddress(&pql, g_wqlo);
    cudaGetSymbolAddress(&pkh, g_wkhi); cudaGetSymbolAddress(&pkl, g_wklo);
    cudaGetSymbolAddress(&pvh, g_wvhi); cudaGetSymbolAddress(&pvl, g_wvlo);
    cudaGetSymbolAddress(&poh, g_wohi); cudaGetSymbolAddress(&pol, g_wolo);
    cudaGetSymbolAddress(&pyh, g_yhi);  cudaGetSymbolAddress(&pyl, g_ylo);
    cudaGetSymbolAddress(&pkh2, g_khi); cudaGetSymbolAddress(&pkl2, g_klo);
    cudaGetSymbolAddress(&pvh2, g_vhi); cudaGetSymbolAddress(&pvl2, g_vlo);

    float* dq = (float*)pq;  float* dk = (float*)pk;
    float* dv = (float*)pv;  float* dy = (float*)py;
    bf16* xhi = (bf16*)pxh; bf16* xlo = (bf16*)pxl;
    bf16* qhi = (bf16*)pqh; bf16* qlo = (bf16*)pql;
    bf16* khi = (bf16*)pkh; bf16* klo = (bf16*)pkl;
    bf16* vhi = (bf16*)pvh; bf16* vlo = (bf16*)pvl;
    bf16* ohi = (bf16*)poh; bf16* olo = (bf16*)pol;
    bf16* yhi = (bf16*)pyh; bf16* ylo = (bf16*)pyl;
    bf16* akh = (bf16*)pkh2; bf16* akl = (bf16*)pkl2;
    bf16* avh = (bf16*)pvh2; bf16* avl = (bf16*)pvl2;

    cudaFuncSetAttribute(gemm_mma, cudaFuncAttributeMaxDynamicSharedMemorySize, GSMEM);
    cudaFuncSetAttribute(attn_mma, cudaFuncAttributeMaxDynamicSharedMemorySize, ATTN_SMEM2);

    // split inputs & weights to bf16 hi/lo
    {
        int n;
        n = SEQLEN*DIM;  split_kernel<<<(n+255)/256, 256>>>(x,  xhi, xlo, n);
        n = DIM*DIM;     split_kernel<<<(n+255)/256, 256>>>(wq, qhi, qlo, n);
        n = KVDIM*DIM;   split_kernel<<<(n+255)/256, 256>>>(wk, khi, klo, n);
        n = KVDIM*DIM;   split_kernel<<<(n+255)/256, 256>>>(wv, vhi, vlo, n);
        n = DIM*DIM;     split_kernel<<<(n+255)/256, 256>>>(wo, ohi, olo, n);
    }

    // projections (HMMA)
    gemm_mma<<<dim3(DIM/128,   SEQLEN/128), 512, GSMEM>>>(xhi, xlo, qhi, qlo, dq, DIM,   DIM);
    gemm_mma<<<dim3(KVDIM/128, SEQLEN/128), 512, GSMEM>>>(xhi, xlo, khi, klo, dk, KVDIM, DIM);
    gemm_mma<<<dim3(KVDIM/128, SEQLEN/128), 512, GSMEM>>>(xhi, xlo, vhi, vlo, dv, KVDIM, DIM);

    // RoPE
    {
        int nq = SEQLEN * NHEADS * (HDIM/2);
        rope_kernel<<<(nq+255)/256, 256>>>(dq, fc, NHEADS);
        int nk = SEQLEN * NKV * (HDIM/2);
        rope_kernel<<<(nk+255)/256, 256>>>(dk, fc, NKV);
    }

    // split q/k/v into bf16 hi/lo for the HMMA attention (q reuses x buffers)
    {
        int n;
        n = SEQLEN*DIM;   split_kernel<<<(n+255)/256, 256>>>(dq, xhi, xlo, n);
        n = SEQLEN*KVDIM; split_kernel<<<(n+255)/256, 256>>>(dk, akh, akl, n);
        n = SEQLEN*KVDIM; split_kernel<<<(n+255)/256, 256>>>(dv, avh, avl, n);
    }

    // attention (HMMA)
    attn_mma<<<dim3(SEQLEN/64, NHEADS), 256, ATTN_SMEM2>>>(xhi, xlo, akh, akl, avh, avl, dy);

    // output projection
    {
        int n = SEQLEN*DIM;
        split_kernel<<<(n+255)/256, 256>>>(dy, yhi, ylo, n);
    }
    gemm_mma<<<dim3(DIM/128, SEQLEN/128), 512, GSMEM>>>(yhi, ylo, ohi, olo, out, DIM, DIM);
}

// round 11
// speedup vs baseline: 2.0784x; 1.1433x over previous
#include <cuda_runtime.h>
#include <cuda_bf16.h>
#include <math.h>
#include <stdint.h>

#define SEQLEN  2048
#define DIM     4096
#define NHEADS  32
#define NKV     8
#define HDIM    128
#define KVDIM   (NKV*HDIM)

typedef __nv_bfloat16 bf16;

extern __shared__ char dynsm[];

// ---------------- device scratch -------------------------------------------
__device__ __align__(256) float g_q[(size_t)SEQLEN*DIM];
__device__ __align__(256) float g_k[(size_t)SEQLEN*KVDIM];
__device__ __align__(256) float g_v[(size_t)SEQLEN*KVDIM];
__device__ __align__(256) float g_y[(size_t)SEQLEN*DIM];
__device__ __align__(256) bf16 g_xhi[(size_t)SEQLEN*DIM];
__device__ __align__(256) bf16 g_xlo[(size_t)SEQLEN*DIM];
__device__ __align__(256) bf16 g_wqhi[(size_t)DIM*DIM];
__device__ __align__(256) bf16 g_wqlo[(size_t)DIM*DIM];
__device__ __align__(256) bf16 g_wkhi[(size_t)KVDIM*DIM];
__device__ __align__(256) bf16 g_wklo[(size_t)KVDIM*DIM];
__device__ __align__(256) bf16 g_wvhi[(size_t)KVDIM*DIM];
__device__ __align__(256) bf16 g_wvlo[(size_t)KVDIM*DIM];
__device__ __align__(256) bf16 g_wohi[(size_t)DIM*DIM];
__device__ __align__(256) bf16 g_wolo[(size_t)DIM*DIM];
__device__ __align__(256) bf16 g_yhi[(size_t)SEQLEN*DIM];
__device__ __align__(256) bf16 g_ylo[(size_t)SEQLEN*DIM];
__device__ __align__(256) bf16 g_khi[(size_t)SEQLEN*KVDIM];
__device__ __align__(256) bf16 g_klo[(size_t)SEQLEN*KVDIM];
__device__ __align__(256) bf16 g_vhi[(size_t)SEQLEN*KVDIM];
__device__ __align__(256) bf16 g_vlo[(size_t)SEQLEN*KVDIM];

// ---------------- split fp32 -> (hi, lo) bf16 ------------------------------
__global__ void split_kernel(const float* __restrict__ in, bf16* __restrict__ hi,
                             bf16* __restrict__ lo, int n){
    int i = blockIdx.x * blockDim.x + threadIdx.x;
    if (i < n){
        float x = in[i];
        bf16 h = __float2bfloat16(x);
        hi[i] = h;
        lo[i] = __float2bfloat16(x - __bfloat162float(h));
    }
}

// ---------------- MMA / LDSM helpers ---------------------------------------
__device__ __forceinline__ void mma16816(float* d, const uint32_t* a, const uint32_t* b){
    asm volatile(
        "mma.sync.aligned.m16n8k16.row.col.f32.bf16.bf16.f32 "
        "{%0,%1,%2,%3}, {%4,%5,%6,%7}, {%8,%9}, {%0,%1,%2,%3};"
        : "+f"(d[0]), "+f"(d[1]), "+f"(d[2]), "+f"(d[3])
        : "r"(a[0]), "r"(a[1]), "r"(a[2]), "r"(a[3]), "r"(b[0]), "r"(b[1]));
}

__device__ __forceinline__ void ldsm4(uint32_t* r, uint32_t saddr){
    asm volatile("ldmatrix.sync.aligned.m8n8.x4.shared.b16 {%0,%1,%2,%3}, [%4];"
                 : "=r"(r[0]), "=r"(r[1]), "=r"(r[2]), "=r"(r[3]) : "r"(saddr));
}

__device__ __forceinline__ void cpa16(void* smem_dst, const void* gmem_src){
    asm volatile("cp.async.cg.shared.global [%0], [%1], 16;"
                 :: "r"((uint32_t)__cvta_generic_to_shared(smem_dst)), "l"(gmem_src));
}
__device__ __forceinline__ void cpa16u(uint32_t smem_dst, const void* gmem_src){
    asm volatile("cp.async.cg.shared.global [%0], [%1], 16;"
                 :: "r"(smem_dst), "l"(gmem_src));
}

// ---------------- bf16 split GEMM: C[M,N] = A[M,K] @ B[N,K]^T --------------
// CTA tile 256x128, BK=32, 512 threads (4Mx4N warps, 64x32 per warp),
// 3-stage cp.async pipeline, ldmatrix fragment loads, 3-pass split accum.
#define BKC    32
#define RSTR   80
#define G_ATILE 20480            // 256*80
#define G_BTILE 10240            // 128*80
#define STAGEB  61440            // 2*ATILE + 2*BTILE
#define NSTG   3
#define GSMEM  (NSTG*STAGEB)     // 184320

__global__ __launch_bounds__(512, 1) void gemm_mma(
    const bf16* __restrict__ Ahi, const bf16* __restrict__ Alo,
    const bf16* __restrict__ Bhi, const bf16* __restrict__ Blo,
    float* __restrict__ C, int N, int K)
{
    char* smb = dynsm;
    const int tid  = threadIdx.x;
    const int wid  = tid >> 5;
    const int lane = tid & 31;
    const int g  = lane >> 2;
    const int tg = lane & 3;
    const int warpM = (wid >> 2) * 64;   // 0,64,128,192
    const int warpN = (wid & 3) * 32;    // 0,32,64,96
    const int row0 = blockIdx.y * 256;
    const int col0 = blockIdx.x * 128;

    float acc[4][4][4];
#pragma unroll
    for (int i = 0; i < 4; i++)
#pragma unroll
        for (int j = 0; j < 4; j++)
#pragma unroll
            for (int l = 0; l < 4; l++) acc[i][j][l] = 0.0f;

    // loader: 3072 cp.async per chunk, 6 per thread
    const bf16* lsrc[6]; uint32_t ldst[6];
#pragma unroll
    for (int o = 0; o < 6; o++){
        int opid = tid + o*512;
        int row = opid >> 2, seg = opid & 3;
        const bf16* base; uint32_t doff;
        if (row < 256)      { base = Ahi + (size_t)(row0 + row)      * K; doff = (uint32_t)row*80u; }
        else if (row < 512) { base = Alo + (size_t)(row0 + row - 256)* K; doff = 20480u + (uint32_t)(row-256)*80u; }
        else if (row < 640) { base = Bhi + (size_t)(col0 + row - 512)* K; doff = 40960u + (uint32_t)(row-512)*80u; }
        else                { base = Blo + (size_t)(col0 + row - 640)* K; doff = 51200u + (uint32_t)(row-640)*80u; }
        lsrc[o] = base + seg*8;
        ldst[o] = doff + seg*16;
    }
    const uint32_t smbase = (uint32_t)__cvta_generic_to_shared(smb);

    auto load_stage = [&](int c, int st){
        uint32_t sb2 = smbase + (uint32_t)(st*STAGEB);
#pragma unroll
        for (int o = 0; o < 6; o++)
            cpa16u(sb2 + ldst[o], lsrc[o] + c*BKC);
    };

    const uint32_t aoff = (uint32_t)((warpM + (lane & 15)) * 80 + (lane >> 4) * 16);
    const uint32_t boff = (uint32_t)((warpN + ((lane >> 4) << 3) + (lane & 7)) * 80 + ((lane >> 3) & 1) * 16);

    const int nc = K / BKC;
    load_stage(0, 0); asm volatile("cp.async.commit_group;" ::: "memory");
    load_stage(1, 1); asm volatile("cp.async.commit_group;" ::: "memory");

    for (int c = 0; c < nc; c++){
        int cl = c + 2;
        if (cl < nc) load_stage(cl, cl % NSTG);
        asm volatile("cp.async.commit_group;" ::: "memory");
        asm volatile("cp.async.wait_group 2;"  ::: "memory");
        __syncthreads();

        uint32_t stb = smbase + (uint32_t)((c % NSTG)*STAGEB);
        uint32_t Ah = stb + aoff;
        uint32_t Al = Ah + G_ATILE;
        uint32_t Bh = stb + 2*G_ATILE + boff;
        uint32_t Bl = Bh + G_BTILE;

#pragma unroll
        for (int kc = 0; kc < 2; kc++){
            uint32_t kb = kc*32;
#pragma unroll
            for (int half = 0; half < 2; half++){
                uint32_t afh[2][4], afl[2][4];
                ldsm4(afh[0], Ah + (half*2+0)*16*80 + kb);
                ldsm4(afh[1], Ah + (half*2+1)*16*80 + kb);
                ldsm4(afl[0], Al + (half*2+0)*16*80 + kb);
                ldsm4(afl[1], Al + (half*2+1)*16*80 + kb);
#pragma unroll
                for (int bh2 = 0; bh2 < 2; bh2++){
                    uint32_t bfh[4], bfl[4];
                    ldsm4(bfh, Bh + bh2*16*80 + kb);
                    ldsm4(bfl, Bl + bh2*16*80 + kb);
#pragma unroll
                    for (int m2 = 0; m2 < 2; m2++){
                        int mt = half*2 + m2;
#pragma unroll
                        for (int np = 0; np < 2; np++){
                            int nt = bh2*2 + np;
                            mma16816(acc[mt][nt], afh[m2], &bfh[np*2]);
                            mma16816(acc[mt][nt], afh[m2], &bfl[np*2]);
                            mma16816(acc[mt][nt], afl[m2], &bfh[np*2]);
                        }
                    }
                }
            }
        }
        __syncthreads();
    }

    // epilogue
#pragma unroll
    for (int mt = 0; mt < 4; mt++){
#pragma unroll
        for (int nt = 0; nt < 4; nt++){
            int r0 = row0 + warpM + mt*16 + g;
            int c0 = col0 + warpN + nt*8 + tg*2;
            *(float2*)(C + (size_t)r0*N + c0)     = make_float2(acc[mt][nt][0], acc[mt][nt][1]);
            *(float2*)(C + (size_t)(r0+8)*N + c0) = make_float2(acc[mt][nt][2], acc[mt][nt][3]);
        }
    }
}

// ---------------- RoPE ------------------------------------------------------
__global__ void rope_kernel(float* __restrict__ t, const float* __restrict__ fc,
                            int nheads)
{
    int idx = blockIdx.x * blockDim.x + threadIdx.x;
    int total = SEQLEN * nheads * (HDIM / 2);
    if (idx >= total) return;
    int p = idx & 63;
    int h = (idx >> 6) % nheads;
    int s = idx / (64 * nheads);
    float c  = fc[s * HDIM + p * 2 + 0];
    float sn = fc[s * HDIM + p * 2 + 1];
    float* base = t + (size_t)s * nheads * HDIM + h * HDIM + p * 2;
    float x0 = base[0], x1 = base[1];
    base[0] = x0 * c - x1 * sn;
    base[1] = x1 * c + x0 * sn;
}

// ---------------- Flash attention: 2 q-heads per CTA share K/V --------------
// 256 threads. K double-buffered, V single-buffered (overlapped with QK).
#define QKSTR 136
#define AQOF(sub) ((sub)*34816)        // QH ; +17408 : QL
#define AKB   69632                    // + st*34816 : Kh ; +17408 : Kl
#define AVB   139264                   // Vh ; +17408 : Vl
#define ASS   174080                   // fp32 [64][73]
#define SSTRF 73
#define APH   192768                   // bf16 [64][72]
#define APL   201984
#define PSTR  72
#define AM    211200                   // 128 floats
#define ALr   211712
#define AAr   212224
#define ATTN_SMEM2 212736

__global__ __launch_bounds__(256, 1) void attn_mma(
    const bf16* __restrict__ qh, const bf16* __restrict__ ql,
    const bf16* __restrict__ kh, const bf16* __restrict__ kl,
    const bf16* __restrict__ vh, const bf16* __restrict__ vl,
    float* __restrict__ y)
{
    char* sb = dynsm;
    float* m_s = (float*)(sb + AM);
    float* l_s = (float*)(sb + ALr);
    float* a_s = (float*)(sb + AAr);

    const int tid  = threadIdx.x;
    const int wid  = tid >> 5;
    const int lane = tid & 31;
    const int g  = lane >> 2;
    const int tg = lane & 3;
    const int qt = (gridDim.x - 1) - blockIdx.x;
    const int hy = blockIdx.y;
    const int hk = hy >> 1;
    const int h0 = hk*4 + (hy & 1)*2;      // heads h0, h0+1 share kv head hk
    const int q0 = qt * 64;
    const float scale = 0.08838834764831845f;

    // prologue: Q for both heads + K tile 0, one group
#pragma unroll
    for (int i = 0; i < 8; i++){
        int chunk = tid + i*256;            // 0..2047
        int sub = chunk >> 10;
        int w = chunk & 1023;
        int r = w >> 4, c2 = w & 15;
        size_t go = (size_t)(q0 + r)*DIM + (h0 + sub)*HDIM + c2*8;
        cpa16(sb + AQOF(sub) + r*272 + c2*16, qh + go);
        cpa16(sb + AQOF(sub) + 17408 + r*272 + c2*16, ql + go);
    }
    auto load_k = [&](int st, int j0){
#pragma unroll
        for (int i = 0; i < 4; i++){
            int chunk = tid + i*256;
            int r = chunk >> 4, c2 = chunk & 15;
            size_t go = (size_t)(j0 + r)*KVDIM + hk*HDIM + c2*8;
            char* kb2 = sb + AKB + st*34816 + r*272 + c2*16;
            cpa16(kb2, kh + go);
            cpa16(kb2 + 17408, kl + go);
        }
    };
    auto load_v = [&](int j0){
#pragma unroll
        for (int i = 0; i < 4; i++){
            int chunk = tid + i*256;
            int r = chunk >> 4, c2 = chunk & 15;
            size_t go = (size_t)(j0 + r)*KVDIM + hk*HDIM + c2*8;
            char* vb2 = sb + AVB + r*272 + c2*16;
            cpa16(vb2, vh + go);
            cpa16(vb2 + 17408, vl + go);
        }
    };
    load_k(0, 0);
    asm volatile("cp.async.commit_group;" ::: "memory");

    if (tid < 128){ m_s[tid] = -INFINITY; l_s[tid] = 0.0f; }

    float o[2][4][2][4];
#pragma unroll
    for (int s2 = 0; s2 < 2; s2++)
#pragma unroll
        for (int mt = 0; mt < 4; mt++)
#pragma unroll
            for (int nt = 0; nt < 2; nt++)
#pragma unroll
                for (int l = 0; l < 4; l++) o[s2][mt][nt][l] = 0.0f;

    const int ntile = qt + 1;
    for (int jt = 0; jt < ntile; jt++){
        const int st = jt & 1;
        const int j0 = jt * 64;
        asm volatile("cp.async.wait_group 0;" ::: "memory");
        __syncthreads();
        load_v(j0);
        asm volatile("cp.async.commit_group;" ::: "memory");   // group A = V(jt)
        if (jt + 1 < ntile) load_k(st ^ 1, (jt+1)*64);
        asm volatile("cp.async.commit_group;" ::: "memory");   // group B = K(jt+1) (may be empty)

        char* Khs = sb + AKB + st*34816;
        char* Kls = Khs + 17408;

        for (int sub = 0; sub < 2; sub++){
            const char* Qhs = sb + AQOF(sub);
            const char* Qls = Qhs + 17408;

            // ---- S = Q K^T ----
            float sacc[4][4];
#pragma unroll
            for (int mt = 0; mt < 4; mt++)
#pragma unroll
                for (int l = 0; l < 4; l++) sacc[mt][l] = 0.0f;

#pragma unroll
            for (int ks = 0; ks < 8; ks++){
                int colb = ks*16 + tg*2;
                uint32_t bh[2], bl[2];
                {
                    int r = wid*8 + g;
                    bh[0] = *(const uint32_t*)(Khs + r*272 + colb*2);
                    bh[1] = *(const uint32_t*)(Khs + r*272 + (colb+8)*2);
                    bl[0] = *(const uint32_t*)(Kls + r*272 + colb*2);
                    bl[1] = *(const uint32_t*)(Kls + r*272 + (colb+8)*2);
                }
#pragma unroll
                for (int mt = 0; mt < 4; mt++){
                    int r = mt*16 + g;
                    uint32_t ah[4], al[4];
                    ah[0] = *(const uint32_t*)(Qhs + r*272 + colb*2);
                    ah[1] = *(const uint32_t*)(Qhs + (r+8)*272 + colb*2);
                    ah[2] = *(const uint32_t*)(Qhs + r*272 + (colb+8)*2);
                    ah[3] = *(const uint32_t*)(Qhs + (r+8)*272 + (colb+8)*2);
                    al[0] = *(const uint32_t*)(Qls + r*272 + colb*2);
                    al[1] = *(const uint32_t*)(Qls + (r+8)*272 + colb*2);
                    al[2] = *(const uint32_t*)(Qls + r*272 + (colb+8)*2);
                    al[3] = *(const uint32_t*)(Qls + (r+8)*272 + (colb+8)*2);
                    mma16816(sacc[mt], ah, bh);
                    mma16816(sacc[mt], ah, bl);
                    mma16816(sacc[mt], al, bh);
                }
            }
            {
                float* Ss = (float*)(sb + ASS);
                int c0 = wid*8 + tg*2;
#pragma unroll
                for (int mt = 0; mt < 4; mt++){
                    int r0 = mt*16 + g, r1 = r0 + 8;
                    float s00 = sacc[mt][0]*scale, s01 = sacc[mt][1]*scale;
                    float s10 = sacc[mt][2]*scale, s11 = sacc[mt][3]*scale;
                    if (j0 + c0     > q0 + r0) s00 = -1e9f;
                    if (j0 + c0 + 1 > q0 + r0) s01 = -1e9f;
                    if (j0 + c0     > q0 + r1) s10 = -1e9f;
                    if (j0 + c0 + 1 > q0 + r1) s11 = -1e9f;
                    Ss[r0*SSTRF + c0] = s00; Ss[r0*SSTRF + c0+1] = s01;
                    Ss[r1*SSTRF + c0] = s10; Ss[r1*SSTRF + c0+1] = s11;
                }
            }
            __syncthreads();

            // ---- online softmax ----
            {
                float* Ss = (float*)(sb + ASS);
                bf16* Ph = (bf16*)(sb + APH);
                bf16* Pl = (bf16*)(sb + APL);
                int row = tid >> 2, part = tid & 3;
                float* srow = Ss + row*SSTRF + part*16;
                float tmax = -INFINITY;
#pragma unroll
                for (int c = 0; c < 16; c++) tmax = fmaxf(tmax, srow[c]);
                tmax = fmaxf(tmax, __shfl_xor_sync(0xffffffffu, tmax, 1));
                tmax = fmaxf(tmax, __shfl_xor_sync(0xffffffffu, tmax, 2));
                int mrow = sub*64 + row;
                float mold = m_s[mrow];
                float mnew = fmaxf(mold, tmax);
                float alpha = (mold == -INFINITY) ? 0.0f : __expf(mold - mnew);
                float sum = 0.0f;
                bf16* phrow = Ph + row*PSTR + part*16;
                bf16* plrow = Pl + row*PSTR + part*16;
#pragma unroll
                for (int c = 0; c < 16; c++){
                    float p = __expf(srow[c] - mnew);
                    sum += p;
                    bf16 ph = __float2bfloat16(p);
                    phrow[c] = ph;
                    plrow[c] = __float2bfloat16(p - __bfloat162float(ph));
                }
                sum += __shfl_xor_sync(0xffffffffu, sum, 1);
                sum += __shfl_xor_sync(0xffffffffu, sum, 2);
                if (part == 0){
                    l_s[mrow] = l_s[mrow]*alpha + sum;
                    m_s[mrow] = mnew;
                    a_s[mrow] = alpha;
                }
            }
            if (sub == 0){
                // ensure V(jt) landed (in-order group retirement: <=1 pending => A done)
                asm volatile("cp.async.wait_group 1;" ::: "memory");
            }
            __syncthreads();

            // ---- rescale o, then O += P V ----
#pragma unroll
            for (int mt = 0; mt < 4; mt++){
                float alA = a_s[sub*64 + mt*16 + g];
                float alB = a_s[sub*64 + mt*16 + g + 8];
#pragma unroll
                for (int nt = 0; nt < 2; nt++){
                    o[sub][mt][nt][0] *= alA; o[sub][mt][nt][1] *= alA;
                    o[sub][mt][nt][2] *= alB; o[sub][mt][nt][3] *= alB;
                }
            }
            {
                bf16* Ph = (bf16*)(sb + APH);
                bf16* Pl = (bf16*)(sb + APL);
                const uint16_t* Vhs = (const uint16_t*)(sb + AVB);
                const uint16_t* Vls = (const uint16_t*)(sb + AVB + 17408);
#pragma unroll
                for (int ksv = 0; ksv < 4; ksv++){
                    int colb = ksv*16 + tg*2;
                    uint32_t aph[4][4], apl[4][4];
#pragma unroll
                    for (int mt = 0; mt < 4; mt++){
                        int r = mt*16 + g;
                        aph[mt][0] = *(const uint32_t*)(Ph + r*PSTR + colb);
                        aph[mt][1] = *(const uint32_t*)(Ph + (r+8)*PSTR + colb);
                        aph[mt][2] = *(const uint32_t*)(Ph + r*PSTR + colb + 8);
                        aph[mt][3] = *(const uint32_t*)(Ph + (r+8)*PSTR + colb + 8);
                        apl[mt][0] = *(const uint32_t*)(Pl + r*PSTR + colb);
                        apl[mt][1] = *(const uint32_t*)(Pl + (r+8)*PSTR + colb);
                        apl[mt][2] = *(const uint32_t*)(Pl + r*PSTR + colb + 8);
                        apl[mt][3] = *(const uint32_t*)(Pl + (r+8)*PSTR + colb + 8);
                    }
#pragma unroll
                    for (int nt = 0; nt < 2; nt++){
                        int n = wid*16 + nt*8 + g;
                        int k0 = ksv*16 + tg*2;
                        uint32_t bvh[2], bvl[2];
                        bvh[0] = (uint32_t)Vhs[k0*QKSTR + n]     | ((uint32_t)Vhs[(k0+1)*QKSTR + n] << 16);
                        bvh[1] = (uint32_t)Vhs[(k0+8)*QKSTR + n] | ((uint32_t)Vhs[(k0+9)*QKSTR + n] << 16);
                        bvl[0] = (uint32_t)Vls[k0*QKSTR + n]     | ((uint32_t)Vls[(k0+1)*QKSTR + n] << 16);
                        bvl[1] = (uint32_t)Vls[(k0+8)*QKSTR + n] | ((uint32_t)Vls[(k0+9)*QKSTR + n] << 16);
#pragma unroll
                        for (int mt = 0; mt < 4; mt++){
                            mma16816(o[sub][mt][nt], aph[mt], bvh);
                            mma16816(o[sub][mt][nt], aph[mt], bvl);
                            mma16816(o[sub][mt][nt], apl[mt], bvh);
                        }
                    }
                }
            }
            __syncthreads();
        }
    }

    // epilogue
#pragma unroll
    for (int sub = 0; sub < 2; sub++){
#pragma unroll
        for (int mt = 0; mt < 4; mt++){
            float invA = 1.0f / l_s[sub*64 + mt*16 + g];
            float invB = 1.0f / l_s[sub*64 + mt*16 + g + 8];
#pragma unroll
            for (int nt = 0; nt < 2; nt++){
                int col = (h0+sub)*HDIM + wid*16 + nt*8 + tg*2;
                int r0 = q0 + mt*16 + g;
                *(float2*)(y + (size_t)r0*DIM + col)     = make_float2(o[sub][mt][nt][0]*invA, o[sub][mt][nt][1]*invA);
                *(float2*)(y + (size_t)(r0+8)*DIM + col) = make_float2(o[sub][mt][nt][2]*invB, o[sub][mt][nt][3]*invB);
            }
        }
    }
}

// ---------------- launch ---------------------------------------------------
extern "C" void kernel_launch(void* const* d_in, const int* in_sizes, int n_in,
                              void* d_out, int out_size)
{
    const float* x  = (const float*)d_in[0];
    const float* fc = (const float*)d_in[1];
    const float* wq = (const float*)d_in[3];
    const float* wk = (const float*)d_in[4];
    const float* wv = (const float*)d_in[5];
    const float* wo = (const float*)d_in[6];
    float* out = (float*)d_out;

    void *pq, *pk, *pv, *py;
    void *pxh, *pxl, *pqh, *pql, *pkh, *pkl, *pvh, *pvl, *poh, *pol, *pyh, *pyl;
    void *pkh2, *pkl2, *pvh2, *pvl2;
    cudaGetSymbolAddress(&pq, g_q);
    cudaGetSymbolAddress(&pk, g_k);
    cudaGetSymbolAddress(&pv, g_v);
    cudaGetSymbolAddress(&py, g_y);
    cudaGetSymbolAddress(&pxh, g_xhi);  cudaGetSymbolAddress(&pxl, g_xlo);
    cudaGetSymbolAddress(&pqh, g_wqhi); cudaGetSymbolAddress(&pql, g_wqlo);
    cudaGetSymbolAddress(&pkh, g_wkhi); cudaGetSymbolAddress(&pkl, g_wklo);
    cudaGetSymbolAddress(&pvh, g_wvhi); cudaGetSymbolAddress(&pvl, g_wvlo);
    cudaGetSymbolAddress(&poh, g_wohi); cudaGetSymbolAddress(&pol, g_wolo);
    cudaGetSymbolAddress(&pyh, g_yhi);  cudaGetSymbolAddress(&pyl, g_ylo);
    cudaGetSymbolAddress(&pkh2, g_khi); cudaGetSymbolAddress(&pkl2, g_klo);
    cudaGetSymbolAddress(&pvh2, g_vhi); cudaGetSymbolAddress(&pvl2, g_vlo);

    float* dq = (float*)pq;  float* dk = (float*)pk;
    float* dv = (float*)pv;  float* dy = (float*)py;
    bf16* xhi = (bf16*)pxh; bf16* xlo = (bf16*)pxl;
    bf16* qhi = (bf16*)pqh; bf16* qlo = (bf16*)pql;
    bf16* khi = (bf16*)pkh; bf16* klo = (bf16*)pkl;
    bf16* vhi = (bf16*)pvh; bf16* vlo = (bf16*)pvl;
    bf16* ohi = (bf16*)poh; bf16* olo = (bf16*)pol;
    bf16* yhi = (bf16*)pyh; bf16* ylo = (bf16*)pyl;
    bf16* akh = (bf16*)pkh2; bf16* akl = (bf16*)pkl2;
    bf16* avh = (bf16*)pvh2; bf16* avl = (bf16*)pvl2;

    cudaFuncSetAttribute(gemm_mma, cudaFuncAttributeMaxDynamicSharedMemorySize, GSMEM);
    cudaFuncSetAttribute(attn_mma, cudaFuncAttributeMaxDynamicSharedMemorySize, ATTN_SMEM2);

    {
        int n;
        n = SEQLEN*DIM;  split_kernel<<<(n+255)/256, 256>>>(x,  xhi, xlo, n);
        n = DIM*DIM;     split_kernel<<<(n+255)/256, 256>>>(wq, qhi, qlo, n);
        n = KVDIM*DIM;   split_kernel<<<(n+255)/256, 256>>>(wk, khi, klo, n);
        n = KVDIM*DIM;   split_kernel<<<(n+255)/256, 256>>>(wv, vhi, vlo, n);
        n = DIM*DIM;     split_kernel<<<(n+255)/256, 256>>>(wo, ohi, olo, n);
    }

    // projections (HMMA, 256x128 tiles)
    gemm_mma<<<dim3(DIM/128,   SEQLEN/256), 512, GSMEM>>>(xhi, xlo, qhi, qlo, dq, DIM,   DIM);
    gemm_mma<<<dim3(KVDIM/128, SEQLEN/256), 512, GSMEM>>>(xhi, xlo, khi, klo, dk, KVDIM, DIM);
    gemm_mma<<<dim3(KVDIM/128, SEQLEN/256), 512, GSMEM>>>(xhi, xlo, vhi, vlo, dv, KVDIM, DIM);

    // RoPE
    {
        int nq = SEQLEN * NHEADS * (HDIM/2);
        rope_kernel<<<(nq+255)/256, 256>>>(dq, fc, NHEADS);
        int nk = SEQLEN * NKV * (HDIM/2);
        rope_kernel<<<(nk+255)/256, 256>>>(dk, fc, NKV);
    }

    // split q/k/v for HMMA attention
    {
        int n;
        n = SEQLEN*DIM;   split_kernel<<<(n+255)/256, 256>>>(dq, xhi, xlo, n);
        n = SEQLEN*KVDIM; split_kernel<<<(n+255)/256, 256>>>(dk, akh, akl, n);
        n = SEQLEN*KVDIM; split_kernel<<<(n+255)/256, 256>>>(dv, avh, avl, n);
    }

    // attention: 2 q-heads per CTA share KV
    attn_mma<<<dim3(SEQLEN/64, NHEADS/2), 256, ATTN_SMEM2>>>(xhi, xlo, akh, akl, avh, avl, dy);

    // output projection
    {
        int n = SEQLEN*DIM;
        split_kernel<<<(n+255)/256, 256>>>(dy, yhi, ylo, n);
    }
    gemm_mma<<<dim3(DIM/128, SEQLEN/256), 512, GSMEM>>>(yhi, ylo, ohi, olo, out, DIM, DIM);
}

// round 14
// speedup vs baseline: 2.6398x; 1.2701x over previous
#include <cuda_runtime.h>
#include <cuda_bf16.h>
#include <math.h>
#include <stdint.h>

#define SEQLEN  2048
#define DIM     4096
#define NHEADS  32
#define NKV     8
#define HDIM    128
#define KVDIM   (NKV*HDIM)

typedef __nv_bfloat16 bf16;

extern __shared__ char dynsm[];

// ---------------- device scratch -------------------------------------------
__device__ __align__(256) float g_q[(size_t)SEQLEN*DIM];
__device__ __align__(256) float g_k[(size_t)SEQLEN*KVDIM];
__device__ __align__(256) float g_v[(size_t)SEQLEN*KVDIM];
__device__ __align__(256) float g_y[(size_t)SEQLEN*DIM];
__device__ __align__(256) bf16 g_xhi[(size_t)SEQLEN*DIM];   // packed x / later q-split
__device__ __align__(256) bf16 g_xlo[(size_t)SEQLEN*DIM];
__device__ __align__(256) bf16 g_wqhi[(size_t)DIM*DIM];
__device__ __align__(256) bf16 g_wqlo[(size_t)DIM*DIM];
__device__ __align__(256) bf16 g_wkhi[(size_t)KVDIM*DIM];
__device__ __align__(256) bf16 g_wklo[(size_t)KVDIM*DIM];
__device__ __align__(256) bf16 g_wvhi[(size_t)KVDIM*DIM];
__device__ __align__(256) bf16 g_wvlo[(size_t)KVDIM*DIM];
__device__ __align__(256) bf16 g_wohi[(size_t)DIM*DIM];
__device__ __align__(256) bf16 g_wolo[(size_t)DIM*DIM];
__device__ __align__(256) bf16 g_yhi[(size_t)SEQLEN*DIM];
__device__ __align__(256) bf16 g_ylo[(size_t)SEQLEN*DIM];
__device__ __align__(256) bf16 g_khi[(size_t)SEQLEN*KVDIM];
__device__ __align__(256) bf16 g_klo[(size_t)SEQLEN*KVDIM];
__device__ __align__(256) bf16 g_vhi[(size_t)SEQLEN*KVDIM];
__device__ __align__(256) bf16 g_vlo[(size_t)SEQLEN*KVDIM];

// ---------------- plain split fp32 -> (hi, lo) bf16 (attention inputs) -----
__global__ void split_kernel(const float* __restrict__ in, bf16* __restrict__ hi,
                             bf16* __restrict__ lo, int n){
    int i = blockIdx.x * blockDim.x + threadIdx.x;
    if (i < n){
        float x = in[i];
        bf16 h = __float2bfloat16(x);
        hi[i] = h;
        lo[i] = __float2bfloat16(x - __bfloat162float(h));
    }
}

// ---------------- pack+split: fp32 [M,4096] -> K-chunked swizzled blocks ---
// block = (1<<blkshift) rows x 32 elems (64 B), layout [rowblk][chunk][row][64B],
// 16B-chunk swizzle j' = j ^ ((r>>1)&3)
__global__ void pack_split(const float* __restrict__ in, bf16* __restrict__ hi,
                           bf16* __restrict__ lo, int blkshift, int total8){
    int t = blockIdx.x * blockDim.x + threadIdx.x;
    if (t >= total8) return;
    int j = t & 3;
    int c = (t >> 2) & 127;          // K/32 = 128 chunks (K==4096 always)
    int r = t >> 9;
    const float4* src = (const float4*)(in + (size_t)r*4096 + c*32 + j*8);
    float4 f0 = src[0], f1 = src[1];
    float fv[8] = {f0.x, f0.y, f0.z, f0.w, f1.x, f1.y, f1.z, f1.w};
    union { bf16 b[8]; uint4 v; } H, L;
#pragma unroll
    for (int i2 = 0; i2 < 8; i2++){
        bf16 h = __float2bfloat16(fv[i2]);
        H.b[i2] = h;
        L.b[i2] = __float2bfloat16(fv[i2] - __bfloat162float(h));
    }
    int jp = j ^ ((r >> 1) & 3);
    int blkrows = 1 << blkshift;
    size_t off = (((size_t)(r >> blkshift) * 128 + c) << (blkshift + 5))
               + (size_t)(r & (blkrows - 1)) * 32 + jp * 8;
    *(uint4*)(hi + off) = H.v;
    *(uint4*)(lo + off) = L.v;
}

// ---------------- MMA / LDSM helpers ---------------------------------------
__device__ __forceinline__ void mma16816(float* d, const uint32_t* a, const uint32_t* b){
    asm volatile(
        "mma.sync.aligned.m16n8k16.row.col.f32.bf16.bf16.f32 "
        "{%0,%1,%2,%3}, {%4,%5,%6,%7}, {%8,%9}, {%0,%1,%2,%3};"
        : "+f"(d[0]), "+f"(d[1]), "+f"(d[2]), "+f"(d[3])
        : "r"(a[0]), "r"(a[1]), "r"(a[2]), "r"(a[3]), "r"(b[0]), "r"(b[1]));
}
__device__ __forceinline__ void ldsm4(uint32_t* r, uint32_t saddr){
    asm volatile("ldmatrix.sync.aligned.m8n8.x4.shared.b16 {%0,%1,%2,%3}, [%4];"
                 : "=r"(r[0]), "=r"(r[1]), "=r"(r[2]), "=r"(r[3]) : "r"(saddr));
}
__device__ __forceinline__ void cpa16(void* smem_dst, const void* gmem_src){
    asm volatile("cp.async.cg.shared.global [%0], [%1], 16;"
                 :: "r"((uint32_t)__cvta_generic_to_shared(smem_dst)), "l"(gmem_src));
}
__device__ __forceinline__ void cpbulk(uint32_t sdst, const void* gsrc, uint32_t bytes, uint32_t mbar){
    asm volatile("cp.async.bulk.shared::cta.global.mbarrier::complete_tx::bytes [%0], [%1], %2, [%3];"
                 :: "r"(sdst), "l"(gsrc), "r"(bytes), "r"(mbar) : "memory");
}
__device__ __forceinline__ void mbar_init(uint32_t a, uint32_t cnt){
    asm volatile("mbarrier.init.shared.b64 [%0], %1;" :: "r"(a), "r"(cnt) : "memory");
}
__device__ __forceinline__ void mbar_expect(uint32_t a, uint32_t bytes){
    asm volatile("mbarrier.arrive.expect_tx.shared.b64 _, [%0], %1;" :: "r"(a), "r"(bytes) : "memory");
}
__device__ __forceinline__ void mbar_wait(uint32_t a, uint32_t par){
    uint32_t done;
    asm volatile("{\n\t.reg .pred p;\n\t"
                 "mbarrier.try_wait.parity.acquire.cta.shared::cta.b64 p, [%1], %2;\n\t"
                 "selp.b32 %0,1,0,p;\n\t}"
                 : "=r"(done) : "r"(a), "r"(par) : "memory");
    if (!done){
        asm volatile("{\n\t.reg .pred P1;\n\t"
                     "W%=:\n\t"
                     "mbarrier.try_wait.parity.acquire.cta.shared::cta.b64 P1, [%0], %1, 0x989680;\n\t"
                     "@P1 bra.uni D%=;\n\t"
                     "bra.uni W%=;\n\t"
                     "D%=:\n\t}"
                     :: "r"(a), "r"(par) : "memory");
    }
}

// ---------------- bulk-fed GEMM: C[M,N] = A[M,K] @ B[N,K]^T ----------------
// CTA tile 256x128, K=4096 (128 chunks of 32), 512 threads, 3-stage bulk
// pipeline, ldmatrix + 3-pass split accumulation.
#define PB_ASZ 16384u            // A block: 256 rows x 64 B
#define PB_BSZ 8192u             // B block: 128 rows x 64 B
#define PSTAGE 49152u
#define PNSTG  3
#define PGSMEM (PNSTG*PSTAGE + 64)

__global__ __launch_bounds__(512, 1) void gemm_bulk(
    const bf16* __restrict__ Aph, const bf16* __restrict__ Apl,
    const bf16* __restrict__ Bph, const bf16* __restrict__ Bpl,
    float* __restrict__ C, int N)
{
    const int tid  = threadIdx.x;
    const int wid  = tid >> 5;
    const int lane = tid & 31;
    const int g  = lane >> 2;
    const int tg = lane & 3;
    const int warpM = (wid >> 2) * 64;
    const int warpN = (wid & 3) * 32;
    const int by = blockIdx.y, bx = blockIdx.x;
    const int nck = 128;

    const uint32_t smbase = (uint32_t)__cvta_generic_to_shared(dynsm);
    const uint32_t mb = smbase + PNSTG*PSTAGE;

    if (tid == 0){
        for (int s = 0; s < PNSTG; s++) mbar_init(mb + 8*s, 1);
    }
    __syncthreads();

    auto issue = [&](int c){
        int st = c % PNSTG;
        uint32_t sb2 = smbase + st*PSTAGE;
        uint32_t bar = mb + 8*st;
        mbar_expect(bar, 49152u);
        cpbulk(sb2,          Aph + ((size_t)by*nck + c)*8192, PB_ASZ, bar);
        cpbulk(sb2 + 16384,  Apl + ((size_t)by*nck + c)*8192, PB_ASZ, bar);
        cpbulk(sb2 + 32768,  Bph + ((size_t)bx*nck + c)*4096, PB_BSZ, bar);
        cpbulk(sb2 + 40960,  Bpl + ((size_t)bx*nck + c)*4096, PB_BSZ, bar);
    };
    if (tid == 0){ issue(0); issue(1); issue(2); }

    float acc[4][4][4];
#pragma unroll
    for (int i = 0; i < 4; i++)
#pragma unroll
        for (int j = 0; j < 4; j++)
#pragma unroll
            for (int l = 0; l < 4; l++) acc[i][j][l] = 0.0f;

    // per-thread constant swizzled fragment offsets
    const int la15 = lane & 15;
    uint32_t aoff[2], boff[2];
#pragma unroll
    for (int kc = 0; kc < 2; kc++){
        int jA = (kc*2 + (lane >> 4)) ^ ((la15 >> 1) & 3);
        aoff[kc] = (uint32_t)(la15*64 + jA*16);
        int rB = ((lane >> 4) << 3) + (lane & 7);
        int jB = (kc*2 + ((lane >> 3) & 1)) ^ (((lane & 7) >> 1) & 3);
        boff[kc] = (uint32_t)(rB*64 + jB*16);
    }

    for (int c = 0; c < nck; c++){
        int st = c % PNSTG;
        mbar_wait(mb + 8*st, (uint32_t)((c/PNSTG) & 1));

        uint32_t stb = smbase + st*PSTAGE;
        uint32_t Ah = stb + (uint32_t)(warpM*64);
        uint32_t Al = Ah + 16384;
        uint32_t Bh = stb + 32768 + (uint32_t)(warpN*64);
        uint32_t Bl = Bh + 8192;

#pragma unroll
        for (int kc = 0; kc < 2; kc++){
#pragma unroll
            for (int half = 0; half < 2; half++){
                uint32_t afh[2][4], afl[2][4];
                ldsm4(afh[0], Ah + (half*2+0)*1024 + aoff[kc]);
                ldsm4(afh[1], Ah + (half*2+1)*1024 + aoff[kc]);
                ldsm4(afl[0], Al + (half*2+0)*1024 + aoff[kc]);
                ldsm4(afl[1], Al + (half*2+1)*1024 + aoff[kc]);
#pragma unroll
                for (int bh2 = 0; bh2 < 2; bh2++){
                    uint32_t bfh[4], bfl[4];
                    ldsm4(bfh, Bh + bh2*1024 + boff[kc]);
                    ldsm4(bfl, Bl + bh2*1024 + boff[kc]);
#pragma unroll
                    for (int m2 = 0; m2 < 2; m2++){
                        int mt = half*2 + m2;
#pragma unroll
                        for (int np = 0; np < 2; np++){
                            int nt = bh2*2 + np;
                            mma16816(acc[mt][nt], afh[m2], &bfh[np*2]);
                            mma16816(acc[mt][nt], afh[m2], &bfl[np*2]);
                            mma16816(acc[mt][nt], afl[m2], &bfh[np*2]);
                        }
                    }
                }
            }
        }
        __syncthreads();
        if (tid == 0 && c + PNSTG < nck) issue(c + PNSTG);
    }

    const int row0 = by * 256, col0 = bx * 128;
#pragma unroll
    for (int mt = 0; mt < 4; mt++){
#pragma unroll
        for (int nt = 0; nt < 4; nt++){
            int r0 = row0 + warpM + mt*16 + g;
            int c0 = col0 + warpN + nt*8 + tg*2;
            *(float2*)(C + (size_t)r0*N + c0)     = make_float2(acc[mt][nt][0], acc[mt][nt][1]);
            *(float2*)(C + (size_t)(r0+8)*N + c0) = make_float2(acc[mt][nt][2], acc[mt][nt][3]);
        }
    }
}

// ---------------- RoPE ------------------------------------------------------
__global__ void rope_kernel(float* __restrict__ t, const float* __restrict__ fc,
                            int nheads)
{
    int idx = blockIdx.x * blockDim.x + threadIdx.x;
    int total = SEQLEN * nheads * (HDIM / 2);
    if (idx >= total) return;
    int p = idx & 63;
    int h = (idx >> 6) % nheads;
    int s = idx / (64 * nheads);
    float c  = fc[s * HDIM + p * 2 + 0];
    float sn = fc[s * HDIM + p * 2 + 1];
    float* base = t + (size_t)s * nheads * HDIM + h * HDIM + p * 2;
    float x0 = base[0], x1 = base[1];
    base[0] = x0 * c - x1 * sn;
    base[1] = x1 * c + x0 * sn;
}

// ---------------- Flash attention: 2 q-heads per CTA share K/V --------------
#define QKSTR 136
#define AQOF(sub) ((sub)*34816)
#define AKB   69632
#define AVB   139264
#define ASS   174080
#define SSTRF 73
#define APH   192768
#define APL   201984
#define PSTR  72
#define AM    211200
#define ALr   211712
#define AAr   212224
#define ATTN_SMEM2 212736

__global__ __launch_bounds__(256, 1) void attn_mma(
    const bf16* __restrict__ qh, const bf16* __restrict__ ql,
    const bf16* __restrict__ kh, const bf16* __restrict__ kl,
    const bf16* __restrict__ vh, const bf16* __restrict__ vl,
    float* __restrict__ y)
{
    char* sb = dynsm;
    float* m_s = (float*)(sb + AM);
    float* l_s = (float*)(sb + ALr);
    float* a_s = (float*)(sb + AAr);

    const int tid  = threadIdx.x;
    const int wid  = tid >> 5;
    const int lane = tid & 31;
    const int g  = lane >> 2;
    const int tg = lane & 3;
    const int qt = (gridDim.x - 1) - blockIdx.x;
    const int hy = blockIdx.y;
    const int hk = hy >> 1;
    const int h0 = hk*4 + (hy & 1)*2;
    const int q0 = qt * 64;
    const float scale = 0.08838834764831845f;

#pragma unroll
    for (int i = 0; i < 8; i++){
        int chunk = tid + i*256;
        int sub = chunk >> 10;
        int w = chunk & 1023;
        int r = w >> 4, c2 = w & 15;
        size_t go = (size_t)(q0 + r)*DIM + (h0 + sub)*HDIM + c2*8;
        cpa16(sb + AQOF(sub) + r*272 + c2*16, qh + go);
        cpa16(sb + AQOF(sub) + 17408 + r*272 + c2*16, ql + go);
    }
    auto load_k = [&](int st, int j0){
#pragma unroll
        for (int i = 0; i < 4; i++){
            int chunk = tid + i*256;
            int r = chunk >> 4, c2 = chunk & 15;
            size_t go = (size_t)(j0 + r)*KVDIM + hk*HDIM + c2*8;
            char* kb2 = sb + AKB + st*34816 + r*272 + c2*16;
            cpa16(kb2, kh + go);
            cpa16(kb2 + 17408, kl + go);
        }
    };
    auto load_v = [&](int j0){
#pragma unroll
        for (int i = 0; i < 4; i++){
            int chunk = tid + i*256;
            int r = chunk >> 4, c2 = chunk & 15;
            size_t go = (size_t)(j0 + r)*KVDIM + hk*HDIM + c2*8;
            char* vb2 = sb + AVB + r*272 + c2*16;
            cpa16(vb2, vh + go);
            cpa16(vb2 + 17408, vl + go);
        }
    };
    load_k(0, 0);
    asm volatile("cp.async.commit_group;" ::: "memory");

    if (tid < 128){ m_s[tid] = -INFINITY; l_s[tid] = 0.0f; }

    float o[2][4][2][4];
#pragma unroll
    for (int s2 = 0; s2 < 2; s2++)
#pragma unroll
        for (int mt = 0; mt < 4; mt++)
#pragma unroll
            for (int nt = 0; nt < 2; nt++)
#pragma unroll
                for (int l = 0; l < 4; l++) o[s2][mt][nt][l] = 0.0f;

    const int ntile = qt + 1;
    for (int jt = 0; jt < ntile; jt++){
        const int st = jt & 1;
        const int j0 = jt * 64;
        asm volatile("cp.async.wait_group 0;" ::: "memory");
        __syncthreads();
        load_v(j0);
        asm volatile("cp.async.commit_group;" ::: "memory");
        if (jt + 1 < ntile) load_k(st ^ 1, (jt+1)*64);
        asm volatile("cp.async.commit_group;" ::: "memory");

        char* Khs = sb + AKB + st*34816;
        char* Kls = Khs + 17408;

        for (int sub = 0; sub < 2; sub++){
            const char* Qhs = sb + AQOF(sub);
            const char* Qls = Qhs + 17408;

            float sacc[4][4];
#pragma unroll
            for (int mt = 0; mt < 4; mt++)
#pragma unroll
                for (int l = 0; l < 4; l++) sacc[mt][l] = 0.0f;

#pragma unroll
            for (int ks = 0; ks < 8; ks++){
                int colb = ks*16 + tg*2;
                uint32_t bh[2], bl[2];
                {
                    int r = wid*8 + g;
                    bh[0] = *(const uint32_t*)(Khs + r*272 + colb*2);
                    bh[1] = *(const uint32_t*)(Khs + r*272 + (colb+8)*2);
                    bl[0] = *(const uint32_t*)(Kls + r*272 + colb*2);
                    bl[1] = *(const uint32_t*)(Kls + r*272 + (colb+8)*2);
                }
#pragma unroll
                for (int mt = 0; mt < 4; mt++){
                    int r = mt*16 + g;
                    uint32_t ah[4], al[4];
                    ah[0] = *(const uint32_t*)(Qhs + r*272 + colb*2);
                    ah[1] = *(const uint32_t*)(Qhs + (r+8)*272 + colb*2);
                    ah[2] = *(const uint32_t*)(Qhs + r*272 + (colb+8)*2);
                    ah[3] = *(const uint32_t*)(Qhs + (r+8)*272 + (colb+8)*2);
                    al[0] = *(const uint32_t*)(Qls + r*272 + colb*2);
                    al[1] = *(const uint32_t*)(Qls + (r+8)*272 + colb*2);
                    al[2] = *(const uint32_t*)(Qls + r*272 + (colb+8)*2);
                    al[3] = *(const uint32_t*)(Qls + (r+8)*272 + (colb+8)*2);
                    mma16816(sacc[mt], ah, bh);
                    mma16816(sacc[mt], ah, bl);
                    mma16816(sacc[mt], al, bh);
                }
            }
            {
                float* Ss = (float*)(sb + ASS);
                int c0 = wid*8 + tg*2;
#pragma unroll
                for (int mt = 0; mt < 4; mt++){
                    int r0 = mt*16 + g, r1 = r0 + 8;
                    float s00 = sacc[mt][0]*scale, s01 = sacc[mt][1]*scale;
                    float s10 = sacc[mt][2]*scale, s11 = sacc[mt][3]*scale;
                    if (j0 + c0     > q0 + r0) s00 = -1e9f;
                    if (j0 + c0 + 1 > q0 + r0) s01 = -1e9f;
                    if (j0 + c0     > q0 + r1) s10 = -1e9f;
                    if (j0 + c0 + 1 > q0 + r1) s11 = -1e9f;
                    Ss[r0*SSTRF + c0] = s00; Ss[r0*SSTRF + c0+1] = s01;
                    Ss[r1*SSTRF + c0] = s10; Ss[r1*SSTRF + c0+1] = s11;
                }
            }
            __syncthreads();

            {
                float* Ss = (float*)(sb + ASS);
                bf16* Ph = (bf16*)(sb + APH);
                bf16* Pl = (bf16*)(sb + APL);
                int row = tid >> 2, part = tid & 3;
                float* srow = Ss + row*SSTRF + part*16;
                float tmax = -INFINITY;
#pragma unroll
                for (int c = 0; c < 16; c++) tmax = fmaxf(tmax, srow[c]);
                tmax = fmaxf(tmax, __shfl_xor_sync(0xffffffffu, tmax, 1));
                tmax = fmaxf(tmax, __shfl_xor_sync(0xffffffffu, tmax, 2));
                int mrow = sub*64 + row;
                float mold = m_s[mrow];
                float mnew = fmaxf(mold, tmax);
                float alpha = (mold == -INFINITY) ? 0.0f : __expf(mold - mnew);
                float sum = 0.0f;
                bf16* phrow = Ph + row*PSTR + part*16;
                bf16* plrow = Pl + row*PSTR + part*16;
#pragma unroll
                for (int c = 0; c < 16; c++){
                    float p = __expf(srow[c] - mnew);
                    sum += p;
                    bf16 ph = __float2bfloat16(p);
                    phrow[c] = ph;
                    plrow[c] = __float2bfloat16(p - __bfloat162float(ph));
                }
                sum += __shfl_xor_sync(0xffffffffu, sum, 1);
                sum += __shfl_xor_sync(0xffffffffu, sum, 2);
                if (part == 0){
                    l_s[mrow] = l_s[mrow]*alpha + sum;
                    m_s[mrow] = mnew;
                    a_s[mrow] = alpha;
                }
            }
            if (sub == 0){
                asm volatile("cp.async.wait_group 1;" ::: "memory");
            }
            __syncthreads();

#pragma unroll
            for (int mt = 0; mt < 4; mt++){
                float alA = a_s[sub*64 + mt*16 + g];
                float alB = a_s[sub*64 + mt*16 + g + 8];
#pragma unroll
                for (int nt = 0; nt < 2; nt++){
                    o[sub][mt][nt][0] *= alA; o[sub][mt][nt][1] *= alA;
                    o[sub][mt][nt][2] *= alB; o[sub][mt][nt][3] *= alB;
                }
            }
            {
                bf16* Ph = (bf16*)(sb + APH);
                bf16* Pl = (bf16*)(sb + APL);
                const uint16_t* Vhs = (const uint16_t*)(sb + AVB);
                const uint16_t* Vls = (const uint16_t*)(sb + AVB + 17408);
#pragma unroll
                for (int ksv = 0; ksv < 4; ksv++){
                    int colb = ksv*16 + tg*2;
                    uint32_t aph[4][4], apl[4][4];
#pragma unroll
                    for (int mt = 0; mt < 4; mt++){
                        int r = mt*16 + g;
                        aph[mt][0] = *(const uint32_t*)(Ph + r*PSTR + colb);
                        aph[mt][1] = *(const uint32_t*)(Ph + (r+8)*PSTR + colb);
                        aph[mt][2] = *(const uint32_t*)(Ph + r*PSTR + colb + 8);
                        aph[mt][3] = *(const uint32_t*)(Ph + (r+8)*PSTR + colb + 8);
                        apl[mt][0] = *(const uint32_t*)(Pl + r*PSTR + colb);
                        apl[mt][1] = *(const uint32_t*)(Pl + (r+8)*PSTR + colb);
                        apl[mt][2] = *(const uint32_t*)(Pl + r*PSTR + colb + 8);
                        apl[mt][3] = *(const uint32_t*)(Pl + (r+8)*PSTR + colb + 8);
                    }
#pragma unroll
                    for (int nt = 0; nt < 2; nt++){
                        int n = wid*16 + nt*8 + g;
                        int k0 = ksv*16 + tg*2;
                        uint32_t bvh[2], bvl[2];
                        bvh[0] = (uint32_t)Vhs[k0*QKSTR + n]     | ((uint32_t)Vhs[(k0+1)*QKSTR + n] << 16);
                        bvh[1] = (uint32_t)Vhs[(k0+8)*QKSTR + n] | ((uint32_t)Vhs[(k0+9)*QKSTR + n] << 16);
                        bvl[0] = (uint32_t)Vls[k0*QKSTR + n]     | ((uint32_t)Vls[(k0+1)*QKSTR + n] << 16);
                        bvl[1] = (uint32_t)Vls[(k0+8)*QKSTR + n] | ((uint32_t)Vls[(k0+9)*QKSTR + n] << 16);
#pragma unroll
                        for (int mt = 0; mt < 4; mt++){
                            mma16816(o[sub][mt][nt], aph[mt], bvh);
                            mma16816(o[sub][mt][nt], aph[mt], bvl);
                            mma16816(o[sub][mt][nt], apl[mt], bvh);
                        }
                    }
                }
            }
            __syncthreads();
        }
    }

#pragma unroll
    for (int sub = 0; sub < 2; sub++){
#pragma unroll
        for (int mt = 0; mt < 4; mt++){
            float invA = 1.0f / l_s[sub*64 + mt*16 + g];
            float invB = 1.0f / l_s[sub*64 + mt*16 + g + 8];
#pragma unroll
            for (int nt = 0; nt < 2; nt++){
                int col = (h0+sub)*HDIM + wid*16 + nt*8 + tg*2;
                int r0 = q0 + mt*16 + g;
                *(float2*)(y + (size_t)r0*DIM + col)     = make_float2(o[sub][mt][nt][0]*invA, o[sub][mt][nt][1]*invA);
                *(float2*)(y + (size_t)(r0+8)*DIM + col) = make_float2(o[sub][mt][nt][2]*invB, o[sub][mt][nt][3]*invB);
            }
        }
    }
}

// ---------------- launch ---------------------------------------------------
extern "C" void kernel_launch(void* const* d_in, const int* in_sizes, int n_in,
                              void* d_out, int out_size)
{
    const float* x  = (const float*)d_in[0];
    const float* fc = (const float*)d_in[1];
    const float* wq = (const float*)d_in[3];
    const float* wk = (const float*)d_in[4];
    const float* wv = (const float*)d_in[5];
    const float* wo = (const float*)d_in[6];
    float* out = (float*)d_out;

    void *pq, *pk, *pv, *py;
    void *pxh, *pxl, *pqh, *pql, *pkh, *pkl, *pvh, *pvl, *poh, *pol, *pyh, *pyl;
    void *pkh2, *pkl2, *pvh2, *pvl2;
    cudaGetSymbolAddress(&pq, g_q);
    cudaGetSymbolAddress(&pk, g_k);
    cudaGetSymbolAddress(&pv, g_v);
    cudaGetSymbolAddress(&py, g_y);
    cudaGetSymbolAddress(&pxh, g_xhi);  cudaGetSymbolAddress(&pxl, g_xlo);
    cudaGetSymbolAddress(&pqh, g_wqhi); cudaGetSymbolAddress(&pql, g_wqlo);
    cudaGetSymbolAddress(&pkh, g_wkhi); cudaGetSymbolAddress(&pkl, g_wklo);
    cudaGetSymbolAddress(&pvh, g_wvhi); cudaGetSymbolAddress(&pvl, g_wvlo);
    cudaGetSymbolAddress(&poh, g_wohi); cudaGetSymbolAddress(&pol, g_wolo);
    cudaGetSymbolAddress(&pyh, g_yhi);  cudaGetSymbolAddress(&pyl, g_ylo);
    cudaGetSymbolAddress(&pkh2, g_khi); cudaGetSymbolAddress(&pkl2, g_klo);
    cudaGetSymbolAddress(&pvh2, g_vhi); cudaGetSymbolAddress(&pvl2, g_vlo);

    float* dq = (float*)pq;  float* dk = (float*)pk;
    float* dv = (float*)pv;  float* dy = (float*)py;
    bf16* xhi = (bf16*)pxh; bf16* xlo = (bf16*)pxl;
    bf16* qhi = (bf16*)pqh; bf16* qlo = (bf16*)pql;
    bf16* khi = (bf16*)pkh; bf16* klo = (bf16*)pkl;
    bf16* vhi = (bf16*)pvh; bf16* vlo = (bf16*)pvl;
    bf16* ohi = (bf16*)poh; bf16* olo = (bf16*)pol;
    bf16* yhi = (bf16*)pyh; bf16* ylo = (bf16*)pyl;
    bf16* akh = (bf16*)pkh2; bf16* akl = (bf16*)pkl2;
    bf16* avh = (bf16*)pvh2; bf16* avl = (bf16*)pvl2;

    cudaFuncSetAttribute(gemm_bulk, cudaFuncAttributeMaxDynamicSharedMemorySize, PGSMEM);
    cudaFuncSetAttribute(attn_mma, cudaFuncAttributeMaxDynamicSharedMemorySize, ATTN_SMEM2);

    // pack inputs & weights into K-chunked swizzled hi/lo blocks
    {
        int n8;
        n8 = SEQLEN*DIM/8;  pack_split<<<(n8+255)/256, 256>>>(x,  xhi, xlo, 8, n8);
        n8 = DIM*DIM/8;     pack_split<<<(n8+255)/256, 256>>>(wq, qhi, qlo, 7, n8);
        n8 = KVDIM*DIM/8;   pack_split<<<(n8+255)/256, 256>>>(wk, khi, klo, 7, n8);
        n8 = KVDIM*DIM/8;   pack_split<<<(n8+255)/256, 256>>>(wv, vhi, vlo, 7, n8);
        n8 = DIM*DIM/8;     pack_split<<<(n8+255)/256, 256>>>(wo, ohi, olo, 7, n8);
    }

    // projections (bulk-fed HMMA, 256x128 tiles)
    gemm_bulk<<<dim3(DIM/128,   SEQLEN/256), 512, PGSMEM>>>(xhi, xlo, qhi, qlo, dq, DIM);
    gemm_bulk<<<dim3(KVDIM/128, SEQLEN/256), 512, PGSMEM>>>(xhi, xlo, khi, klo, dk, KVDIM);
    gemm_bulk<<<dim3(KVDIM/128, SEQLEN/256), 512, PGSMEM>>>(xhi, xlo, vhi, vlo, dv, KVDIM);

    // RoPE
    {
        int nq = SEQLEN * NHEADS * (HDIM/2);
        rope_kernel<<<(nq+255)/256, 256>>>(dq, fc, NHEADS);
        int nk = SEQLEN * NKV * (HDIM/2);
        rope_kernel<<<(nk+255)/256, 256>>>(dk, fc, NKV);
    }

    // split q/k/v for attention (row-major hi/lo; q reuses x buffers)
    {
        int n;
        n = SEQLEN*DIM;   split_kernel<<<(n+255)/256, 256>>>(dq, xhi, xlo, n);
        n = SEQLEN*KVDIM; split_kernel<<<(n+255)/256, 256>>>(dk, akh, akl, n);
        n = SEQLEN*KVDIM; split_kernel<<<(n+255)/256, 256>>>(dv, avh, avl, n);
    }

    // attention: 2 q-heads per CTA share KV
    attn_mma<<<dim3(SEQLEN/64, NHEADS/2), 256, ATTN_SMEM2>>>(xhi, xlo, akh, akl, avh, avl, dy);

    // output projection: pack y, then bulk GEMM
    {
        int n8 = SEQLEN*DIM/8;
        pack_split<<<(n8+255)/256, 256>>>(dy, yhi, ylo, 8, n8);
    }
    gemm_bulk<<<dim3(DIM/128, SEQLEN/256), 512, PGSMEM>>>(yhi, ylo, ohi, olo, out, DIM);
}

// round 15
// speedup vs baseline: 2.6910x; 1.0194x over previous
#include <cuda_runtime.h>
#include <cuda_bf16.h>
#include <math.h>
#include <stdint.h>

#define SEQLEN  2048
#define DIM     4096
#define NHEADS  32
#define NKV     8
#define HDIM    128
#define KVDIM   (NKV*HDIM)

typedef __nv_bfloat16 bf16;

extern __shared__ char dynsm[];

// ---------------- device scratch -------------------------------------------
__device__ __align__(256) float g_q[(size_t)SEQLEN*DIM];     // reused: q hi||lo bf16
__device__ __align__(256) float g_k[(size_t)SEQLEN*KVDIM];   // reused: k hi||lo bf16
__device__ __align__(256) float g_v[(size_t)SEQLEN*KVDIM];   // reused: v hi||lo bf16
__device__ __align__(256) bf16 g_xhi[(size_t)SEQLEN*DIM];    // packed x hi
__device__ __align__(256) bf16 g_xlo[(size_t)SEQLEN*DIM];
__device__ __align__(256) bf16 g_wqhi[(size_t)DIM*DIM];
__device__ __align__(256) bf16 g_wqlo[(size_t)DIM*DIM];
__device__ __align__(256) bf16 g_wkhi[(size_t)KVDIM*DIM];
__device__ __align__(256) bf16 g_wklo[(size_t)KVDIM*DIM];
__device__ __align__(256) bf16 g_wvhi[(size_t)KVDIM*DIM];
__device__ __align__(256) bf16 g_wvlo[(size_t)KVDIM*DIM];
__device__ __align__(256) bf16 g_wohi[(size_t)DIM*DIM];
__device__ __align__(256) bf16 g_wolo[(size_t)DIM*DIM];
__device__ __align__(256) bf16 g_yhi[(size_t)SEQLEN*DIM];    // packed y hi
__device__ __align__(256) bf16 g_ylo[(size_t)SEQLEN*DIM];

// ---------------- pack+split: fp32 [M,4096] -> K-chunked swizzled blocks ---
__global__ void pack_split(const float* __restrict__ in, bf16* __restrict__ hi,
                           bf16* __restrict__ lo, int blkshift, int total8){
    int t = blockIdx.x * blockDim.x + threadIdx.x;
    if (t >= total8) return;
    int j = t & 3;
    int c = (t >> 2) & 127;
    int r = t >> 9;
    const float4* src = (const float4*)(in + (size_t)r*4096 + c*32 + j*8);
    float4 f0 = src[0], f1 = src[1];
    float fv[8] = {f0.x, f0.y, f0.z, f0.w, f1.x, f1.y, f1.z, f1.w};
    union { bf16 b[8]; uint4 v; } H, L;
#pragma unroll
    for (int i2 = 0; i2 < 8; i2++){
        bf16 h = __float2bfloat16(fv[i2]);
        H.b[i2] = h;
        L.b[i2] = __float2bfloat16(fv[i2] - __bfloat162float(h));
    }
    int jp = j ^ ((r >> 1) & 3);
    int blkrows = 1 << blkshift;
    size_t off = (((size_t)(r >> blkshift) * 128 + c) << (blkshift + 5))
               + (size_t)(r & (blkrows - 1)) * 32 + jp * 8;
    *(uint4*)(hi + off) = H.v;
    *(uint4*)(lo + off) = L.v;
}

// ---------------- MMA / LDSM helpers ---------------------------------------
__device__ __forceinline__ void mma16816(float* d, const uint32_t* a, const uint32_t* b){
    asm volatile(
        "mma.sync.aligned.m16n8k16.row.col.f32.bf16.bf16.f32 "
        "{%0,%1,%2,%3}, {%4,%5,%6,%7}, {%8,%9}, {%0,%1,%2,%3};"
        : "+f"(d[0]), "+f"(d[1]), "+f"(d[2]), "+f"(d[3])
        : "r"(a[0]), "r"(a[1]), "r"(a[2]), "r"(a[3]), "r"(b[0]), "r"(b[1]));
}
__device__ __forceinline__ void ldsm4(uint32_t* r, uint32_t saddr){
    asm volatile("ldmatrix.sync.aligned.m8n8.x4.shared.b16 {%0,%1,%2,%3}, [%4];"
                 : "=r"(r[0]), "=r"(r[1]), "=r"(r[2]), "=r"(r[3]) : "r"(saddr));
}
__device__ __forceinline__ void cpa16(void* smem_dst, const void* gmem_src){
    asm volatile("cp.async.cg.shared.global [%0], [%1], 16;"
                 :: "r"((uint32_t)__cvta_generic_to_shared(smem_dst)), "l"(gmem_src));
}
__device__ __forceinline__ void cpbulk(uint32_t sdst, const void* gsrc, uint32_t bytes, uint32_t mbar){
    asm volatile("cp.async.bulk.shared::cta.global.mbarrier::complete_tx::bytes [%0], [%1], %2, [%3];"
                 :: "r"(sdst), "l"(gsrc), "r"(bytes), "r"(mbar) : "memory");
}
__device__ __forceinline__ void mbar_init(uint32_t a, uint32_t cnt){
    asm volatile("mbarrier.init.shared.b64 [%0], %1;" :: "r"(a), "r"(cnt) : "memory");
}
__device__ __forceinline__ void mbar_expect(uint32_t a, uint32_t bytes){
    asm volatile("mbarrier.arrive.expect_tx.shared.b64 _, [%0], %1;" :: "r"(a), "r"(bytes) : "memory");
}
__device__ __forceinline__ void mbar_wait(uint32_t a, uint32_t par){
    uint32_t done;
    asm volatile("{\n\t.reg .pred p;\n\t"
                 "mbarrier.try_wait.parity.acquire.cta.shared::cta.b64 p, [%1], %2;\n\t"
                 "selp.b32 %0,1,0,p;\n\t}"
                 : "=r"(done) : "r"(a), "r"(par) : "memory");
    if (!done){
        asm volatile("{\n\t.reg .pred P1;\n\t"
                     "W%=:\n\t"
                     "mbarrier.try_wait.parity.acquire.cta.shared::cta.b64 P1, [%0], %1, 0x989680;\n\t"
                     "@P1 bra.uni D%=;\n\t"
                     "bra.uni W%=;\n\t"
                     "D%=:\n\t}"
                     :: "r"(a), "r"(par) : "memory");
    }
}
__device__ __forceinline__ uint32_t packbf2(float a, float b){
    union { bf16 x[2]; uint32_t u; } t;
    t.x[0] = __float2bfloat16(a);
    t.x[1] = __float2bfloat16(b);
    return t.u;
}

// ---------------- bulk-fed GEMM with fused epilogues ------------------------
// MODE 0: fp32 C.  MODE 1: RoPE + hi/lo bf16 split (row-major).  MODE 2: split only.
#define PB_ASZ 16384u
#define PB_BSZ 8192u
#define PSTAGE 49152u
#define PNSTG  3
#define PGSMEM (PNSTG*PSTAGE + 64)

template<int MODE>
__global__ __launch_bounds__(512, 1) void gemm_bulk(
    const bf16* __restrict__ Aph, const bf16* __restrict__ Apl,
    const bf16* __restrict__ Bph, const bf16* __restrict__ Bpl,
    float* __restrict__ C, bf16* __restrict__ Chi, bf16* __restrict__ Clo,
    const float* __restrict__ fc, int N)
{
    const int tid  = threadIdx.x;
    const int wid  = tid >> 5;
    const int lane = tid & 31;
    const int g  = lane >> 2;
    const int tg = lane & 3;
    const int warpM = (wid >> 2) * 64;
    const int warpN = (wid & 3) * 32;
    const int by = blockIdx.y, bx = blockIdx.x;
    const int nck = 128;

    const uint32_t smbase = (uint32_t)__cvta_generic_to_shared(dynsm);
    const uint32_t mb = smbase + PNSTG*PSTAGE;

    if (tid == 0){
        for (int s = 0; s < PNSTG; s++) mbar_init(mb + 8*s, 1);
    }
    __syncthreads();

    auto issue = [&](int c){
        int st = c % PNSTG;
        uint32_t sb2 = smbase + st*PSTAGE;
        uint32_t bar = mb + 8*st;
        mbar_expect(bar, 49152u);
        cpbulk(sb2,          Aph + ((size_t)by*nck + c)*8192, PB_ASZ, bar);
        cpbulk(sb2 + 16384,  Apl + ((size_t)by*nck + c)*8192, PB_ASZ, bar);
        cpbulk(sb2 + 32768,  Bph + ((size_t)bx*nck + c)*4096, PB_BSZ, bar);
        cpbulk(sb2 + 40960,  Bpl + ((size_t)bx*nck + c)*4096, PB_BSZ, bar);
    };
    if (tid == 0){ issue(0); issue(1); issue(2); }

    float acc[4][4][4];
#pragma unroll
    for (int i = 0; i < 4; i++)
#pragma unroll
        for (int j = 0; j < 4; j++)
#pragma unroll
            for (int l = 0; l < 4; l++) acc[i][j][l] = 0.0f;

    const int la15 = lane & 15;
    uint32_t aoff[2], boff[2];
#pragma unroll
    for (int kc = 0; kc < 2; kc++){
        int jA = (kc*2 + (lane >> 4)) ^ ((la15 >> 1) & 3);
        aoff[kc] = (uint32_t)(la15*64 + jA*16);
        int rB = ((lane >> 4) << 3) + (lane & 7);
        int jB = (kc*2 + ((lane >> 3) & 1)) ^ (((lane & 7) >> 1) & 3);
        boff[kc] = (uint32_t)(rB*64 + jB*16);
    }

    for (int c = 0; c < nck; c++){
        int st = c % PNSTG;
        mbar_wait(mb + 8*st, (uint32_t)((c/PNSTG) & 1));

        uint32_t stb = smbase + st*PSTAGE;
        uint32_t Ah = stb + (uint32_t)(warpM*64);
        uint32_t Al = Ah + 16384;
        uint32_t Bh = stb + 32768 + (uint32_t)(warpN*64);
        uint32_t Bl = Bh + 8192;

#pragma unroll
        for (int kc = 0; kc < 2; kc++){
#pragma unroll
            for (int half = 0; half < 2; half++){
                uint32_t afh[2][4], afl[2][4];
                ldsm4(afh[0], Ah + (half*2+0)*1024 + aoff[kc]);
                ldsm4(afh[1], Ah + (half*2+1)*1024 + aoff[kc]);
                ldsm4(afl[0], Al + (half*2+0)*1024 + aoff[kc]);
                ldsm4(afl[1], Al + (half*2+1)*1024 + aoff[kc]);
#pragma unroll
                for (int bh2 = 0; bh2 < 2; bh2++){
                    uint32_t bfh[4], bfl[4];
                    ldsm4(bfh, Bh + bh2*1024 + boff[kc]);
                    ldsm4(bfl, Bl + bh2*1024 + boff[kc]);
#pragma unroll
                    for (int m2 = 0; m2 < 2; m2++){
                        int mt = half*2 + m2;
#pragma unroll
                        for (int np = 0; np < 2; np++){
                            int nt = bh2*2 + np;
                            mma16816(acc[mt][nt], afh[m2], &bfh[np*2]);
                            mma16816(acc[mt][nt], afh[m2], &bfl[np*2]);
                            mma16816(acc[mt][nt], afl[m2], &bfh[np*2]);
                        }
                    }
                }
            }
        }
        __syncthreads();
        if (tid == 0 && c + PNSTG < nck) issue(c + PNSTG);
    }

    const int row0 = by * 256, col0 = bx * 128;
#pragma unroll
    for (int mt = 0; mt < 4; mt++){
#pragma unroll
        for (int nt = 0; nt < 4; nt++){
            int r0 = row0 + warpM + mt*16 + g;
            int c0 = col0 + warpN + nt*8 + tg*2;
            if (MODE == 0){
                *(float2*)(C + (size_t)r0*N + c0)     = make_float2(acc[mt][nt][0], acc[mt][nt][1]);
                *(float2*)(C + (size_t)(r0+8)*N + c0) = make_float2(acc[mt][nt][2], acc[mt][nt][3]);
            } else {
#pragma unroll
                for (int rr = 0; rr < 2; rr++){
                    int r = r0 + rr*8;
                    float v0 = acc[mt][nt][rr*2+0];
                    float v1 = acc[mt][nt][rr*2+1];
                    if (MODE == 1){
                        float2 f = *(const float2*)(fc + (size_t)r*HDIM + (c0 & (HDIM-1)));
                        float re = v0*f.x - v1*f.y;
                        float im = v1*f.x + v0*f.y;
                        v0 = re; v1 = im;
                    }
                    bf16 h0 = __float2bfloat16(v0);
                    bf16 h1 = __float2bfloat16(v1);
                    union { bf16 x[2]; uint32_t u; } H, L;
                    H.x[0] = h0; H.x[1] = h1;
                    L.x[0] = __float2bfloat16(v0 - __bfloat162float(h0));
                    L.x[1] = __float2bfloat16(v1 - __bfloat162float(h1));
                    *(uint32_t*)(Chi + (size_t)r*N + c0) = H.u;
                    *(uint32_t*)(Clo + (size_t)r*N + c0) = L.u;
                }
            }
        }
    }
}

// ---------------- Flash attention: 2 q-heads per CTA share K/V --------------
// Epilogue writes y directly in packed hi/lo layout for the wo GEMM.
#define QKSTR 136
#define AQOF(sub) ((sub)*34816)
#define AKB   69632
#define AVB   139264
#define ASS   174080
#define SSTRF 73
#define APH   192768
#define APL   201984
#define PSTR  72
#define AM    211200
#define ALr   211712
#define AAr   212224
#define ATTN_SMEM2 212736

__global__ __launch_bounds__(256, 1) void attn_mma(
    const bf16* __restrict__ qh, const bf16* __restrict__ ql,
    const bf16* __restrict__ kh, const bf16* __restrict__ kl,
    const bf16* __restrict__ vh, const bf16* __restrict__ vl,
    bf16* __restrict__ yhi, bf16* __restrict__ ylo)
{
    char* sb = dynsm;
    float* m_s = (float*)(sb + AM);
    float* l_s = (float*)(sb + ALr);
    float* a_s = (float*)(sb + AAr);

    const int tid  = threadIdx.x;
    const int wid  = tid >> 5;
    const int lane = tid & 31;
    const int g  = lane >> 2;
    const int tg = lane & 3;
    const int qt = (gridDim.x - 1) - blockIdx.x;
    const int hy = blockIdx.y;
    const int hk = hy >> 1;
    const int h0 = hk*4 + (hy & 1)*2;
    const int q0 = qt * 64;
    const float scale = 0.08838834764831845f;

#pragma unroll
    for (int i = 0; i < 8; i++){
        int chunk = tid + i*256;
        int sub = chunk >> 10;
        int w = chunk & 1023;
        int r = w >> 4, c2 = w & 15;
        size_t go = (size_t)(q0 + r)*DIM + (h0 + sub)*HDIM + c2*8;
        cpa16(sb + AQOF(sub) + r*272 + c2*16, qh + go);
        cpa16(sb + AQOF(sub) + 17408 + r*272 + c2*16, ql + go);
    }
    auto load_k = [&](int st, int j0){
#pragma unroll
        for (int i = 0; i < 4; i++){
            int chunk = tid + i*256;
            int r = chunk >> 4, c2 = chunk & 15;
            size_t go = (size_t)(j0 + r)*KVDIM + hk*HDIM + c2*8;
            char* kb2 = sb + AKB + st*34816 + r*272 + c2*16;
            cpa16(kb2, kh + go);
            cpa16(kb2 + 17408, kl + go);
        }
    };
    auto load_v = [&](int j0){
#pragma unroll
        for (int i = 0; i < 4; i++){
            int chunk = tid + i*256;
            int r = chunk >> 4, c2 = chunk & 15;
            size_t go = (size_t)(j0 + r)*KVDIM + hk*HDIM + c2*8;
            char* vb2 = sb + AVB + r*272 + c2*16;
            cpa16(vb2, vh + go);
            cpa16(vb2 + 17408, vl + go);
        }
    };
    load_k(0, 0);
    asm volatile("cp.async.commit_group;" ::: "memory");

    if (tid < 128){ m_s[tid] = -INFINITY; l_s[tid] = 0.0f; }

    float o[2][4][2][4];
#pragma unroll
    for (int s2 = 0; s2 < 2; s2++)
#pragma unroll
        for (int mt = 0; mt < 4; mt++)
#pragma unroll
            for (int nt = 0; nt < 2; nt++)
#pragma unroll
                for (int l = 0; l < 4; l++) o[s2][mt][nt][l] = 0.0f;

    const int ntile = qt + 1;
    for (int jt = 0; jt < ntile; jt++){
        const int st = jt & 1;
        const int j0 = jt * 64;
        asm volatile("cp.async.wait_group 0;" ::: "memory");
        __syncthreads();
        load_v(j0);
        asm volatile("cp.async.commit_group;" ::: "memory");
        if (jt + 1 < ntile) load_k(st ^ 1, (jt+1)*64);
        asm volatile("cp.async.commit_group;" ::: "memory");

        char* Khs = sb + AKB + st*34816;
        char* Kls = Khs + 17408;

        for (int sub = 0; sub < 2; sub++){
            const char* Qhs = sb + AQOF(sub);
            const char* Qls = Qhs + 17408;

            float sacc[4][4];
#pragma unroll
            for (int mt = 0; mt < 4; mt++)
#pragma unroll
                for (int l = 0; l < 4; l++) sacc[mt][l] = 0.0f;

#pragma unroll
            for (int ks = 0; ks < 8; ks++){
                int colb = ks*16 + tg*2;
                uint32_t bh[2], bl[2];
                {
                    int r = wid*8 + g;
                    bh[0] = *(const uint32_t*)(Khs + r*272 + colb*2);
                    bh[1] = *(const uint32_t*)(Khs + r*272 + (colb+8)*2);
                    bl[0] = *(const uint32_t*)(Kls + r*272 + colb*2);
                    bl[1] = *(const uint32_t*)(Kls + r*272 + (colb+8)*2);
                }
#pragma unroll
                for (int mt = 0; mt < 4; mt++){
                    int r = mt*16 + g;
                    uint32_t ah[4], al[4];
                    ah[0] = *(const uint32_t*)(Qhs + r*272 + colb*2);
                    ah[1] = *(const uint32_t*)(Qhs + (r+8)*272 + colb*2);
                    ah[2] = *(const uint32_t*)(Qhs + r*272 + (colb+8)*2);
                    ah[3] = *(const uint32_t*)(Qhs + (r+8)*272 + (colb+8)*2);
                    al[0] = *(const uint32_t*)(Qls + r*272 + colb*2);
                    al[1] = *(const uint32_t*)(Qls + (r+8)*272 + colb*2);
                    al[2] = *(const uint32_t*)(Qls + r*272 + (colb+8)*2);
                    al[3] = *(const uint32_t*)(Qls + (r+8)*272 + (colb+8)*2);
                    mma16816(sacc[mt], ah, bh);
                    mma16816(sacc[mt], ah, bl);
                    mma16816(sacc[mt], al, bh);
                }
            }
            {
                float* Ss = (float*)(sb + ASS);
                int c0 = wid*8 + tg*2;
#pragma unroll
                for (int mt = 0; mt < 4; mt++){
                    int r0 = mt*16 + g, r1 = r0 + 8;
                    float s00 = sacc[mt][0]*scale, s01 = sacc[mt][1]*scale;
                    float s10 = sacc[mt][2]*scale, s11 = sacc[mt][3]*scale;
                    if (j0 + c0     > q0 + r0) s00 = -1e9f;
                    if (j0 + c0 + 1 > q0 + r0) s01 = -1e9f;
                    if (j0 + c0     > q0 + r1) s10 = -1e9f;
                    if (j0 + c0 + 1 > q0 + r1) s11 = -1e9f;
                    Ss[r0*SSTRF + c0] = s00; Ss[r0*SSTRF + c0+1] = s01;
                    Ss[r1*SSTRF + c0] = s10; Ss[r1*SSTRF + c0+1] = s11;
                }
            }
            __syncthreads();

            {
                float* Ss = (float*)(sb + ASS);
                bf16* Ph = (bf16*)(sb + APH);
                bf16* Pl = (bf16*)(sb + APL);
                int row = tid >> 2, part = tid & 3;
                float* srow = Ss + row*SSTRF + part*16;
                float tmax = -INFINITY;
#pragma unroll
                for (int c = 0; c < 16; c++) tmax = fmaxf(tmax, srow[c]);
                tmax = fmaxf(tmax, __shfl_xor_sync(0xffffffffu, tmax, 1));
                tmax = fmaxf(tmax, __shfl_xor_sync(0xffffffffu, tmax, 2));
                int mrow = sub*64 + row;
                float mold = m_s[mrow];
                float mnew = fmaxf(mold, tmax);
                float alpha = (mold == -INFINITY) ? 0.0f : __expf(mold - mnew);
                float sum = 0.0f;
                bf16* phrow = Ph + row*PSTR + part*16;
                bf16* plrow = Pl + row*PSTR + part*16;
#pragma unroll
                for (int c = 0; c < 16; c++){
                    float p = __expf(srow[c] - mnew);
                    sum += p;
                    bf16 ph = __float2bfloat16(p);
                    phrow[c] = ph;
                    plrow[c] = __float2bfloat16(p - __bfloat162float(ph));
                }
                sum += __shfl_xor_sync(0xffffffffu, sum, 1);
                sum += __shfl_xor_sync(0xffffffffu, sum, 2);
                if (part == 0){
                    l_s[mrow] = l_s[mrow]*alpha + sum;
                    m_s[mrow] = mnew;
                    a_s[mrow] = alpha;
                }
            }
            if (sub == 0){
                asm volatile("cp.async.wait_group 1;" ::: "memory");
            }
            __syncthreads();

#pragma unroll
            for (int mt = 0; mt < 4; mt++){
                float alA = a_s[sub*64 + mt*16 + g];
                float alB = a_s[sub*64 + mt*16 + g + 8];
#pragma unroll
                for (int nt = 0; nt < 2; nt++){
                    o[sub][mt][nt][0] *= alA; o[sub][mt][nt][1] *= alA;
                    o[sub][mt][nt][2] *= alB; o[sub][mt][nt][3] *= alB;
                }
            }
            {
                bf16* Ph = (bf16*)(sb + APH);
                bf16* Pl = (bf16*)(sb + APL);
                const uint16_t* Vhs = (const uint16_t*)(sb + AVB);
                const uint16_t* Vls = (const uint16_t*)(sb + AVB + 17408);
#pragma unroll
                for (int ksv = 0; ksv < 4; ksv++){
                    int colb = ksv*16 + tg*2;
                    uint32_t aph[4][4], apl[4][4];
#pragma unroll
                    for (int mt = 0; mt < 4; mt++){
                        int r = mt*16 + g;
                        aph[mt][0] = *(const uint32_t*)(Ph + r*PSTR + colb);
                        aph[mt][1] = *(const uint32_t*)(Ph + (r+8)*PSTR + colb);
                        aph[mt][2] = *(const uint32_t*)(Ph + r*PSTR + colb + 8);
                        aph[mt][3] = *(const uint32_t*)(Ph + (r+8)*PSTR + colb + 8);
                        apl[mt][0] = *(const uint32_t*)(Pl + r*PSTR + colb);
                        apl[mt][1] = *(const uint32_t*)(Pl + (r+8)*PSTR + colb);
                        apl[mt][2] = *(const uint32_t*)(Pl + r*PSTR + colb + 8);
                        apl[mt][3] = *(const uint32_t*)(Pl + (r+8)*PSTR + colb + 8);
                    }
#pragma unroll
                    for (int nt = 0; nt < 2; nt++){
                        int n = wid*16 + nt*8 + g;
                        int k0 = ksv*16 + tg*2;
                        uint32_t bvh[2], bvl[2];
                        bvh[0] = (uint32_t)Vhs[k0*QKSTR + n]     | ((uint32_t)Vhs[(k0+1)*QKSTR + n] << 16);
                        bvh[1] = (uint32_t)Vhs[(k0+8)*QKSTR + n] | ((uint32_t)Vhs[(k0+9)*QKSTR + n] << 16);
                        bvl[0] = (uint32_t)Vls[k0*QKSTR + n]     | ((uint32_t)Vls[(k0+1)*QKSTR + n] << 16);
                        bvl[1] = (uint32_t)Vls[(k0+8)*QKSTR + n] | ((uint32_t)Vls[(k0+9)*QKSTR + n] << 16);
#pragma unroll
                        for (int mt = 0; mt < 4; mt++){
                            mma16816(o[sub][mt][nt], aph[mt], bvh);
                            mma16816(o[sub][mt][nt], aph[mt], bvl);
                            mma16816(o[sub][mt][nt], apl[mt], bvh);
                        }
                    }
                }
            }
            __syncthreads();
        }
    }

    // epilogue: write y directly in the packed swizzled hi/lo layout
#pragma unroll
    for (int sub = 0; sub < 2; sub++){
#pragma unroll
        for (int mt = 0; mt < 4; mt++){
            float invA = 1.0f / l_s[sub*64 + mt*16 + g];
            float invB = 1.0f / l_s[sub*64 + mt*16 + g + 8];
#pragma unroll
            for (int nt = 0; nt < 2; nt++){
                int col = (h0+sub)*HDIM + wid*16 + nt*8 + tg*2;
                int cchunk = col >> 5;
                int j = (col & 31) >> 3;
#pragma unroll
                for (int rr = 0; rr < 2; rr++){
                    int r = q0 + mt*16 + g + rr*8;
                    float inv = rr ? invB : invA;
                    float v0 = o[sub][mt][nt][rr*2+0] * inv;
                    float v1 = o[sub][mt][nt][rr*2+1] * inv;
                    bf16 h0b = __float2bfloat16(v0);
                    bf16 h1b = __float2bfloat16(v1);
                    union { bf16 x[2]; uint32_t u; } H, L;
                    H.x[0] = h0b; H.x[1] = h1b;
                    L.x[0] = __float2bfloat16(v0 - __bfloat162float(h0b));
                    L.x[1] = __float2bfloat16(v1 - __bfloat162float(h1b));
                    int jp = j ^ ((r >> 1) & 3);
                    size_t off = (((size_t)(r >> 8) * 128 + cchunk) << 13)
                               + (size_t)(r & 255) * 32 + jp*8 + (col & 7);
                    *(uint32_t*)(yhi + off) = H.u;
                    *(uint32_t*)(ylo + off) = L.u;
                }
            }
        }
    }
}

// ---------------- launch ---------------------------------------------------
extern "C" void kernel_launch(void* const* d_in, const int* in_sizes, int n_in,
                              void* d_out, int out_size)
{
    const float* x  = (const float*)d_in[0];
    const float* fc = (const float*)d_in[1];
    const float* wq = (const float*)d_in[3];
    const float* wk = (const float*)d_in[4];
    const float* wv = (const float*)d_in[5];
    const float* wo = (const float*)d_in[6];
    float* out = (float*)d_out;

    void *pq, *pk, *pv;
    void *pxh, *pxl, *pqh, *pql, *pkh, *pkl, *pvh, *pvl, *poh, *pol, *pyh, *pyl;
    cudaGetSymbolAddress(&pq, g_q);
    cudaGetSymbolAddress(&pk, g_k);
    cudaGetSymbolAddress(&pv, g_v);
    cudaGetSymbolAddress(&pxh, g_xhi);  cudaGetSymbolAddress(&pxl, g_xlo);
    cudaGetSymbolAddress(&pqh, g_wqhi); cudaGetSymbolAddress(&pql, g_wqlo);
    cudaGetSymbolAddress(&pkh, g_wkhi); cudaGetSymbolAddress(&pkl, g_wklo);
    cudaGetSymbolAddress(&pvh, g_wvhi); cudaGetSymbolAddress(&pvl, g_wvlo);
    cudaGetSymbolAddress(&poh, g_wohi); cudaGetSymbolAddress(&pol, g_wolo);
    cudaGetSymbolAddress(&pyh, g_yhi);  cudaGetSymbolAddress(&pyl, g_ylo);

    bf16* xhi = (bf16*)pxh; bf16* xlo = (bf16*)pxl;
    bf16* qhi = (bf16*)pqh; bf16* qlo = (bf16*)pql;
    bf16* khi = (bf16*)pkh; bf16* klo = (bf16*)pkl;
    bf16* vhi = (bf16*)pvh; bf16* vlo = (bf16*)pvl;
    bf16* ohi = (bf16*)poh; bf16* olo = (bf16*)pol;
    bf16* yhi = (bf16*)pyh; bf16* ylo = (bf16*)pyl;
    // q/k/v hi||lo splits live in the old fp32 scratch buffers
    bf16* aqh = (bf16*)pq;  bf16* aql = aqh + (size_t)SEQLEN*DIM;
    bf16* akh = (bf16*)pk;  bf16* akl = akh + (size_t)SEQLEN*KVDIM;
    bf16* avh = (bf16*)pv;  bf16* avl = avh + (size_t)SEQLEN*KVDIM;

    cudaFuncSetAttribute(gemm_bulk<0>, cudaFuncAttributeMaxDynamicSharedMemorySize, PGSMEM);
    cudaFuncSetAttribute(gemm_bulk<1>, cudaFuncAttributeMaxDynamicSharedMemorySize, PGSMEM);
    cudaFuncSetAttribute(gemm_bulk<2>, cudaFuncAttributeMaxDynamicSharedMemorySize, PGSMEM);
    cudaFuncSetAttribute(attn_mma, cudaFuncAttributeMaxDynamicSharedMemorySize, ATTN_SMEM2);

    // pack inputs & weights into K-chunked swizzled hi/lo blocks
    {
        int n8;
        n8 = SEQLEN*DIM/8;  pack_split<<<(n8+255)/256, 256>>>(x,  xhi, xlo, 8, n8);
        n8 = DIM*DIM/8;     pack_split<<<(n8+255)/256, 256>>>(wq, qhi, qlo, 7, n8);
        n8 = KVDIM*DIM/8;   pack_split<<<(n8+255)/256, 256>>>(wk, khi, klo, 7, n8);
        n8 = KVDIM*DIM/8;   pack_split<<<(n8+255)/256, 256>>>(wv, vhi, vlo, 7, n8);
        n8 = DIM*DIM/8;     pack_split<<<(n8+255)/256, 256>>>(wo, ohi, olo, 7, n8);
    }

    // projections with fused RoPE+split (q,k) / split (v) epilogues
    gemm_bulk<1><<<dim3(DIM/128,   SEQLEN/256), 512, PGSMEM>>>(xhi, xlo, qhi, qlo, nullptr, aqh, aql, fc, DIM);
    gemm_bulk<1><<<dim3(KVDIM/128, SEQLEN/256), 512, PGSMEM>>>(xhi, xlo, khi, klo, nullptr, akh, akl, fc, KVDIM);
    gemm_bulk<2><<<dim3(KVDIM/128, SEQLEN/256), 512, PGSMEM>>>(xhi, xlo, vhi, vlo, nullptr, avh, avl, nullptr, KVDIM);

    // attention: 2 q-heads per CTA share KV; writes packed y hi/lo
    attn_mma<<<dim3(SEQLEN/64, NHEADS/2), 256, ATTN_SMEM2>>>(aqh, aql, akh, akl, avh, avl, yhi, ylo);

    // output projection (packed y already in wo-GEMM layout)
    gemm_bulk<0><<<dim3(DIM/128, SEQLEN/256), 512, PGSMEM>>>(yhi, ylo, ohi, olo, out, nullptr, nullptr, nullptr, DIM);
}

// round 16
// speedup vs baseline: 3.1168x; 1.1582x over previous
#include <cuda_runtime.h>
#include <cuda_bf16.h>
#include <math.h>
#include <stdint.h>

#define SEQLEN  2048
#define DIM     4096
#define NHEADS  32
#define NKV     8
#define HDIM    128
#define KVDIM   (NKV*HDIM)

typedef __nv_bfloat16 bf16;

extern __shared__ char dynsm[];

// ---------------- device scratch -------------------------------------------
__device__ __align__(256) float g_q[(size_t)SEQLEN*DIM];     // reused: q hi||lo bf16
__device__ __align__(256) float g_k[(size_t)SEQLEN*KVDIM];   // reused: k hi||lo bf16
__device__ __align__(256) float g_v[(size_t)SEQLEN*KVDIM];   // reused: v hi||lo bf16
__device__ __align__(256) bf16 g_xhi[(size_t)SEQLEN*DIM];
__device__ __align__(256) bf16 g_xlo[(size_t)SEQLEN*DIM];
__device__ __align__(256) bf16 g_wqhi[(size_t)DIM*DIM];
__device__ __align__(256) bf16 g_wqlo[(size_t)DIM*DIM];
__device__ __align__(256) bf16 g_wkvhi[(size_t)2*KVDIM*DIM]; // fused wk||wv packed
__device__ __align__(256) bf16 g_wkvlo[(size_t)2*KVDIM*DIM];
__device__ __align__(256) bf16 g_wohi[(size_t)DIM*DIM];
__device__ __align__(256) bf16 g_wolo[(size_t)DIM*DIM];
__device__ __align__(256) bf16 g_yhi[(size_t)SEQLEN*DIM];
__device__ __align__(256) bf16 g_ylo[(size_t)SEQLEN*DIM];

// ---------------- pack+split: fp32 [M,4096] -> K-chunked swizzled blocks ---
__global__ void pack_split(const float* __restrict__ in, bf16* __restrict__ hi,
                           bf16* __restrict__ lo, int blkshift, int total8){
    int t = blockIdx.x * blockDim.x + threadIdx.x;
    if (t >= total8) return;
    int j = t & 3;
    int c = (t >> 2) & 127;
    int r = t >> 9;
    const float4* src = (const float4*)(in + (size_t)r*4096 + c*32 + j*8);
    float4 f0 = src[0], f1 = src[1];
    float fv[8] = {f0.x, f0.y, f0.z, f0.w, f1.x, f1.y, f1.z, f1.w};
    union { bf16 b[8]; uint4 v; } H, L;
#pragma unroll
    for (int i2 = 0; i2 < 8; i2++){
        bf16 h = __float2bfloat16(fv[i2]);
        H.b[i2] = h;
        L.b[i2] = __float2bfloat16(fv[i2] - __bfloat162float(h));
    }
    int jp = j ^ ((r >> 1) & 3);
    int blkrows = 1 << blkshift;
    size_t off = (((size_t)(r >> blkshift) * 128 + c) << (blkshift + 5))
               + (size_t)(r & (blkrows - 1)) * 32 + jp * 8;
    *(uint4*)(hi + off) = H.v;
    *(uint4*)(lo + off) = L.v;
}

// ---------------- MMA / LDSM helpers ---------------------------------------
__device__ __forceinline__ void mma16816(float* d, const uint32_t* a, const uint32_t* b){
    asm volatile(
        "mma.sync.aligned.m16n8k16.row.col.f32.bf16.bf16.f32 "
        "{%0,%1,%2,%3}, {%4,%5,%6,%7}, {%8,%9}, {%0,%1,%2,%3};"
        : "+f"(d[0]), "+f"(d[1]), "+f"(d[2]), "+f"(d[3])
        : "r"(a[0]), "r"(a[1]), "r"(a[2]), "r"(a[3]), "r"(b[0]), "r"(b[1]));
}
__device__ __forceinline__ void ldsm4(uint32_t* r, uint32_t saddr){
    asm volatile("ldmatrix.sync.aligned.m8n8.x4.shared.b16 {%0,%1,%2,%3}, [%4];"
                 : "=r"(r[0]), "=r"(r[1]), "=r"(r[2]), "=r"(r[3]) : "r"(saddr));
}
__device__ __forceinline__ void cpa16(void* smem_dst, const void* gmem_src){
    asm volatile("cp.async.cg.shared.global [%0], [%1], 16;"
                 :: "r"((uint32_t)__cvta_generic_to_shared(smem_dst)), "l"(gmem_src));
}
__device__ __forceinline__ void cpbulk(uint32_t sdst, const void* gsrc, uint32_t bytes, uint32_t mbar){
    asm volatile("cp.async.bulk.shared::cta.global.mbarrier::complete_tx::bytes [%0], [%1], %2, [%3];"
                 :: "r"(sdst), "l"(gsrc), "r"(bytes), "r"(mbar) : "memory");
}
__device__ __forceinline__ void mbar_init(uint32_t a, uint32_t cnt){
    asm volatile("mbarrier.init.shared.b64 [%0], %1;" :: "r"(a), "r"(cnt) : "memory");
}
__device__ __forceinline__ void mbar_expect(uint32_t a, uint32_t bytes){
    asm volatile("mbarrier.arrive.expect_tx.shared.b64 _, [%0], %1;" :: "r"(a), "r"(bytes) : "memory");
}
__device__ __forceinline__ void mbar_wait(uint32_t a, uint32_t par){
    uint32_t done;
    asm volatile("{\n\t.reg .pred p;\n\t"
                 "mbarrier.try_wait.parity.acquire.cta.shared::cta.b64 p, [%1], %2;\n\t"
                 "selp.b32 %0,1,0,p;\n\t}"
                 : "=r"(done) : "r"(a), "r"(par) : "memory");
    if (!done){
        asm volatile("{\n\t.reg .pred P1;\n\t"
                     "W%=:\n\t"
                     "mbarrier.try_wait.parity.acquire.cta.shared::cta.b64 P1, [%0], %1, 0x989680;\n\t"
                     "@P1 bra.uni D%=;\n\t"
                     "bra.uni W%=;\n\t"
                     "D%=:\n\t}"
                     :: "r"(a), "r"(par) : "memory");
    }
}

// ---------------- bulk-fed GEMM, 128x128 tile, 2 CTAs/SM --------------------
// MODE 0: fp32 C. MODE 1: RoPE + split (row-major). MODE 3: fused k|v epilogue.
#define P2STAGE 32768u
#define P2NSTG  3
#define P2GSMEM (P2NSTG*P2STAGE + 64)

template<int MODE>
__global__ __launch_bounds__(256, 2) void gemm_bulk2(
    const bf16* __restrict__ Aph, const bf16* __restrict__ Apl,
    const bf16* __restrict__ Bph, const bf16* __restrict__ Bpl,
    float* __restrict__ C, bf16* __restrict__ Chi, bf16* __restrict__ Clo,
    bf16* __restrict__ Vhi, bf16* __restrict__ Vlo,
    const float* __restrict__ fc, int N)
{
    const int tid  = threadIdx.x;
    const int wid  = tid >> 5;
    const int lane = tid & 31;
    const int g  = lane >> 2;
    const int tg = lane & 3;
    const int warpM = (wid >> 2) * 64;   // 0,64
    const int warpN = (wid & 3) * 32;    // 0,32,64,96
    const int by = blockIdx.y, bx = blockIdx.x;
    const int nck = 128;

    const uint32_t smbase = (uint32_t)__cvta_generic_to_shared(dynsm);
    const uint32_t mb = smbase + P2NSTG*P2STAGE;

    if (tid == 0){
        for (int s = 0; s < P2NSTG; s++) mbar_init(mb + 8*s, 1);
    }
    __syncthreads();

    // A packed with blkshift 8 (256-row blocks): our 128-row tile is a
    // contiguous half of the (block, chunk) slab.
    const size_t abase = ((size_t)(by >> 1) * 128) * 8192 + (size_t)(by & 1) * 4096;
    const size_t bbase = (size_t)bx * 128 * 4096;

    auto issue = [&](int c){
        int st = c % P2NSTG;
        uint32_t sb2 = smbase + st*P2STAGE;
        uint32_t bar = mb + 8*st;
        mbar_expect(bar, 32768u);
        cpbulk(sb2,          Aph + abase + (size_t)c*8192, 8192u, bar);
        cpbulk(sb2 + 8192,   Apl + abase + (size_t)c*8192, 8192u, bar);
        cpbulk(sb2 + 16384,  Bph + bbase + (size_t)c*4096, 8192u, bar);
        cpbulk(sb2 + 24576,  Bpl + bbase + (size_t)c*4096, 8192u, bar);
    };
    if (tid == 0){ issue(0); issue(1); issue(2); }

    float acc[4][4][4];
#pragma unroll
    for (int i = 0; i < 4; i++)
#pragma unroll
        for (int j = 0; j < 4; j++)
#pragma unroll
            for (int l = 0; l < 4; l++) acc[i][j][l] = 0.0f;

    const int la15 = lane & 15;
    uint32_t aoff[2], boff[2];
#pragma unroll
    for (int kc = 0; kc < 2; kc++){
        int jA = (kc*2 + (lane >> 4)) ^ ((la15 >> 1) & 3);
        aoff[kc] = (uint32_t)(la15*64 + jA*16);
        int rB = ((lane >> 4) << 3) + (lane & 7);
        int jB = (kc*2 + ((lane >> 3) & 1)) ^ (((lane & 7) >> 1) & 3);
        boff[kc] = (uint32_t)(rB*64 + jB*16);
    }

    for (int c = 0; c < nck; c++){
        int st = c % P2NSTG;
        mbar_wait(mb + 8*st, (uint32_t)((c/P2NSTG) & 1));

        uint32_t stb = smbase + st*P2STAGE;
        uint32_t Ah = stb + (uint32_t)(warpM*64);
        uint32_t Al = Ah + 8192;
        uint32_t Bh = stb + 16384 + (uint32_t)(warpN*64);
        uint32_t Bl = Bh + 8192;

#pragma unroll
        for (int kc = 0; kc < 2; kc++){
#pragma unroll
            for (int half = 0; half < 2; half++){
                uint32_t afh[2][4], afl[2][4];
                ldsm4(afh[0], Ah + (half*2+0)*1024 + aoff[kc]);
                ldsm4(afh[1], Ah + (half*2+1)*1024 + aoff[kc]);
                ldsm4(afl[0], Al + (half*2+0)*1024 + aoff[kc]);
                ldsm4(afl[1], Al + (half*2+1)*1024 + aoff[kc]);
#pragma unroll
                for (int bh2 = 0; bh2 < 2; bh2++){
                    uint32_t bfh[4], bfl[4];
                    ldsm4(bfh, Bh + bh2*1024 + boff[kc]);
                    ldsm4(bfl, Bl + bh2*1024 + boff[kc]);
#pragma unroll
                    for (int m2 = 0; m2 < 2; m2++){
                        int mt = half*2 + m2;
#pragma unroll
                        for (int np = 0; np < 2; np++){
                            int nt = bh2*2 + np;
                            mma16816(acc[mt][nt], afh[m2], &bfh[np*2]);
                            mma16816(acc[mt][nt], afh[m2], &bfl[np*2]);
                            mma16816(acc[mt][nt], afl[m2], &bfh[np*2]);
                        }
                    }
                }
            }
        }
        __syncthreads();
        if (tid == 0 && c + P2NSTG < nck) issue(c + P2NSTG);
    }

    const int row0 = by * 128, col0 = bx * 128;
#pragma unroll
    for (int mt = 0; mt < 4; mt++){
#pragma unroll
        for (int nt = 0; nt < 4; nt++){
            int r0 = row0 + warpM + mt*16 + g;
            int c0 = col0 + warpN + nt*8 + tg*2;
            if (MODE == 0){
                *(float2*)(C + (size_t)r0*N + c0)     = make_float2(acc[mt][nt][0], acc[mt][nt][1]);
                *(float2*)(C + (size_t)(r0+8)*N + c0) = make_float2(acc[mt][nt][2], acc[mt][nt][3]);
            } else {
                bf16* dh; bf16* dl; int cc = c0; bool dorope; int dn;
                if (MODE == 1){ dh = Chi; dl = Clo; dorope = true; dn = N; }
                else {
                    if (c0 < KVDIM){ dh = Chi; dl = Clo; dorope = true; }
                    else           { dh = Vhi; dl = Vlo; cc = c0 - KVDIM; dorope = false; }
                    dn = KVDIM;
                }
#pragma unroll
                for (int rr = 0; rr < 2; rr++){
                    int r = r0 + rr*8;
                    float v0 = acc[mt][nt][rr*2+0];
                    float v1 = acc[mt][nt][rr*2+1];
                    if (dorope){
                        float2 f = *(const float2*)(fc + (size_t)r*HDIM + (cc & (HDIM-1)));
                        float re = v0*f.x - v1*f.y;
                        float im = v1*f.x + v0*f.y;
                        v0 = re; v1 = im;
                    }
                    bf16 h0 = __float2bfloat16(v0);
                    bf16 h1 = __float2bfloat16(v1);
                    union { bf16 x[2]; uint32_t u; } H, L;
                    H.x[0] = h0; H.x[1] = h1;
                    L.x[0] = __float2bfloat16(v0 - __bfloat162float(h0));
                    L.x[1] = __float2bfloat16(v1 - __bfloat162float(h1));
                    *(uint32_t*)(dh + (size_t)r*dn + cc) = H.u;
                    *(uint32_t*)(dl + (size_t)r*dn + cc) = L.u;
                }
            }
        }
    }
}

// ---------------- Flash attention: 2 q-heads per CTA share K/V --------------
#define QKSTR 136
#define AQOF(sub) ((sub)*34816)
#define AKB   69632
#define AVB   139264
#define ASS   174080
#define SSTRF 73
#define APH   192768
#define APL   201984
#define PSTR  72
#define AM    211200
#define ALr   211712
#define AAr   212224
#define ATTN_SMEM2 212736

__global__ __launch_bounds__(256, 1) void attn_mma(
    const bf16* __restrict__ qh, const bf16* __restrict__ ql,
    const bf16* __restrict__ kh, const bf16* __restrict__ kl,
    const bf16* __restrict__ vh, const bf16* __restrict__ vl,
    bf16* __restrict__ yhi, bf16* __restrict__ ylo)
{
    char* sb = dynsm;
    float* m_s = (float*)(sb + AM);
    float* l_s = (float*)(sb + ALr);
    float* a_s = (float*)(sb + AAr);

    const int tid  = threadIdx.x;
    const int wid  = tid >> 5;
    const int lane = tid & 31;
    const int g  = lane >> 2;
    const int tg = lane & 3;
    const int qt = (gridDim.x - 1) - blockIdx.x;
    const int hy = blockIdx.y;
    const int hk = hy >> 1;
    const int h0 = hk*4 + (hy & 1)*2;
    const int q0 = qt * 64;
    const float scale = 0.08838834764831845f;

#pragma unroll
    for (int i = 0; i < 8; i++){
        int chunk = tid + i*256;
        int sub = chunk >> 10;
        int w = chunk & 1023;
        int r = w >> 4, c2 = w & 15;
        size_t go = (size_t)(q0 + r)*DIM + (h0 + sub)*HDIM + c2*8;
        cpa16(sb + AQOF(sub) + r*272 + c2*16, qh + go);
        cpa16(sb + AQOF(sub) + 17408 + r*272 + c2*16, ql + go);
    }
    auto load_k = [&](int st, int j0){
#pragma unroll
        for (int i = 0; i < 4; i++){
            int chunk = tid + i*256;
            int r = chunk >> 4, c2 = chunk & 15;
            size_t go = (size_t)(j0 + r)*KVDIM + hk*HDIM + c2*8;
            char* kb2 = sb + AKB + st*34816 + r*272 + c2*16;
            cpa16(kb2, kh + go);
            cpa16(kb2 + 17408, kl + go);
        }
    };
    auto load_v = [&](int j0){
#pragma unroll
        for (int i = 0; i < 4; i++){
            int chunk = tid + i*256;
            int r = chunk >> 4, c2 = chunk & 15;
            size_t go = (size_t)(j0 + r)*KVDIM + hk*HDIM + c2*8;
            char* vb2 = sb + AVB + r*272 + c2*16;
            cpa16(vb2, vh + go);
            cpa16(vb2 + 17408, vl + go);
        }
    };
    load_k(0, 0);
    asm volatile("cp.async.commit_group;" ::: "memory");

    if (tid < 128){ m_s[tid] = -INFINITY; l_s[tid] = 0.0f; }

    float o[2][4][2][4];
#pragma unroll
    for (int s2 = 0; s2 < 2; s2++)
#pragma unroll
        for (int mt = 0; mt < 4; mt++)
#pragma unroll
            for (int nt = 0; nt < 2; nt++)
#pragma unroll
                for (int l = 0; l < 4; l++) o[s2][mt][nt][l] = 0.0f;

    const int ntile = qt + 1;
    for (int jt = 0; jt < ntile; jt++){
        const int st = jt & 1;
        const int j0 = jt * 64;
        asm volatile("cp.async.wait_group 0;" ::: "memory");
        __syncthreads();
        load_v(j0);
        asm volatile("cp.async.commit_group;" ::: "memory");
        if (jt + 1 < ntile) load_k(st ^ 1, (jt+1)*64);
        asm volatile("cp.async.commit_group;" ::: "memory");

        char* Khs = sb + AKB + st*34816;
        char* Kls = Khs + 17408;

        for (int sub = 0; sub < 2; sub++){
            const char* Qhs = sb + AQOF(sub);
            const char* Qls = Qhs + 17408;

            float sacc[4][4];
#pragma unroll
            for (int mt = 0; mt < 4; mt++)
#pragma unroll
                for (int l = 0; l < 4; l++) sacc[mt][l] = 0.0f;

#pragma unroll
            for (int ks = 0; ks < 8; ks++){
                int colb = ks*16 + tg*2;
                uint32_t bh[2], bl[2];
                {
                    int r = wid*8 + g;
                    bh[0] = *(const uint32_t*)(Khs + r*272 + colb*2);
                    bh[1] = *(const uint32_t*)(Khs + r*272 + (colb+8)*2);
                    bl[0] = *(const uint32_t*)(Kls + r*272 + colb*2);
                    bl[1] = *(const uint32_t*)(Kls + r*272 + (colb+8)*2);
                }
#pragma unroll
                for (int mt = 0; mt < 4; mt++){
                    int r = mt*16 + g;
                    uint32_t ah[4], al[4];
                    ah[0] = *(const uint32_t*)(Qhs + r*272 + colb*2);
                    ah[1] = *(const uint32_t*)(Qhs + (r+8)*272 + colb*2);
                    ah[2] = *(const uint32_t*)(Qhs + r*272 + (colb+8)*2);
                    ah[3] = *(const uint32_t*)(Qhs + (r+8)*272 + (colb+8)*2);
                    al[0] = *(const uint32_t*)(Qls + r*272 + colb*2);
                    al[1] = *(const uint32_t*)(Qls + (r+8)*272 + colb*2);
                    al[2] = *(const uint32_t*)(Qls + r*272 + (colb+8)*2);
                    al[3] = *(const uint32_t*)(Qls + (r+8)*272 + (colb+8)*2);
                    mma16816(sacc[mt], ah, bh);
                    mma16816(sacc[mt], ah, bl);
                    mma16816(sacc[mt], al, bh);
                }
            }
            {
                float* Ss = (float*)(sb + ASS);
                int c0 = wid*8 + tg*2;
#pragma unroll
                for (int mt = 0; mt < 4; mt++){
                    int r0 = mt*16 + g, r1 = r0 + 8;
                    float s00 = sacc[mt][0]*scale, s01 = sacc[mt][1]*scale;
                    float s10 = sacc[mt][2]*scale, s11 = sacc[mt][3]*scale;
                    if (j0 + c0     > q0 + r0) s00 = -1e9f;
                    if (j0 + c0 + 1 > q0 + r0) s01 = -1e9f;
                    if (j0 + c0     > q0 + r1) s10 = -1e9f;
                    if (j0 + c0 + 1 > q0 + r1) s11 = -1e9f;
                    Ss[r0*SSTRF + c0] = s00; Ss[r0*SSTRF + c0+1] = s01;
                    Ss[r1*SSTRF + c0] = s10; Ss[r1*SSTRF + c0+1] = s11;
                }
            }
            __syncthreads();

            {
                float* Ss = (float*)(sb + ASS);
                bf16* Ph = (bf16*)(sb + APH);
                bf16* Pl = (bf16*)(sb + APL);
                int row = tid >> 2, part = tid & 3;
                float* srow = Ss + row*SSTRF + part*16;
                float tmax = -INFINITY;
#pragma unroll
                for (int c = 0; c < 16; c++) tmax = fmaxf(tmax, srow[c]);
                tmax = fmaxf(tmax, __shfl_xor_sync(0xffffffffu, tmax, 1));
                tmax = fmaxf(tmax, __shfl_xor_sync(0xffffffffu, tmax, 2));
                int mrow = sub*64 + row;
                float mold = m_s[mrow];
                float mnew = fmaxf(mold, tmax);
                float alpha = (mold == -INFINITY) ? 0.0f : __expf(mold - mnew);
                float sum = 0.0f;
                bf16* phrow = Ph + row*PSTR + part*16;
                bf16* plrow = Pl + row*PSTR + part*16;
#pragma unroll
                for (int c = 0; c < 16; c++){
                    float p = __expf(srow[c] - mnew);
                    sum += p;
                    bf16 ph = __float2bfloat16(p);
                    phrow[c] = ph;
                    plrow[c] = __float2bfloat16(p - __bfloat162float(ph));
                }
                sum += __shfl_xor_sync(0xffffffffu, sum, 1);
                sum += __shfl_xor_sync(0xffffffffu, sum, 2);
                if (part == 0){
                    l_s[mrow] = l_s[mrow]*alpha + sum;
                    m_s[mrow] = mnew;
                    a_s[mrow] = alpha;
                }
            }
            if (sub == 0){
                asm volatile("cp.async.wait_group 1;" ::: "memory");
            }
            __syncthreads();

#pragma unroll
            for (int mt = 0; mt < 4; mt++){
                float alA = a_s[sub*64 + mt*16 + g];
                float alB = a_s[sub*64 + mt*16 + g + 8];
#pragma unroll
                for (int nt = 0; nt < 2; nt++){
                    o[sub][mt][nt][0] *= alA; o[sub][mt][nt][1] *= alA;
                    o[sub][mt][nt][2] *= alB; o[sub][mt][nt][3] *= alB;
                }
            }
            {
                bf16* Ph = (bf16*)(sb + APH);
                bf16* Pl = (bf16*)(sb + APL);
                const uint16_t* Vhs = (const uint16_t*)(sb + AVB);
                const uint16_t* Vls = (const uint16_t*)(sb + AVB + 17408);
#pragma unroll
                for (int ksv = 0; ksv < 4; ksv++){
                    int colb = ksv*16 + tg*2;
                    uint32_t aph[4][4], apl[4][4];
#pragma unroll
                    for (int mt = 0; mt < 4; mt++){
                        int r = mt*16 + g;
                        aph[mt][0] = *(const uint32_t*)(Ph + r*PSTR + colb);
                        aph[mt][1] = *(const uint32_t*)(Ph + (r+8)*PSTR + colb);
                        aph[mt][2] = *(const uint32_t*)(Ph + r*PSTR + colb + 8);
                        aph[mt][3] = *(const uint32_t*)(Ph + (r+8)*PSTR + colb + 8);
                        apl[mt][0] = *(const uint32_t*)(Pl + r*PSTR + colb);
                        apl[mt][1] = *(const uint32_t*)(Pl + (r+8)*PSTR + colb);
                        apl[mt][2] = *(const uint32_t*)(Pl + r*PSTR + colb + 8);
                        apl[mt][3] = *(const uint32_t*)(Pl + (r+8)*PSTR + colb + 8);
                    }
#pragma unroll
                    for (int nt = 0; nt < 2; nt++){
                        int n = wid*16 + nt*8 + g;
                        int k0 = ksv*16 + tg*2;
                        uint32_t bvh[2], bvl[2];
                        bvh[0] = (uint32_t)Vhs[k0*QKSTR + n]     | ((uint32_t)Vhs[(k0+1)*QKSTR + n] << 16);
                        bvh[1] = (uint32_t)Vhs[(k0+8)*QKSTR + n] | ((uint32_t)Vhs[(k0+9)*QKSTR + n] << 16);
                        bvl[0] = (uint32_t)Vls[k0*QKSTR + n]     | ((uint32_t)Vls[(k0+1)*QKSTR + n] << 16);
                        bvl[1] = (uint32_t)Vls[(k0+8)*QKSTR + n] | ((uint32_t)Vls[(k0+9)*QKSTR + n] << 16);
#pragma unroll
                        for (int mt = 0; mt < 4; mt++){
                            mma16816(o[sub][mt][nt], aph[mt], bvh);
                            mma16816(o[sub][mt][nt], aph[mt], bvl);
                            mma16816(o[sub][mt][nt], apl[mt], bvh);
                        }
                    }
                }
            }
            __syncthreads();
        }
    }

    // epilogue: write y directly in the packed swizzled hi/lo layout
#pragma unroll
    for (int sub = 0; sub < 2; sub++){
#pragma unroll
        for (int mt = 0; mt < 4; mt++){
            float invA = 1.0f / l_s[sub*64 + mt*16 + g];
            float invB = 1.0f / l_s[sub*64 + mt*16 + g + 8];
#pragma unroll
            for (int nt = 0; nt < 2; nt++){
                int col = (h0+sub)*HDIM + wid*16 + nt*8 + tg*2;
                int cchunk = col >> 5;
                int j = (col & 31) >> 3;
#pragma unroll
                for (int rr = 0; rr < 2; rr++){
                    int r = q0 + mt*16 + g + rr*8;
                    float inv = rr ? invB : invA;
                    float v0 = o[sub][mt][nt][rr*2+0] * inv;
                    float v1 = o[sub][mt][nt][rr*2+1] * inv;
                    bf16 h0b = __float2bfloat16(v0);
                    bf16 h1b = __float2bfloat16(v1);
                    union { bf16 x[2]; uint32_t u; } H, L;
                    H.x[0] = h0b; H.x[1] = h1b;
                    L.x[0] = __float2bfloat16(v0 - __bfloat162float(h0b));
                    L.x[1] = __float2bfloat16(v1 - __bfloat162float(h1b));
                    int jp = j ^ ((r >> 1) & 3);
                    size_t off = (((size_t)(r >> 8) * 128 + cchunk) << 13)
                               + (size_t)(r & 255) * 32 + jp*8 + (col & 7);
                    *(uint32_t*)(yhi + off) = H.u;
                    *(uint32_t*)(ylo + off) = L.u;
                }
            }
        }
    }
}

// ---------------- launch ---------------------------------------------------
extern "C" void kernel_launch(void* const* d_in, const int* in_sizes, int n_in,
                              void* d_out, int out_size)
{
    const float* x  = (const float*)d_in[0];
    const float* fc = (const float*)d_in[1];
    const float* wq = (const float*)d_in[3];
    const float* wk = (const float*)d_in[4];
    const float* wv = (const float*)d_in[5];
    const float* wo = (const float*)d_in[6];
    float* out = (float*)d_out;

    void *pq, *pk, *pv;
    void *pxh, *pxl, *pqh, *pql, *pkvh, *pkvl, *poh, *pol, *pyh, *pyl;
    cudaGetSymbolAddress(&pq, g_q);
    cudaGetSymbolAddress(&pk, g_k);
    cudaGetSymbolAddress(&pv, g_v);
    cudaGetSymbolAddress(&pxh, g_xhi);   cudaGetSymbolAddress(&pxl, g_xlo);
    cudaGetSymbolAddress(&pqh, g_wqhi);  cudaGetSymbolAddress(&pql, g_wqlo);
    cudaGetSymbolAddress(&pkvh, g_wkvhi); cudaGetSymbolAddress(&pkvl, g_wkvlo);
    cudaGetSymbolAddress(&poh, g_wohi);  cudaGetSymbolAddress(&pol, g_wolo);
    cudaGetSymbolAddress(&pyh, g_yhi);   cudaGetSymbolAddress(&pyl, g_ylo);

    bf16* xhi = (bf16*)pxh; bf16* xlo = (bf16*)pxl;
    bf16* qhi = (bf16*)pqh; bf16* qlo = (bf16*)pql;
    bf16* kvhi = (bf16*)pkvh; bf16* kvlo = (bf16*)pkvl;
    bf16* ohi = (bf16*)poh; bf16* olo = (bf16*)pol;
    bf16* yhi = (bf16*)pyh; bf16* ylo = (bf16*)pyl;
    bf16* aqh = (bf16*)pq;  bf16* aql = aqh + (size_t)SEQLEN*DIM;
    bf16* akh = (bf16*)pk;  bf16* akl = akh + (size_t)SEQLEN*KVDIM;
    bf16* avh = (bf16*)pv;  bf16* avl = avh + (size_t)SEQLEN*KVDIM;

    cudaFuncSetAttribute(gemm_bulk2<0>, cudaFuncAttributeMaxDynamicSharedMemorySize, P2GSMEM);
    cudaFuncSetAttribute(gemm_bulk2<1>, cudaFuncAttributeMaxDynamicSharedMemorySize, P2GSMEM);
    cudaFuncSetAttribute(gemm_bulk2<3>, cudaFuncAttributeMaxDynamicSharedMemorySize, P2GSMEM);
    cudaFuncSetAttribute(attn_mma, cudaFuncAttributeMaxDynamicSharedMemorySize, ATTN_SMEM2);

    // pack inputs & weights (wk||wv fused into one [2048,4096] packed tensor)
    {
        int n8;
        const size_t WOFF = (size_t)KVDIM * DIM;   // 1024*4096 elems
        n8 = SEQLEN*DIM/8;  pack_split<<<(n8+255)/256, 256>>>(x,  xhi, xlo, 8, n8);
        n8 = DIM*DIM/8;     pack_split<<<(n8+255)/256, 256>>>(wq, qhi, qlo, 7, n8);
        n8 = KVDIM*DIM/8;   pack_split<<<(n8+255)/256, 256>>>(wk, kvhi, kvlo, 7, n8);
        n8 = KVDIM*DIM/8;   pack_split<<<(n8+255)/256, 256>>>(wv, kvhi + WOFF, kvlo + WOFF, 7, n8);
        n8 = DIM*DIM/8;     pack_split<<<(n8+255)/256, 256>>>(wo, ohi, olo, 7, n8);
    }

    // q projection (RoPE+split epilogue) and fused k|v projection
    gemm_bulk2<1><<<dim3(DIM/128,     SEQLEN/128), 256, P2GSMEM>>>(
        xhi, xlo, qhi, qlo, nullptr, aqh, aql, nullptr, nullptr, fc, DIM);
    gemm_bulk2<3><<<dim3(2*KVDIM/128, SEQLEN/128), 256, P2GSMEM>>>(
        xhi, xlo, kvhi, kvlo, nullptr, akh, akl, avh, avl, fc, 2*KVDIM);

    // attention: 2 q-heads per CTA share KV; writes packed y hi/lo
    attn_mma<<<dim3(SEQLEN/64, NHEADS/2), 256, ATTN_SMEM2>>>(aqh, aql, akh, akl, avh, avl, yhi, ylo);

    // output projection (packed y already in wo-GEMM layout)
    gemm_bulk2<0><<<dim3(DIM/128, SEQLEN/128), 256, P2GSMEM>>>(
        yhi, ylo, ohi, olo, out, nullptr, nullptr, nullptr, nullptr, nullptr, DIM);
}